// round 6
// baseline (speedup 1.0000x reference)
#include <cuda_runtime.h>
#include <cuda_bf16.h>
#include <math.h>
#include <stdint.h>

// Problem constants (fixed by the dataset)
#define NN 50000
#define EE 800000
#define HH 128
#define FIN 128
#define NSE 16
#define LL 3
#define CC 10
#define GG 256

// ---------------- scratch (static __device__ — no allocs allowed) ----------
__device__ float d_x [NN * HH];
__device__ float d_s [NN * HH];
__device__ float d_y [NN * HH];
__device__ float d_z [NN * HH];
__device__ float d_hs[NN * HH];
__device__ float d_g [GG * HH];
__device__ float d_gp[GG * HH];
__device__ float d_dinv[NN];
__device__ int   d_degc[NN];
__device__ int   d_rowptr[NN + 1];
__device__ int   d_cursor[NN];
__device__ int   d_col[EE];

// ---------------- CSR build ------------------------------------------------
__global__ void count_deg_kernel(const int* __restrict__ ei, int* __restrict__ degc) {
    int e = blockIdx.x * blockDim.x + threadIdx.x;
    if (e < EE) atomicAdd(&degc[ei[EE + e]], 1);
}

__global__ void scan_deg_kernel(const int* __restrict__ degc,
                                int* __restrict__ rowptr,
                                float* __restrict__ dinv) {
    __shared__ int ssum[1024];
    int t = threadIdx.x;
    const int chunk = (NN + 1023) / 1024;
    int b0 = t * chunk;
    int b1 = b0 + chunk; if (b1 > NN) b1 = NN;
    int sum = 0;
    for (int i = b0; i < b1; i++) sum += degc[i];
    ssum[t] = sum;
    __syncthreads();
    for (int off = 1; off < 1024; off <<= 1) {
        int v = 0;
        if (t >= off) v = ssum[t - off];
        __syncthreads();
        if (t >= off) ssum[t] += v;
        __syncthreads();
    }
    int prefix = (t == 0) ? 0 : ssum[t - 1];
    for (int i = b0; i < b1; i++) {
        int d = degc[i];
        rowptr[i] = prefix;
        prefix += d;
        dinv[i] = rsqrtf((float)d + 1.0f);
    }
    if (t == 1023) rowptr[NN] = ssum[1023];
}

__global__ void fill_csr_kernel(const int* __restrict__ ei,
                                const int* __restrict__ rowptr,
                                int* __restrict__ cursor,
                                int* __restrict__ col) {
    int e = blockIdx.x * blockDim.x + threadIdx.x;
    if (e < EE) {
        int src = ei[e];
        int dst = ei[EE + e];
        int pos = atomicAdd(&cursor[dst], 1);
        col[rowptr[dst] + pos] = src;
    }
}

// ---------------- TF32 helpers ---------------------------------------------
__device__ __forceinline__ uint32_t f2tf32(float x) {
    uint32_t r;
    asm("cvt.rna.tf32.f32 %0, %1;" : "=r"(r) : "f"(x));
    return r;
}
__device__ __forceinline__ void split_tf32(float x, uint32_t& hi, uint32_t& lo) {
    hi = f2tf32(x);
    lo = f2tf32(x - __uint_as_float(hi));
}
__device__ __forceinline__ void mma_tf32(float* c, const uint32_t* a, const uint32_t* b) {
    asm volatile("mma.sync.aligned.m16n8k8.row.col.f32.tf32.tf32.f32 "
        "{%0,%1,%2,%3}, {%4,%5,%6,%7}, {%8,%9}, {%0,%1,%2,%3};"
        : "+f"(c[0]), "+f"(c[1]), "+f"(c[2]), "+f"(c[3])
        : "r"(a[0]), "r"(a[1]), "r"(a[2]), "r"(a[3]), "r"(b[0]), "r"(b[1]));
}

// ---------------- TF32 GEMM (pre-split hi/lo in smem, dual-A) --------------
// C[M,128] = A1[M,K1] @ W[0:K1,:] + A2[M,K2] @ W[K1:,:] (+bias)(+relu)
// Block 128x128, BK=8, 8 warps as 4(M)x2(N); warp tile 32x64.
// Split hi/lo done ONCE per element at smem store; inner loop is LDS+HMMA.
#define TM 128
#define TN 128
#define TKK 8
#define AP 12          // A row width (8 + pad 4), multiple of 4
#define BP (TN + 4)    // B row width, multiple of 4
__global__ __launch_bounds__(256)
void tf32_gemm_dual(const float* __restrict__ A1, int K1,
                    const float* __restrict__ A2, int K2,
                    const float* __restrict__ W,
                    const float* __restrict__ bias,
                    float* __restrict__ C, int M, int relu) {
    __shared__ uint32_t AsH[2][TM][AP];
    __shared__ uint32_t AsL[2][TM][AP];
    __shared__ uint32_t BsH[2][TKK][BP];
    __shared__ uint32_t BsL[2][TKK][BP];
    const int tid  = threadIdx.x;
    const int wid  = tid >> 5;
    const int lane = tid & 31;
    const int g    = lane >> 2;      // 0..7
    const int t    = lane & 3;       // 0..3
    const int wm   = wid & 3;        // M warp coord (0..3)
    const int wn   = wid >> 2;       // N warp coord (0..1)
    const int row0 = blockIdx.x * TM;
    const int nb   = (K1 + K2) / TKK;

    float acc[2][8][4];
#pragma unroll
    for (int mi = 0; mi < 2; mi++)
#pragma unroll
        for (int ni = 0; ni < 8; ni++)
#pragma unroll
            for (int q = 0; q < 4; q++) acc[mi][ni][q] = 0.0f;

    // A: 128 rows x 8 k => 1 float4/thread (r=tid>>1, c=(tid&1)*4)
    const int aRow = tid >> 1;
    const int aC   = (tid & 1) * 4;
    // B: 8 k-rows x 128 n => 1 float4/thread (kr=tid>>5, cn=(tid&31)*4)
    const int bKr  = tid >> 5;
    const int bCn  = (tid & 31) * 4;

    auto fetchA = [&](int kb) -> float4 {
        int kg = kb * TKK + aC;
        const float* Ap; int kl, Kd;
        if (kg < K1) { Ap = A1; kl = kg; Kd = K1; }
        else         { Ap = A2; kl = kg - K1; Kd = K2; }
        if (row0 + aRow < M)
            return *(const float4*)(Ap + (size_t)(row0 + aRow) * Kd + kl);
        return make_float4(0.f, 0.f, 0.f, 0.f);
    };
    auto fetchB = [&](int kb) -> float4 {
        return *(const float4*)(W + (size_t)(kb * TKK + bKr) * TN + bCn);
    };
    auto stSplitA = [&](int buf, float4 v) {
        uint4 h, l;
        split_tf32(v.x, h.x, l.x); split_tf32(v.y, h.y, l.y);
        split_tf32(v.z, h.z, l.z); split_tf32(v.w, h.w, l.w);
        *(uint4*)&AsH[buf][aRow][aC] = h;
        *(uint4*)&AsL[buf][aRow][aC] = l;
    };
    auto stSplitB = [&](int buf, float4 v) {
        uint4 h, l;
        split_tf32(v.x, h.x, l.x); split_tf32(v.y, h.y, l.y);
        split_tf32(v.z, h.z, l.z); split_tf32(v.w, h.w, l.w);
        *(uint4*)&BsH[buf][bKr][bCn] = h;
        *(uint4*)&BsL[buf][bKr][bCn] = l;
    };

    stSplitA(0, fetchA(0));
    stSplitB(0, fetchB(0));
    __syncthreads();

    for (int kb = 0; kb < nb; kb++) {
        const int cur = kb & 1, nxt = cur ^ 1;
        float4 pa, pb;
        if (kb + 1 < nb) { pa = fetchA(kb + 1); pb = fetchB(kb + 1); }

        uint32_t ahi[2][4], alo[2][4];
#pragma unroll
        for (int mi = 0; mi < 2; mi++) {
            int mb = wm * 32 + mi * 16;
            ahi[mi][0] = AsH[cur][mb + g    ][t    ];
            ahi[mi][1] = AsH[cur][mb + g + 8][t    ];
            ahi[mi][2] = AsH[cur][mb + g    ][t + 4];
            ahi[mi][3] = AsH[cur][mb + g + 8][t + 4];
            alo[mi][0] = AsL[cur][mb + g    ][t    ];
            alo[mi][1] = AsL[cur][mb + g + 8][t    ];
            alo[mi][2] = AsL[cur][mb + g    ][t + 4];
            alo[mi][3] = AsL[cur][mb + g + 8][t + 4];
        }
        uint32_t bhi[8][2], blo[8][2];
#pragma unroll
        for (int ni = 0; ni < 8; ni++) {
            int nbase = wn * 64 + ni * 8 + g;
            bhi[ni][0] = BsH[cur][t    ][nbase];
            bhi[ni][1] = BsH[cur][t + 4][nbase];
            blo[ni][0] = BsL[cur][t    ][nbase];
            blo[ni][1] = BsL[cur][t + 4][nbase];
        }
#pragma unroll
        for (int mi = 0; mi < 2; mi++)
#pragma unroll
            for (int ni = 0; ni < 8; ni++) {
                mma_tf32(acc[mi][ni], ahi[mi], bhi[ni]);
                mma_tf32(acc[mi][ni], ahi[mi], blo[ni]);
                mma_tf32(acc[mi][ni], alo[mi], bhi[ni]);
            }

        if (kb + 1 < nb) { stSplitA(nxt, pa); stSplitB(nxt, pb); }
        __syncthreads();
    }

    // Epilogue: c0->(g,2t) c1->(g,2t+1) c2->(g+8,2t) c3->(g+8,2t+1)
#pragma unroll
    for (int mi = 0; mi < 2; mi++) {
        int rbase = row0 + wm * 32 + mi * 16 + g;
#pragma unroll
        for (int ni = 0; ni < 8; ni++) {
            int colb = wn * 64 + ni * 8 + 2 * t;
            float b0 = bias ? bias[colb]     : 0.f;
            float b1 = bias ? bias[colb + 1] : 0.f;
            float v0 = acc[mi][ni][0] + b0;
            float v1 = acc[mi][ni][1] + b1;
            float v2 = acc[mi][ni][2] + b0;
            float v3 = acc[mi][ni][3] + b1;
            if (relu) {
                v0 = fmaxf(v0, 0.f); v1 = fmaxf(v1, 0.f);
                v2 = fmaxf(v2, 0.f); v3 = fmaxf(v3, 0.f);
            }
            if (rbase < M)
                *(float2*)(C + (size_t)rbase * TN + colb) = make_float2(v0, v1);
            if (rbase + 8 < M)
                *(float2*)(C + (size_t)(rbase + 8) * TN + colb) = make_float2(v2, v3);
        }
    }
}

// ---------------- Fused GIN+GCN aggregation --------------------------------
// One warp per node, one CSR walk serving both streams:
//   z = relu(y_i + sum_in y_src + b1)
//   s = tanh(dinv_i * sum_in dinv_src*hs_src + hs_i*dinv_i^2 + gcn_b)
__global__ __launch_bounds__(256)
void fused_agg_kernel(const float* __restrict__ y,
                      const float* __restrict__ hs,
                      const float* __restrict__ dinv,
                      const int* __restrict__ col,
                      const int* __restrict__ rowptr,
                      const float* __restrict__ b1,
                      const float* __restrict__ gcn_b,
                      float* __restrict__ z,
                      float* __restrict__ s_out) {
    int node = (blockIdx.x * blockDim.x + threadIdx.x) >> 5;
    if (node >= NN) return;
    int lane = threadIdx.x & 31;
    const float4* yv = (const float4*)y;
    const float4* hv = (const float4*)hs;

    float yx = 0.f, yy = 0.f, yz = 0.f, yw = 0.f;   // sum y
    float gx = 0.f, gy = 0.f, gz = 0.f, gw = 0.f;   // sum dinv*hs
    int b = rowptr[node], e = rowptr[node + 1];
    int j = b;
    for (; j + 2 <= e; j += 2) {
        int s0 = col[j], s1 = col[j + 1];
        float d0 = dinv[s0], d1 = dinv[s1];
        float4 a0 = yv[(size_t)s0 * 32 + lane];
        float4 a1 = yv[(size_t)s1 * 32 + lane];
        float4 h0 = hv[(size_t)s0 * 32 + lane];
        float4 h1 = hv[(size_t)s1 * 32 + lane];
        yx += a0.x + a1.x; yy += a0.y + a1.y;
        yz += a0.z + a1.z; yw += a0.w + a1.w;
        gx += d0 * h0.x + d1 * h1.x;
        gy += d0 * h0.y + d1 * h1.y;
        gz += d0 * h0.z + d1 * h1.z;
        gw += d0 * h0.w + d1 * h1.w;
    }
    for (; j < e; j++) {
        int sc = col[j];
        float dd = dinv[sc];
        float4 a = yv[(size_t)sc * 32 + lane];
        float4 h = hv[(size_t)sc * 32 + lane];
        yx += a.x; yy += a.y; yz += a.z; yw += a.w;
        gx += dd * h.x; gy += dd * h.y; gz += dd * h.z; gw += dd * h.w;
    }

    float4 yself = yv[(size_t)node * 32 + lane];
    float4 bb1   = ((const float4*)b1)[lane];
    float4 oz;
    oz.x = fmaxf(yself.x + yx + bb1.x, 0.f);
    oz.y = fmaxf(yself.y + yy + bb1.y, 0.f);
    oz.z = fmaxf(yself.z + yz + bb1.z, 0.f);
    oz.w = fmaxf(yself.w + yw + bb1.w, 0.f);
    ((float4*)z)[(size_t)node * 32 + lane] = oz;

    float di  = dinv[node];
    float di2 = di * di;
    float4 hself = hv[(size_t)node * 32 + lane];
    float4 bbg   = ((const float4*)gcn_b)[lane];
    float4 os;
    os.x = tanhf(di * gx + hself.x * di2 + bbg.x);
    os.y = tanhf(di * gy + hself.y * di2 + bbg.y);
    os.z = tanhf(di * gz + hself.z * di2 + bbg.z);
    os.w = tanhf(di * gw + hself.w * di2 + bbg.w);
    ((float4*)s_out)[(size_t)node * 32 + lane] = os;
}

// ---------------- global add pool -----------------------------------------
__global__ void pool_kernel(const float* __restrict__ xf,
                            const int* __restrict__ batch,
                            float* __restrict__ g) {
    int idx = blockIdx.x * blockDim.x + threadIdx.x;
    if (idx < NN * HH) {
        int i = idx >> 7;
        int f = idx & 127;
        atomicAdd(&g[batch[i] * HH + f], xf[idx]);
    }
}

// ---------------- post: relu(g @ post_w + b) ------------------------------
__global__ void post_kernel(const float* __restrict__ g,
                            const float* __restrict__ W,
                            const float* __restrict__ bias,
                            float* __restrict__ gp) {
    int r = blockIdx.x;
    int c = threadIdx.x;
    __shared__ float row[HH];
    row[c] = g[(size_t)r * HH + c];
    __syncthreads();
    float acc = bias[c];
#pragma unroll 8
    for (int k = 0; k < HH; k++) acc = fmaf(row[k], W[(size_t)k * HH + c], acc);
    gp[(size_t)r * HH + c] = fmaxf(acc, 0.0f);
}

// ---------------- readout + log_softmax ----------------------------------
__global__ void readout_kernel(const float* __restrict__ gp,
                               const float* __restrict__ W,
                               const float* __restrict__ bias,
                               float* __restrict__ out) {
    int r = blockIdx.x * blockDim.x + threadIdx.x;
    if (r < GG) {
        float logit[CC];
#pragma unroll
        for (int c = 0; c < CC; c++) logit[c] = bias[c];
        for (int k = 0; k < HH; k++) {
            float gv = gp[(size_t)r * HH + k];
#pragma unroll
            for (int c = 0; c < CC; c++)
                logit[c] = fmaf(gv, W[(size_t)k * CC + c], logit[c]);
        }
        float m = logit[0];
#pragma unroll
        for (int c = 1; c < CC; c++) m = fmaxf(m, logit[c]);
        float sum = 0.0f;
#pragma unroll
        for (int c = 0; c < CC; c++) sum += expf(logit[c] - m);
        float lse = m + logf(sum);
#pragma unroll
        for (int c = 0; c < CC; c++) out[(size_t)r * CC + c] = logit[c] - lse;
    }
}

// ---------------- driver ---------------------------------------------------
extern "C" void kernel_launch(void* const* d_in, const int* in_sizes, int n_in,
                              void* d_out, int out_size) {
    const float* x_in   = (const float*)d_in[0];
    const float* s_in   = (const float*)d_in[1];
    const int*   ei     = (const int*)d_in[2];
    const int*   batch  = (const int*)d_in[3];
    const float* pre_w  = (const float*)d_in[4];
    const float* pre_b  = (const float*)d_in[5];
    const float* emb_w  = (const float*)d_in[6];
    const float* emb_b  = (const float*)d_in[7];
    const float* gin_w1 = (const float*)d_in[8];
    const float* gin_b1 = (const float*)d_in[9];
    const float* gin_w2 = (const float*)d_in[10];
    const float* gin_b2 = (const float*)d_in[11];
    const float* gcn_w  = (const float*)d_in[12];
    const float* gcn_b  = (const float*)d_in[13];
    const float* whp_w  = (const float*)d_in[14];
    const float* whp_b  = (const float*)d_in[15];
    const float* post_w = (const float*)d_in[16];
    const float* post_b = (const float*)d_in[17];
    const float* ro_w   = (const float*)d_in[18];
    const float* ro_b   = (const float*)d_in[19];
    float* out = (float*)d_out;

    float *px, *ps, *py, *pz, *phs, *pg, *pgp, *pdinv;
    int *pdegc, *prow, *pcur, *pcol;
    cudaGetSymbolAddress((void**)&px,    d_x);
    cudaGetSymbolAddress((void**)&ps,    d_s);
    cudaGetSymbolAddress((void**)&py,    d_y);
    cudaGetSymbolAddress((void**)&pz,    d_z);
    cudaGetSymbolAddress((void**)&phs,   d_hs);
    cudaGetSymbolAddress((void**)&pg,    d_g);
    cudaGetSymbolAddress((void**)&pgp,   d_gp);
    cudaGetSymbolAddress((void**)&pdinv, d_dinv);
    cudaGetSymbolAddress((void**)&pdegc, d_degc);
    cudaGetSymbolAddress((void**)&prow,  d_rowptr);
    cudaGetSymbolAddress((void**)&pcur,  d_cursor);
    cudaGetSymbolAddress((void**)&pcol,  d_col);

    const int TPB = 256;
    const int eBlocks = (EE + TPB - 1) / TPB;
    const int gemmBlocks = (NN + TM - 1) / TM;
    const int aggBlocks = (NN * 32 + TPB - 1) / TPB;

    // CSR build
    cudaMemsetAsync(pdegc, 0, NN * sizeof(int), 0);
    cudaMemsetAsync(pcur,  0, NN * sizeof(int), 0);
    count_deg_kernel<<<eBlocks, TPB>>>(ei, pdegc);
    scan_deg_kernel<<<1, 1024>>>(pdegc, prow, pdinv);
    fill_csr_kernel<<<eBlocks, TPB>>>(ei, prow, pcur, pcol);

    // pre / embedding
    tf32_gemm_dual<<<gemmBlocks, 256>>>(x_in, FIN, nullptr, 0, pre_w, pre_b, px, NN, 0);
    tf32_gemm_dual<<<gemmBlocks, 256>>>(s_in, NSE, nullptr, 0, emb_w, emb_b, ps, NN, 0);

    for (int i = 0; i < LL; i++) {
        // y = [x|s] @ gin_w1 (split dual-A)
        tf32_gemm_dual<<<gemmBlocks, 256>>>(px, HH, ps, HH,
                                            gin_w1 + (size_t)i * 2 * HH * HH,
                                            nullptr, py, NN, 0);
        // hs = s @ gcn_w[i]
        tf32_gemm_dual<<<gemmBlocks, 256>>>(ps, HH, nullptr, 0,
                                            gcn_w + (size_t)i * HH * HH,
                                            nullptr, phs, NN, 0);
        // fused: z = relu(y + A.y + b1);  s = tanh(gcn norm-agg + b)
        fused_agg_kernel<<<aggBlocks, TPB>>>(py, phs, pdinv, pcol, prow,
                                             gin_b1 + (size_t)i * HH,
                                             gcn_b + (size_t)i * HH, pz, ps);
        // x = relu(z @ gin_w2 + b2)
        tf32_gemm_dual<<<gemmBlocks, 256>>>(pz, HH, nullptr, 0,
                                            gin_w2 + (size_t)i * HH * HH,
                                            gin_b2 + (size_t)i * HH, px, NN, 1);
    }

    // whp on split concat
    tf32_gemm_dual<<<gemmBlocks, 256>>>(px, HH, ps, HH, whp_w, whp_b, py, NN, 0);

    // pool -> post -> readout
    cudaMemsetAsync(pg, 0, GG * HH * sizeof(float), 0);
    pool_kernel<<<(NN * HH + TPB - 1) / TPB, TPB>>>(py, batch, pg);
    post_kernel<<<GG, HH>>>(pg, post_w, post_b, pgp);
    readout_kernel<<<1, GG>>>(pgp, ro_w, ro_b, out);
}

// round 7
// speedup vs baseline: 1.3035x; 1.3035x over previous
#include <cuda_runtime.h>
#include <cuda_bf16.h>
#include <math.h>
#include <stdint.h>

// Problem constants (fixed by the dataset)
#define NN 50000
#define EE 800000
#define HH 128
#define FIN 128
#define NSE 16
#define LL 3
#define CC 10
#define GG 256

// ---------------- scratch (static __device__ — no allocs allowed) ----------
__device__ float d_x [NN * HH];
__device__ float d_s [NN * HH];
__device__ float d_y [NN * HH];
__device__ float d_z [NN * HH];
__device__ float d_hs[NN * HH];
__device__ float d_g [GG * HH];
__device__ float d_gp[GG * HH];
__device__ float d_dinv[NN];
__device__ int   d_degc[NN];
__device__ int   d_rowptr[NN + 1];
__device__ int   d_cursor[NN];
__device__ int   d_col[EE];

// ---------------- CSR build ------------------------------------------------
__global__ void count_deg_kernel(const int* __restrict__ ei, int* __restrict__ degc) {
    int e = blockIdx.x * blockDim.x + threadIdx.x;
    if (e < EE) atomicAdd(&degc[ei[EE + e]], 1);
}

__global__ void scan_deg_kernel(const int* __restrict__ degc,
                                int* __restrict__ rowptr,
                                float* __restrict__ dinv) {
    __shared__ int ssum[1024];
    int t = threadIdx.x;
    const int chunk = (NN + 1023) / 1024;
    int b0 = t * chunk;
    int b1 = b0 + chunk; if (b1 > NN) b1 = NN;
    int sum = 0;
    for (int i = b0; i < b1; i++) sum += degc[i];
    ssum[t] = sum;
    __syncthreads();
    for (int off = 1; off < 1024; off <<= 1) {
        int v = 0;
        if (t >= off) v = ssum[t - off];
        __syncthreads();
        if (t >= off) ssum[t] += v;
        __syncthreads();
    }
    int prefix = (t == 0) ? 0 : ssum[t - 1];
    for (int i = b0; i < b1; i++) {
        int d = degc[i];
        rowptr[i] = prefix;
        prefix += d;
        dinv[i] = rsqrtf((float)d + 1.0f);
    }
    if (t == 1023) rowptr[NN] = ssum[1023];
}

__global__ void fill_csr_kernel(const int* __restrict__ ei,
                                const int* __restrict__ rowptr,
                                int* __restrict__ cursor,
                                int* __restrict__ col) {
    int e = blockIdx.x * blockDim.x + threadIdx.x;
    if (e < EE) {
        int src = ei[e];
        int dst = ei[EE + e];
        int pos = atomicAdd(&cursor[dst], 1);
        col[rowptr[dst] + pos] = src;
    }
}

// ---------------- bf16 split helpers ---------------------------------------
__device__ __forceinline__ void split2_bf16(float a, float b,
                                            uint32_t& hiPair, uint32_t& loPair) {
    __nv_bfloat16 ha = __float2bfloat16_rn(a);
    __nv_bfloat16 hb = __float2bfloat16_rn(b);
    float ra = a - __bfloat162float(ha);
    float rb = b - __bfloat162float(hb);
    __nv_bfloat16 la = __float2bfloat16_rn(ra);
    __nv_bfloat16 lb = __float2bfloat16_rn(rb);
    hiPair = (uint32_t)__bfloat16_as_ushort(ha) |
             ((uint32_t)__bfloat16_as_ushort(hb) << 16);
    loPair = (uint32_t)__bfloat16_as_ushort(la) |
             ((uint32_t)__bfloat16_as_ushort(lb) << 16);
}

__device__ __forceinline__ void mma_bf16(float* c, const uint32_t* a, const uint32_t* b) {
    asm volatile("mma.sync.aligned.m16n8k16.row.col.f32.bf16.bf16.f32 "
        "{%0,%1,%2,%3}, {%4,%5,%6,%7}, {%8,%9}, {%0,%1,%2,%3};"
        : "+f"(c[0]), "+f"(c[1]), "+f"(c[2]), "+f"(c[3])
        : "r"(a[0]), "r"(a[1]), "r"(a[2]), "r"(a[3]), "r"(b[0]), "r"(b[1]));
}

// ---------------- bf16x3 GEMM (split hi/lo in smem, dual-A) ----------------
// C[M,128] = A1[M,K1] @ W[0:K1,:] + A2[M,K2] @ W[K1:,:] (+bias)(+relu)
// Block 128x128, BK=16, 8 warps as 4(M)x2(N); warp tile 32x64.
// A smem [row][k] bf16; B smem TRANSPOSED [n][k] bf16 so fragment regs are
// single packed 32-bit LDS. Rows padded to 24 elems (48B, odd 16B stride).
#define TM 128
#define TN 128
#define TKK 16
#define RPAD 24
__global__ __launch_bounds__(256)
void bf16_gemm_dual(const float* __restrict__ A1, int K1,
                    const float* __restrict__ A2, int K2,
                    const float* __restrict__ W,
                    const float* __restrict__ bias,
                    float* __restrict__ C, int M, int relu) {
    __shared__ uint16_t AsH[2][TM][RPAD];
    __shared__ uint16_t AsL[2][TM][RPAD];
    __shared__ uint16_t BsH[2][TN][RPAD];
    __shared__ uint16_t BsL[2][TN][RPAD];
    const int tid  = threadIdx.x;
    const int wid  = tid >> 5;
    const int lane = tid & 31;
    const int g    = lane >> 2;      // 0..7
    const int t    = lane & 3;       // 0..3
    const int wm   = wid & 3;        // M warp coord (0..3)
    const int wn   = wid >> 2;       // N warp coord (0..1)
    const int row0 = blockIdx.x * TM;
    const int nb   = (K1 + K2) / TKK;

    float acc[2][8][4];
#pragma unroll
    for (int mi = 0; mi < 2; mi++)
#pragma unroll
        for (int ni = 0; ni < 8; ni++)
#pragma unroll
            for (int q = 0; q < 4; q++) acc[mi][ni][q] = 0.0f;

    // A loader: r = tid>>1 (0..127), kOff = (tid&1)*8 -> 8 k's per thread
    const int aRow = tid >> 1;
    const int aOff = (tid & 1) * 8;
    // B loader: n = tid&127, kG = tid>>7 (0/1) -> 8 k's per thread at fixed n
    const int bN  = tid & 127;
    const int bG  = (tid >> 7) * 8;

    auto fetchA = [&](int kb, float4& v0, float4& v1) {
        int kg = kb * TKK + aOff;
        const float* Ap; int kl, Kd;
        if (kg < K1) { Ap = A1; kl = kg; Kd = K1; }
        else         { Ap = A2; kl = kg - K1; Kd = K2; }
        if (row0 + aRow < M) {
            const float* p = Ap + (size_t)(row0 + aRow) * Kd + kl;
            v0 = *(const float4*)p;
            v1 = *(const float4*)(p + 4);
        } else {
            v0 = make_float4(0.f, 0.f, 0.f, 0.f);
            v1 = v0;
        }
    };
    auto fetchB = [&](int kb, float* w) {
        int kbase = kb * TKK + bG;
#pragma unroll
        for (int i = 0; i < 8; i++)
            w[i] = W[(size_t)(kbase + i) * TN + bN];
    };
    auto stA = [&](int buf, float4 v0, float4 v1) {
        uint4 h, l;
        split2_bf16(v0.x, v0.y, h.x, l.x);
        split2_bf16(v0.z, v0.w, h.y, l.y);
        split2_bf16(v1.x, v1.y, h.z, l.z);
        split2_bf16(v1.z, v1.w, h.w, l.w);
        *(uint4*)&AsH[buf][aRow][aOff] = h;
        *(uint4*)&AsL[buf][aRow][aOff] = l;
    };
    auto stB = [&](int buf, const float* w) {
        uint4 h, l;
        split2_bf16(w[0], w[1], h.x, l.x);
        split2_bf16(w[2], w[3], h.y, l.y);
        split2_bf16(w[4], w[5], h.z, l.z);
        split2_bf16(w[6], w[7], h.w, l.w);
        *(uint4*)&BsH[buf][bN][bG] = h;
        *(uint4*)&BsL[buf][bN][bG] = l;
    };

    {
        float4 a0, a1; float w[8];
        fetchA(0, a0, a1); fetchB(0, w);
        stA(0, a0, a1); stB(0, w);
    }
    __syncthreads();

    for (int kb = 0; kb < nb; kb++) {
        const int cur = kb & 1, nxt = cur ^ 1;
        float4 pa0, pa1; float pw[8];
        if (kb + 1 < nb) { fetchA(kb + 1, pa0, pa1); fetchB(kb + 1, pw); }

        uint32_t ahi[2][4], alo[2][4];
#pragma unroll
        for (int mi = 0; mi < 2; mi++) {
            int mb = wm * 32 + mi * 16;
            ahi[mi][0] = *(const uint32_t*)&AsH[cur][mb + g    ][2 * t    ];
            ahi[mi][1] = *(const uint32_t*)&AsH[cur][mb + g + 8][2 * t    ];
            ahi[mi][2] = *(const uint32_t*)&AsH[cur][mb + g    ][2 * t + 8];
            ahi[mi][3] = *(const uint32_t*)&AsH[cur][mb + g + 8][2 * t + 8];
            alo[mi][0] = *(const uint32_t*)&AsL[cur][mb + g    ][2 * t    ];
            alo[mi][1] = *(const uint32_t*)&AsL[cur][mb + g + 8][2 * t    ];
            alo[mi][2] = *(const uint32_t*)&AsL[cur][mb + g    ][2 * t + 8];
            alo[mi][3] = *(const uint32_t*)&AsL[cur][mb + g + 8][2 * t + 8];
        }
        uint32_t bhi[8][2], blo[8][2];
#pragma unroll
        for (int ni = 0; ni < 8; ni++) {
            int nbase = wn * 64 + ni * 8 + g;
            bhi[ni][0] = *(const uint32_t*)&BsH[cur][nbase][2 * t    ];
            bhi[ni][1] = *(const uint32_t*)&BsH[cur][nbase][2 * t + 8];
            blo[ni][0] = *(const uint32_t*)&BsL[cur][nbase][2 * t    ];
            blo[ni][1] = *(const uint32_t*)&BsL[cur][nbase][2 * t + 8];
        }
#pragma unroll
        for (int mi = 0; mi < 2; mi++)
#pragma unroll
            for (int ni = 0; ni < 8; ni++) {
                mma_bf16(acc[mi][ni], ahi[mi], bhi[ni]);
                mma_bf16(acc[mi][ni], ahi[mi], blo[ni]);
                mma_bf16(acc[mi][ni], alo[mi], bhi[ni]);
            }

        if (kb + 1 < nb) { stA(nxt, pa0, pa1); stB(nxt, pw); }
        __syncthreads();
    }

    // Epilogue: c0->(g,2t) c1->(g,2t+1) c2->(g+8,2t) c3->(g+8,2t+1)
#pragma unroll
    for (int mi = 0; mi < 2; mi++) {
        int rbase = row0 + wm * 32 + mi * 16 + g;
#pragma unroll
        for (int ni = 0; ni < 8; ni++) {
            int colb = wn * 64 + ni * 8 + 2 * t;
            float b0 = bias ? bias[colb]     : 0.f;
            float b1 = bias ? bias[colb + 1] : 0.f;
            float v0 = acc[mi][ni][0] + b0;
            float v1 = acc[mi][ni][1] + b1;
            float v2 = acc[mi][ni][2] + b0;
            float v3 = acc[mi][ni][3] + b1;
            if (relu) {
                v0 = fmaxf(v0, 0.f); v1 = fmaxf(v1, 0.f);
                v2 = fmaxf(v2, 0.f); v3 = fmaxf(v3, 0.f);
            }
            if (rbase < M)
                *(float2*)(C + (size_t)rbase * TN + colb) = make_float2(v0, v1);
            if (rbase + 8 < M)
                *(float2*)(C + (size_t)(rbase + 8) * TN + colb) = make_float2(v2, v3);
        }
    }
}

// ---------------- GIN fused agg: z = relu(y_i + sum_in y_src + b1) ---------
__global__ __launch_bounds__(256)
void gin_agg_relu_kernel(const float* __restrict__ y,
                         const int* __restrict__ col,
                         const int* __restrict__ rowptr,
                         const float* __restrict__ b1,
                         float* __restrict__ z) {
    int warp = (blockIdx.x * blockDim.x + threadIdx.x) >> 5;
    if (warp >= NN) return;
    int lane = threadIdx.x & 31;
    const float4* yv = (const float4*)y;
    float4 a = yv[(size_t)warp * 32 + lane];
    float ax = a.x, ay = a.y, az = a.z, aw = a.w;
    int b = rowptr[warp], e = rowptr[warp + 1];
    int j = b;
    for (; j + 4 <= e; j += 4) {
        int s0 = col[j], s1 = col[j + 1], s2 = col[j + 2], s3 = col[j + 3];
        float4 v0 = yv[(size_t)s0 * 32 + lane];
        float4 v1 = yv[(size_t)s1 * 32 + lane];
        float4 v2 = yv[(size_t)s2 * 32 + lane];
        float4 v3 = yv[(size_t)s3 * 32 + lane];
        ax += v0.x + v1.x + v2.x + v3.x;
        ay += v0.y + v1.y + v2.y + v3.y;
        az += v0.z + v1.z + v2.z + v3.z;
        aw += v0.w + v1.w + v2.w + v3.w;
    }
    for (; j < e; j++) {
        float4 v = yv[(size_t)col[j] * 32 + lane];
        ax += v.x; ay += v.y; az += v.z; aw += v.w;
    }
    float4 bb = ((const float4*)b1)[lane];
    float4 o;
    o.x = fmaxf(ax + bb.x, 0.f);
    o.y = fmaxf(ay + bb.y, 0.f);
    o.z = fmaxf(az + bb.z, 0.f);
    o.w = fmaxf(aw + bb.w, 0.f);
    ((float4*)z)[(size_t)warp * 32 + lane] = o;
}

// ---------------- GCN agg ---------------------------------------------------
__global__ __launch_bounds__(256)
void gcn_agg_kernel(const float* __restrict__ hs,
                    const float* __restrict__ dinv,
                    const int* __restrict__ col,
                    const int* __restrict__ rowptr,
                    const float* __restrict__ bias,
                    float* __restrict__ s) {
    int warp = (blockIdx.x * blockDim.x + threadIdx.x) >> 5;
    if (warp >= NN) return;
    int lane = threadIdx.x & 31;
    const float4* hv = (const float4*)hs;
    float ax = 0.f, ay = 0.f, az = 0.f, aw = 0.f;
    int b = rowptr[warp], e = rowptr[warp + 1];
    int j = b;
    for (; j + 4 <= e; j += 4) {
        int s0 = col[j], s1 = col[j + 1], s2 = col[j + 2], s3 = col[j + 3];
        float d0 = dinv[s0], d1 = dinv[s1], d2 = dinv[s2], d3 = dinv[s3];
        float4 v0 = hv[(size_t)s0 * 32 + lane];
        float4 v1 = hv[(size_t)s1 * 32 + lane];
        float4 v2 = hv[(size_t)s2 * 32 + lane];
        float4 v3 = hv[(size_t)s3 * 32 + lane];
        ax += d0 * v0.x + d1 * v1.x + d2 * v2.x + d3 * v3.x;
        ay += d0 * v0.y + d1 * v1.y + d2 * v2.y + d3 * v3.y;
        az += d0 * v0.z + d1 * v1.z + d2 * v2.z + d3 * v3.z;
        aw += d0 * v0.w + d1 * v1.w + d2 * v2.w + d3 * v3.w;
    }
    for (; j < e; j++) {
        int sc = col[j];
        float dd = dinv[sc];
        float4 v = hv[(size_t)sc * 32 + lane];
        ax += dd * v.x; ay += dd * v.y; az += dd * v.z; aw += dd * v.w;
    }
    float di = dinv[warp];
    float di2 = di * di;
    float4 hself = hv[(size_t)warp * 32 + lane];
    float4 bb = ((const float4*)bias)[lane];
    float4 o;
    o.x = tanhf(di * ax + hself.x * di2 + bb.x);
    o.y = tanhf(di * ay + hself.y * di2 + bb.y);
    o.z = tanhf(di * az + hself.z * di2 + bb.z);
    o.w = tanhf(di * aw + hself.w * di2 + bb.w);
    ((float4*)s)[(size_t)warp * 32 + lane] = o;
}

// ---------------- global add pool -----------------------------------------
__global__ void pool_kernel(const float* __restrict__ xf,
                            const int* __restrict__ batch,
                            float* __restrict__ g) {
    int idx = blockIdx.x * blockDim.x + threadIdx.x;
    if (idx < NN * HH) {
        int i = idx >> 7;
        int f = idx & 127;
        atomicAdd(&g[batch[i] * HH + f], xf[idx]);
    }
}

// ---------------- post: relu(g @ post_w + b) ------------------------------
__global__ void post_kernel(const float* __restrict__ g,
                            const float* __restrict__ W,
                            const float* __restrict__ bias,
                            float* __restrict__ gp) {
    int r = blockIdx.x;
    int c = threadIdx.x;
    __shared__ float row[HH];
    row[c] = g[(size_t)r * HH + c];
    __syncthreads();
    float acc = bias[c];
#pragma unroll 8
    for (int k = 0; k < HH; k++) acc = fmaf(row[k], W[(size_t)k * HH + c], acc);
    gp[(size_t)r * HH + c] = fmaxf(acc, 0.0f);
}

// ---------------- readout + log_softmax ----------------------------------
__global__ void readout_kernel(const float* __restrict__ gp,
                               const float* __restrict__ W,
                               const float* __restrict__ bias,
                               float* __restrict__ out) {
    int r = blockIdx.x * blockDim.x + threadIdx.x;
    if (r < GG) {
        float logit[CC];
#pragma unroll
        for (int c = 0; c < CC; c++) logit[c] = bias[c];
        for (int k = 0; k < HH; k++) {
            float gv = gp[(size_t)r * HH + k];
#pragma unroll
            for (int c = 0; c < CC; c++)
                logit[c] = fmaf(gv, W[(size_t)k * CC + c], logit[c]);
        }
        float m = logit[0];
#pragma unroll
        for (int c = 1; c < CC; c++) m = fmaxf(m, logit[c]);
        float sum = 0.0f;
#pragma unroll
        for (int c = 0; c < CC; c++) sum += expf(logit[c] - m);
        float lse = m + logf(sum);
#pragma unroll
        for (int c = 0; c < CC; c++) out[(size_t)r * CC + c] = logit[c] - lse;
    }
}

// ---------------- driver ---------------------------------------------------
extern "C" void kernel_launch(void* const* d_in, const int* in_sizes, int n_in,
                              void* d_out, int out_size) {
    const float* x_in   = (const float*)d_in[0];
    const float* s_in   = (const float*)d_in[1];
    const int*   ei     = (const int*)d_in[2];
    const int*   batch  = (const int*)d_in[3];
    const float* pre_w  = (const float*)d_in[4];
    const float* pre_b  = (const float*)d_in[5];
    const float* emb_w  = (const float*)d_in[6];
    const float* emb_b  = (const float*)d_in[7];
    const float* gin_w1 = (const float*)d_in[8];
    const float* gin_b1 = (const float*)d_in[9];
    const float* gin_w2 = (const float*)d_in[10];
    const float* gin_b2 = (const float*)d_in[11];
    const float* gcn_w  = (const float*)d_in[12];
    const float* gcn_b  = (const float*)d_in[13];
    const float* whp_w  = (const float*)d_in[14];
    const float* whp_b  = (const float*)d_in[15];
    const float* post_w = (const float*)d_in[16];
    const float* post_b = (const float*)d_in[17];
    const float* ro_w   = (const float*)d_in[18];
    const float* ro_b   = (const float*)d_in[19];
    float* out = (float*)d_out;

    float *px, *ps, *py, *pz, *phs, *pg, *pgp, *pdinv;
    int *pdegc, *prow, *pcur, *pcol;
    cudaGetSymbolAddress((void**)&px,    d_x);
    cudaGetSymbolAddress((void**)&ps,    d_s);
    cudaGetSymbolAddress((void**)&py,    d_y);
    cudaGetSymbolAddress((void**)&pz,    d_z);
    cudaGetSymbolAddress((void**)&phs,   d_hs);
    cudaGetSymbolAddress((void**)&pg,    d_g);
    cudaGetSymbolAddress((void**)&pgp,   d_gp);
    cudaGetSymbolAddress((void**)&pdinv, d_dinv);
    cudaGetSymbolAddress((void**)&pdegc, d_degc);
    cudaGetSymbolAddress((void**)&prow,  d_rowptr);
    cudaGetSymbolAddress((void**)&pcur,  d_cursor);
    cudaGetSymbolAddress((void**)&pcol,  d_col);

    const int TPB = 256;
    const int eBlocks = (EE + TPB - 1) / TPB;
    const int gemmBlocks = (NN + TM - 1) / TM;
    const int aggBlocks = (NN * 32 + TPB - 1) / TPB;

    // CSR build
    cudaMemsetAsync(pdegc, 0, NN * sizeof(int), 0);
    cudaMemsetAsync(pcur,  0, NN * sizeof(int), 0);
    count_deg_kernel<<<eBlocks, TPB>>>(ei, pdegc);
    scan_deg_kernel<<<1, 1024>>>(pdegc, prow, pdinv);
    fill_csr_kernel<<<eBlocks, TPB>>>(ei, prow, pcur, pcol);

    // pre / embedding
    bf16_gemm_dual<<<gemmBlocks, 256>>>(x_in, FIN, nullptr, 0, pre_w, pre_b, px, NN, 0);
    bf16_gemm_dual<<<gemmBlocks, 256>>>(s_in, NSE, nullptr, 0, emb_w, emb_b, ps, NN, 0);

    for (int i = 0; i < LL; i++) {
        // y = [x|s] @ gin_w1 (split dual-A)
        bf16_gemm_dual<<<gemmBlocks, 256>>>(px, HH, ps, HH,
                                            gin_w1 + (size_t)i * 2 * HH * HH,
                                            nullptr, py, NN, 0);
        // hs = s @ gcn_w[i]
        bf16_gemm_dual<<<gemmBlocks, 256>>>(ps, HH, nullptr, 0,
                                            gcn_w + (size_t)i * HH * HH,
                                            nullptr, phs, NN, 0);
        // z = relu(y + A·y + b1)
        gin_agg_relu_kernel<<<aggBlocks, TPB>>>(py, pcol, prow,
                                                gin_b1 + (size_t)i * HH, pz);
        // s = tanh(norm-agg(hs) + b)
        gcn_agg_kernel<<<aggBlocks, TPB>>>(phs, pdinv, pcol, prow,
                                           gcn_b + (size_t)i * HH, ps);
        // x = relu(z @ gin_w2 + b2)
        bf16_gemm_dual<<<gemmBlocks, 256>>>(pz, HH, nullptr, 0,
                                            gin_w2 + (size_t)i * HH * HH,
                                            gin_b2 + (size_t)i * HH, px, NN, 1);
    }

    // whp on split concat
    bf16_gemm_dual<<<gemmBlocks, 256>>>(px, HH, ps, HH, whp_w, whp_b, py, NN, 0);

    // pool -> post -> readout
    cudaMemsetAsync(pg, 0, GG * HH * sizeof(float), 0);
    pool_kernel<<<(NN * HH + TPB - 1) / TPB, TPB>>>(py, batch, pg);
    post_kernel<<<GG, HH>>>(pg, post_w, post_b, pgp);
    readout_kernel<<<1, GG>>>(pgp, ro_w, ro_b, out);
}

// round 8
// speedup vs baseline: 1.3263x; 1.0175x over previous
#include <cuda_runtime.h>
#include <cuda_bf16.h>
#include <math.h>
#include <stdint.h>

// Problem constants (fixed by the dataset)
#define NN 50000
#define EE 800000
#define HH 128
#define FIN 128
#define NSE 16
#define LL 3
#define CC 10
#define GG 256

// ---------------- scratch (static __device__ — no allocs allowed) ----------
__device__ float d_x [NN * HH];
__device__ float d_s [NN * HH];
__device__ float d_y [NN * HH];
__device__ float d_z [NN * HH];
__device__ float d_hs[NN * HH];
__device__ float d_g [GG * HH];
__device__ float d_gp[GG * HH];
__device__ float d_dinv[NN];
__device__ int   d_degc[NN];
__device__ int   d_rowptr[NN + 1];
__device__ int   d_cursor[NN];
__device__ int   d_col[EE];

// ---------------- CSR build ------------------------------------------------
__global__ void count_deg_kernel(const int* __restrict__ ei, int* __restrict__ degc) {
    int e = blockIdx.x * blockDim.x + threadIdx.x;
    if (e < EE) atomicAdd(&degc[ei[EE + e]], 1);
}

__global__ void scan_deg_kernel(const int* __restrict__ degc,
                                int* __restrict__ rowptr,
                                float* __restrict__ dinv) {
    __shared__ int ssum[1024];
    int t = threadIdx.x;
    const int chunk = (NN + 1023) / 1024;
    int b0 = t * chunk;
    int b1 = b0 + chunk; if (b1 > NN) b1 = NN;
    int sum = 0;
    for (int i = b0; i < b1; i++) sum += degc[i];
    ssum[t] = sum;
    __syncthreads();
    for (int off = 1; off < 1024; off <<= 1) {
        int v = 0;
        if (t >= off) v = ssum[t - off];
        __syncthreads();
        if (t >= off) ssum[t] += v;
        __syncthreads();
    }
    int prefix = (t == 0) ? 0 : ssum[t - 1];
    for (int i = b0; i < b1; i++) {
        int d = degc[i];
        rowptr[i] = prefix;
        prefix += d;
        dinv[i] = rsqrtf((float)d + 1.0f);
    }
    if (t == 1023) rowptr[NN] = ssum[1023];
}

__global__ void fill_csr_kernel(const int* __restrict__ ei,
                                const int* __restrict__ rowptr,
                                int* __restrict__ cursor,
                                int* __restrict__ col) {
    int e = blockIdx.x * blockDim.x + threadIdx.x;
    if (e < EE) {
        int src = ei[e];
        int dst = ei[EE + e];
        int pos = atomicAdd(&cursor[dst], 1);
        col[rowptr[dst] + pos] = src;
    }
}

// ---------------- bf16 split helpers ---------------------------------------
__device__ __forceinline__ void split2_bf16(float a, float b,
                                            uint32_t& hiPair, uint32_t& loPair) {
    __nv_bfloat16 ha = __float2bfloat16_rn(a);
    __nv_bfloat16 hb = __float2bfloat16_rn(b);
    float ra = a - __bfloat162float(ha);
    float rb = b - __bfloat162float(hb);
    __nv_bfloat16 la = __float2bfloat16_rn(ra);
    __nv_bfloat16 lb = __float2bfloat16_rn(rb);
    hiPair = (uint32_t)__bfloat16_as_ushort(ha) |
             ((uint32_t)__bfloat16_as_ushort(hb) << 16);
    loPair = (uint32_t)__bfloat16_as_ushort(la) |
             ((uint32_t)__bfloat16_as_ushort(lb) << 16);
}

__device__ __forceinline__ void mma_bf16(float* c, const uint32_t* a, const uint32_t* b) {
    asm volatile("mma.sync.aligned.m16n8k16.row.col.f32.bf16.bf16.f32 "
        "{%0,%1,%2,%3}, {%4,%5,%6,%7}, {%8,%9}, {%0,%1,%2,%3};"
        : "+f"(c[0]), "+f"(c[1]), "+f"(c[2]), "+f"(c[3])
        : "r"(a[0]), "r"(a[1]), "r"(a[2]), "r"(a[3]), "r"(b[0]), "r"(b[1]));
}

// ---------------- bf16x3 GEMM (split hi/lo in smem, dual-A, rowscale) ------
// C[M,128] = rowscale[r] * (A1[M,K1]@W[0:K1,:] + A2[M,K2]@W[K1:,:]) (+bias)(+relu)
#define TM 128
#define TN 128
#define TKK 16
#define RPAD 24
__global__ __launch_bounds__(256)
void bf16_gemm_dual(const float* __restrict__ A1, int K1,
                    const float* __restrict__ A2, int K2,
                    const float* __restrict__ W,
                    const float* __restrict__ bias,
                    const float* __restrict__ rowscale,
                    float* __restrict__ C, int M, int relu) {
    __shared__ uint16_t AsH[2][TM][RPAD];
    __shared__ uint16_t AsL[2][TM][RPAD];
    __shared__ uint16_t BsH[2][TN][RPAD];
    __shared__ uint16_t BsL[2][TN][RPAD];
    const int tid  = threadIdx.x;
    const int wid  = tid >> 5;
    const int lane = tid & 31;
    const int g    = lane >> 2;      // 0..7
    const int t    = lane & 3;       // 0..3
    const int wm   = wid & 3;        // M warp coord (0..3)
    const int wn   = wid >> 2;       // N warp coord (0..1)
    const int row0 = blockIdx.x * TM;
    const int nb   = (K1 + K2) / TKK;

    float acc[2][8][4];
#pragma unroll
    for (int mi = 0; mi < 2; mi++)
#pragma unroll
        for (int ni = 0; ni < 8; ni++)
#pragma unroll
            for (int q = 0; q < 4; q++) acc[mi][ni][q] = 0.0f;

    const int aRow = tid >> 1;
    const int aOff = (tid & 1) * 8;
    const int bN  = tid & 127;
    const int bG  = (tid >> 7) * 8;

    auto fetchA = [&](int kb, float4& v0, float4& v1) {
        int kg = kb * TKK + aOff;
        const float* Ap; int kl, Kd;
        if (kg < K1) { Ap = A1; kl = kg; Kd = K1; }
        else         { Ap = A2; kl = kg - K1; Kd = K2; }
        if (row0 + aRow < M) {
            const float* p = Ap + (size_t)(row0 + aRow) * Kd + kl;
            v0 = *(const float4*)p;
            v1 = *(const float4*)(p + 4);
        } else {
            v0 = make_float4(0.f, 0.f, 0.f, 0.f);
            v1 = v0;
        }
    };
    auto fetchB = [&](int kb, float* w) {
        int kbase = kb * TKK + bG;
#pragma unroll
        for (int i = 0; i < 8; i++)
            w[i] = W[(size_t)(kbase + i) * TN + bN];
    };
    auto stA = [&](int buf, float4 v0, float4 v1) {
        uint4 h, l;
        split2_bf16(v0.x, v0.y, h.x, l.x);
        split2_bf16(v0.z, v0.w, h.y, l.y);
        split2_bf16(v1.x, v1.y, h.z, l.z);
        split2_bf16(v1.z, v1.w, h.w, l.w);
        *(uint4*)&AsH[buf][aRow][aOff] = h;
        *(uint4*)&AsL[buf][aRow][aOff] = l;
    };
    auto stB = [&](int buf, const float* w) {
        uint4 h, l;
        split2_bf16(w[0], w[1], h.x, l.x);
        split2_bf16(w[2], w[3], h.y, l.y);
        split2_bf16(w[4], w[5], h.z, l.z);
        split2_bf16(w[6], w[7], h.w, l.w);
        *(uint4*)&BsH[buf][bN][bG] = h;
        *(uint4*)&BsL[buf][bN][bG] = l;
    };

    {
        float4 a0, a1; float w[8];
        fetchA(0, a0, a1); fetchB(0, w);
        stA(0, a0, a1); stB(0, w);
    }
    __syncthreads();

    for (int kb = 0; kb < nb; kb++) {
        const int cur = kb & 1, nxt = cur ^ 1;
        float4 pa0, pa1; float pw[8];
        if (kb + 1 < nb) { fetchA(kb + 1, pa0, pa1); fetchB(kb + 1, pw); }

        uint32_t ahi[2][4], alo[2][4];
#pragma unroll
        for (int mi = 0; mi < 2; mi++) {
            int mb = wm * 32 + mi * 16;
            ahi[mi][0] = *(const uint32_t*)&AsH[cur][mb + g    ][2 * t    ];
            ahi[mi][1] = *(const uint32_t*)&AsH[cur][mb + g + 8][2 * t    ];
            ahi[mi][2] = *(const uint32_t*)&AsH[cur][mb + g    ][2 * t + 8];
            ahi[mi][3] = *(const uint32_t*)&AsH[cur][mb + g + 8][2 * t + 8];
            alo[mi][0] = *(const uint32_t*)&AsL[cur][mb + g    ][2 * t    ];
            alo[mi][1] = *(const uint32_t*)&AsL[cur][mb + g + 8][2 * t    ];
            alo[mi][2] = *(const uint32_t*)&AsL[cur][mb + g    ][2 * t + 8];
            alo[mi][3] = *(const uint32_t*)&AsL[cur][mb + g + 8][2 * t + 8];
        }
        uint32_t bhi[8][2], blo[8][2];
#pragma unroll
        for (int ni = 0; ni < 8; ni++) {
            int nbase = wn * 64 + ni * 8 + g;
            bhi[ni][0] = *(const uint32_t*)&BsH[cur][nbase][2 * t    ];
            bhi[ni][1] = *(const uint32_t*)&BsH[cur][nbase][2 * t + 8];
            blo[ni][0] = *(const uint32_t*)&BsL[cur][nbase][2 * t    ];
            blo[ni][1] = *(const uint32_t*)&BsL[cur][nbase][2 * t + 8];
        }
#pragma unroll
        for (int mi = 0; mi < 2; mi++)
#pragma unroll
            for (int ni = 0; ni < 8; ni++) {
                mma_bf16(acc[mi][ni], ahi[mi], bhi[ni]);
                mma_bf16(acc[mi][ni], ahi[mi], blo[ni]);
                mma_bf16(acc[mi][ni], alo[mi], bhi[ni]);
            }

        if (kb + 1 < nb) { stA(nxt, pa0, pa1); stB(nxt, pw); }
        __syncthreads();
    }

    // Epilogue: c0->(g,2t) c1->(g,2t+1) c2->(g+8,2t) c3->(g+8,2t+1)
#pragma unroll
    for (int mi = 0; mi < 2; mi++) {
        int rbase = row0 + wm * 32 + mi * 16 + g;
        float rs0 = 1.f, rs1 = 1.f;
        if (rowscale) {
            if (rbase < M)     rs0 = rowscale[rbase];
            if (rbase + 8 < M) rs1 = rowscale[rbase + 8];
        }
#pragma unroll
        for (int ni = 0; ni < 8; ni++) {
            int colb = wn * 64 + ni * 8 + 2 * t;
            float b0 = bias ? bias[colb]     : 0.f;
            float b1 = bias ? bias[colb + 1] : 0.f;
            float v0 = acc[mi][ni][0] * rs0 + b0;
            float v1 = acc[mi][ni][1] * rs0 + b1;
            float v2 = acc[mi][ni][2] * rs1 + b0;
            float v3 = acc[mi][ni][3] * rs1 + b1;
            if (relu) {
                v0 = fmaxf(v0, 0.f); v1 = fmaxf(v1, 0.f);
                v2 = fmaxf(v2, 0.f); v3 = fmaxf(v3, 0.f);
            }
            if (rbase < M)
                *(float2*)(C + (size_t)rbase * TN + colb) = make_float2(v0, v1);
            if (rbase + 8 < M)
                *(float2*)(C + (size_t)(rbase + 8) * TN + colb) = make_float2(v2, v3);
        }
    }
}

// ---------------- GIN agg: z = relu(y_i + sum_in y_src + b1), unroll 8 -----
__global__ __launch_bounds__(256)
void gin_agg_relu_kernel(const float* __restrict__ y,
                         const int* __restrict__ col,
                         const int* __restrict__ rowptr,
                         const float* __restrict__ b1,
                         float* __restrict__ z) {
    int warp = (blockIdx.x * blockDim.x + threadIdx.x) >> 5;
    if (warp >= NN) return;
    int lane = threadIdx.x & 31;
    const float4* yv = (const float4*)y;
    float4 a = yv[(size_t)warp * 32 + lane];
    float ax = a.x, ay = a.y, az = a.z, aw = a.w;
    int b = rowptr[warp], e = rowptr[warp + 1];
    int j = b;
    for (; j + 8 <= e; j += 8) {
        int c0 = col[j],     c1 = col[j + 1], c2 = col[j + 2], c3 = col[j + 3];
        int c4 = col[j + 4], c5 = col[j + 5], c6 = col[j + 6], c7 = col[j + 7];
        float4 v0 = yv[(size_t)c0 * 32 + lane];
        float4 v1 = yv[(size_t)c1 * 32 + lane];
        float4 v2 = yv[(size_t)c2 * 32 + lane];
        float4 v3 = yv[(size_t)c3 * 32 + lane];
        float4 v4 = yv[(size_t)c4 * 32 + lane];
        float4 v5 = yv[(size_t)c5 * 32 + lane];
        float4 v6 = yv[(size_t)c6 * 32 + lane];
        float4 v7 = yv[(size_t)c7 * 32 + lane];
        ax += (v0.x + v1.x) + (v2.x + v3.x) + (v4.x + v5.x) + (v6.x + v7.x);
        ay += (v0.y + v1.y) + (v2.y + v3.y) + (v4.y + v5.y) + (v6.y + v7.y);
        az += (v0.z + v1.z) + (v2.z + v3.z) + (v4.z + v5.z) + (v6.z + v7.z);
        aw += (v0.w + v1.w) + (v2.w + v3.w) + (v4.w + v5.w) + (v6.w + v7.w);
    }
    for (; j + 2 <= e; j += 2) {
        int c0 = col[j], c1 = col[j + 1];
        float4 v0 = yv[(size_t)c0 * 32 + lane];
        float4 v1 = yv[(size_t)c1 * 32 + lane];
        ax += v0.x + v1.x; ay += v0.y + v1.y;
        az += v0.z + v1.z; aw += v0.w + v1.w;
    }
    for (; j < e; j++) {
        float4 v = yv[(size_t)col[j] * 32 + lane];
        ax += v.x; ay += v.y; az += v.z; aw += v.w;
    }
    float4 bb = ((const float4*)b1)[lane];
    float4 o;
    o.x = fmaxf(ax + bb.x, 0.f);
    o.y = fmaxf(ay + bb.y, 0.f);
    o.z = fmaxf(az + bb.z, 0.f);
    o.w = fmaxf(aw + bb.w, 0.f);
    ((float4*)z)[(size_t)warp * 32 + lane] = o;
}

// ---------------- GCN agg on prescaled hs' = dinv*hs, unroll 8 -------------
// s = tanh(dinv_i * (sum_in hs'_src + hs'_i) + b)
__global__ __launch_bounds__(256)
void gcn_agg_kernel(const float* __restrict__ hsp,
                    const float* __restrict__ dinv,
                    const int* __restrict__ col,
                    const int* __restrict__ rowptr,
                    const float* __restrict__ bias,
                    float* __restrict__ s) {
    int warp = (blockIdx.x * blockDim.x + threadIdx.x) >> 5;
    if (warp >= NN) return;
    int lane = threadIdx.x & 31;
    const float4* hv = (const float4*)hsp;
    float4 a = hv[(size_t)warp * 32 + lane];
    float ax = a.x, ay = a.y, az = a.z, aw = a.w;
    int b = rowptr[warp], e = rowptr[warp + 1];
    int j = b;
    for (; j + 8 <= e; j += 8) {
        int c0 = col[j],     c1 = col[j + 1], c2 = col[j + 2], c3 = col[j + 3];
        int c4 = col[j + 4], c5 = col[j + 5], c6 = col[j + 6], c7 = col[j + 7];
        float4 v0 = hv[(size_t)c0 * 32 + lane];
        float4 v1 = hv[(size_t)c1 * 32 + lane];
        float4 v2 = hv[(size_t)c2 * 32 + lane];
        float4 v3 = hv[(size_t)c3 * 32 + lane];
        float4 v4 = hv[(size_t)c4 * 32 + lane];
        float4 v5 = hv[(size_t)c5 * 32 + lane];
        float4 v6 = hv[(size_t)c6 * 32 + lane];
        float4 v7 = hv[(size_t)c7 * 32 + lane];
        ax += (v0.x + v1.x) + (v2.x + v3.x) + (v4.x + v5.x) + (v6.x + v7.x);
        ay += (v0.y + v1.y) + (v2.y + v3.y) + (v4.y + v5.y) + (v6.y + v7.y);
        az += (v0.z + v1.z) + (v2.z + v3.z) + (v4.z + v5.z) + (v6.z + v7.z);
        aw += (v0.w + v1.w) + (v2.w + v3.w) + (v4.w + v5.w) + (v6.w + v7.w);
    }
    for (; j + 2 <= e; j += 2) {
        int c0 = col[j], c1 = col[j + 1];
        float4 v0 = hv[(size_t)c0 * 32 + lane];
        float4 v1 = hv[(size_t)c1 * 32 + lane];
        ax += v0.x + v1.x; ay += v0.y + v1.y;
        az += v0.z + v1.z; aw += v0.w + v1.w;
    }
    for (; j < e; j++) {
        float4 v = hv[(size_t)col[j] * 32 + lane];
        ax += v.x; ay += v.y; az += v.z; aw += v.w;
    }
    float di = dinv[warp];
    float4 bb = ((const float4*)bias)[lane];
    float4 o;
    o.x = tanhf(di * ax + bb.x);
    o.y = tanhf(di * ay + bb.y);
    o.z = tanhf(di * az + bb.z);
    o.w = tanhf(di * aw + bb.w);
    ((float4*)s)[(size_t)warp * 32 + lane] = o;
}

// ---------------- global add pool -----------------------------------------
__global__ void pool_kernel(const float* __restrict__ xf,
                            const int* __restrict__ batch,
                            float* __restrict__ g) {
    int idx = blockIdx.x * blockDim.x + threadIdx.x;
    if (idx < NN * HH) {
        int i = idx >> 7;
        int f = idx & 127;
        atomicAdd(&g[batch[i] * HH + f], xf[idx]);
    }
}

// ---------------- post: relu(g @ post_w + b) ------------------------------
__global__ void post_kernel(const float* __restrict__ g,
                            const float* __restrict__ W,
                            const float* __restrict__ bias,
                            float* __restrict__ gp) {
    int r = blockIdx.x;
    int c = threadIdx.x;
    __shared__ float row[HH];
    row[c] = g[(size_t)r * HH + c];
    __syncthreads();
    float acc = bias[c];
#pragma unroll 8
    for (int k = 0; k < HH; k++) acc = fmaf(row[k], W[(size_t)k * HH + c], acc);
    gp[(size_t)r * HH + c] = fmaxf(acc, 0.0f);
}

// ---------------- readout + log_softmax ----------------------------------
__global__ void readout_kernel(const float* __restrict__ gp,
                               const float* __restrict__ W,
                               const float* __restrict__ bias,
                               float* __restrict__ out) {
    int r = blockIdx.x * blockDim.x + threadIdx.x;
    if (r < GG) {
        float logit[CC];
#pragma unroll
        for (int c = 0; c < CC; c++) logit[c] = bias[c];
        for (int k = 0; k < HH; k++) {
            float gv = gp[(size_t)r * HH + k];
#pragma unroll
            for (int c = 0; c < CC; c++)
                logit[c] = fmaf(gv, W[(size_t)k * CC + c], logit[c]);
        }
        float m = logit[0];
#pragma unroll
        for (int c = 1; c < CC; c++) m = fmaxf(m, logit[c]);
        float sum = 0.0f;
#pragma unroll
        for (int c = 0; c < CC; c++) sum += expf(logit[c] - m);
        float lse = m + logf(sum);
#pragma unroll
        for (int c = 0; c < CC; c++) out[(size_t)r * CC + c] = logit[c] - lse;
    }
}

// ---------------- driver ---------------------------------------------------
extern "C" void kernel_launch(void* const* d_in, const int* in_sizes, int n_in,
                              void* d_out, int out_size) {
    const float* x_in   = (const float*)d_in[0];
    const float* s_in   = (const float*)d_in[1];
    const int*   ei     = (const int*)d_in[2];
    const int*   batch  = (const int*)d_in[3];
    const float* pre_w  = (const float*)d_in[4];
    const float* pre_b  = (const float*)d_in[5];
    const float* emb_w  = (const float*)d_in[6];
    const float* emb_b  = (const float*)d_in[7];
    const float* gin_w1 = (const float*)d_in[8];
    const float* gin_b1 = (const float*)d_in[9];
    const float* gin_w2 = (const float*)d_in[10];
    const float* gin_b2 = (const float*)d_in[11];
    const float* gcn_w  = (const float*)d_in[12];
    const float* gcn_b  = (const float*)d_in[13];
    const float* whp_w  = (const float*)d_in[14];
    const float* whp_b  = (const float*)d_in[15];
    const float* post_w = (const float*)d_in[16];
    const float* post_b = (const float*)d_in[17];
    const float* ro_w   = (const float*)d_in[18];
    const float* ro_b   = (const float*)d_in[19];
    float* out = (float*)d_out;

    float *px, *ps, *py, *pz, *phs, *pg, *pgp, *pdinv;
    int *pdegc, *prow, *pcur, *pcol;
    cudaGetSymbolAddress((void**)&px,    d_x);
    cudaGetSymbolAddress((void**)&ps,    d_s);
    cudaGetSymbolAddress((void**)&py,    d_y);
    cudaGetSymbolAddress((void**)&pz,    d_z);
    cudaGetSymbolAddress((void**)&phs,   d_hs);
    cudaGetSymbolAddress((void**)&pg,    d_g);
    cudaGetSymbolAddress((void**)&pgp,   d_gp);
    cudaGetSymbolAddress((void**)&pdinv, d_dinv);
    cudaGetSymbolAddress((void**)&pdegc, d_degc);
    cudaGetSymbolAddress((void**)&prow,  d_rowptr);
    cudaGetSymbolAddress((void**)&pcur,  d_cursor);
    cudaGetSymbolAddress((void**)&pcol,  d_col);

    const int TPB = 256;
    const int eBlocks = (EE + TPB - 1) / TPB;
    const int gemmBlocks = (NN + TM - 1) / TM;
    const int aggBlocks = (NN * 32 + TPB - 1) / TPB;

    // CSR build
    cudaMemsetAsync(pdegc, 0, NN * sizeof(int), 0);
    cudaMemsetAsync(pcur,  0, NN * sizeof(int), 0);
    count_deg_kernel<<<eBlocks, TPB>>>(ei, pdegc);
    scan_deg_kernel<<<1, 1024>>>(pdegc, prow, pdinv);
    fill_csr_kernel<<<eBlocks, TPB>>>(ei, prow, pcur, pcol);

    // pre / embedding
    bf16_gemm_dual<<<gemmBlocks, 256>>>(x_in, FIN, nullptr, 0, pre_w, pre_b,
                                        nullptr, px, NN, 0);
    bf16_gemm_dual<<<gemmBlocks, 256>>>(s_in, NSE, nullptr, 0, emb_w, emb_b,
                                        nullptr, ps, NN, 0);

    for (int i = 0; i < LL; i++) {
        // y = [x|s] @ gin_w1 (split dual-A)
        bf16_gemm_dual<<<gemmBlocks, 256>>>(px, HH, ps, HH,
                                            gin_w1 + (size_t)i * 2 * HH * HH,
                                            nullptr, nullptr, py, NN, 0);
        // hs' = dinv * (s @ gcn_w[i])   (rowscale fused in epilogue)
        bf16_gemm_dual<<<gemmBlocks, 256>>>(ps, HH, nullptr, 0,
                                            gcn_w + (size_t)i * HH * HH,
                                            nullptr, pdinv, phs, NN, 0);
        // z = relu(y + A·y + b1)
        gin_agg_relu_kernel<<<aggBlocks, TPB>>>(py, pcol, prow,
                                                gin_b1 + (size_t)i * HH, pz);
        // s = tanh(dinv_i*(sum hs' + hs'_i) + b)
        gcn_agg_kernel<<<aggBlocks, TPB>>>(phs, pdinv, pcol, prow,
                                           gcn_b + (size_t)i * HH, ps);
        // x = relu(z @ gin_w2 + b2)
        bf16_gemm_dual<<<gemmBlocks, 256>>>(pz, HH, nullptr, 0,
                                            gin_w2 + (size_t)i * HH * HH,
                                            gin_b2 + (size_t)i * HH,
                                            nullptr, px, NN, 1);
    }

    // whp on split concat
    bf16_gemm_dual<<<gemmBlocks, 256>>>(px, HH, ps, HH, whp_w, whp_b,
                                        nullptr, py, NN, 0);

    // pool -> post -> readout
    cudaMemsetAsync(pg, 0, GG * HH * sizeof(float), 0);
    pool_kernel<<<(NN * HH + TPB - 1) / TPB, TPB>>>(py, batch, pg);
    post_kernel<<<GG, HH>>>(pg, post_w, post_b, pgp);
    readout_kernel<<<1, GG>>>(pgp, ro_w, ro_b, out);
}

// round 9
// speedup vs baseline: 1.3560x; 1.0224x over previous
#include <cuda_runtime.h>
#include <cuda_bf16.h>
#include <cuda_fp16.h>
#include <math.h>
#include <stdint.h>

// Problem constants (fixed by the dataset)
#define NN 50000
#define EE 800000
#define HH 128
#define FIN 128
#define NSE 16
#define LL 3
#define CC 10
#define GG 256

// ---------------- scratch (static __device__ — no allocs allowed) ----------
__device__ float d_x [NN * HH];
__device__ float d_s [NN * HH];
__device__ float d_y [NN * HH];     // holds fp16 y / fp32 whp out (reused)
__device__ float d_z [NN * HH];
__device__ float d_hs[NN * HH];     // holds fp16 hs'
__device__ float d_g [GG * HH];
__device__ float d_gp[GG * HH];
__device__ float d_dinv[NN];
__device__ int   d_degc[NN];
__device__ int   d_rowptr[NN + 1];
__device__ int   d_cursor[NN];
__device__ int   d_col[EE];

// ---------------- CSR build ------------------------------------------------
__global__ void count_deg_kernel(const int* __restrict__ ei, int* __restrict__ degc) {
    int e = blockIdx.x * blockDim.x + threadIdx.x;
    if (e < EE) atomicAdd(&degc[ei[EE + e]], 1);
}

__global__ void scan_deg_kernel(const int* __restrict__ degc,
                                int* __restrict__ rowptr,
                                float* __restrict__ dinv) {
    __shared__ int ssum[1024];
    int t = threadIdx.x;
    const int chunk = (NN + 1023) / 1024;
    int b0 = t * chunk;
    int b1 = b0 + chunk; if (b1 > NN) b1 = NN;
    int sum = 0;
    for (int i = b0; i < b1; i++) sum += degc[i];
    ssum[t] = sum;
    __syncthreads();
    for (int off = 1; off < 1024; off <<= 1) {
        int v = 0;
        if (t >= off) v = ssum[t - off];
        __syncthreads();
        if (t >= off) ssum[t] += v;
        __syncthreads();
    }
    int prefix = (t == 0) ? 0 : ssum[t - 1];
    for (int i = b0; i < b1; i++) {
        int d = degc[i];
        rowptr[i] = prefix;
        prefix += d;
        dinv[i] = rsqrtf((float)d + 1.0f);
    }
    if (t == 1023) rowptr[NN] = ssum[1023];
}

__global__ void fill_csr_kernel(const int* __restrict__ ei,
                                const int* __restrict__ rowptr,
                                int* __restrict__ cursor,
                                int* __restrict__ col) {
    int e = blockIdx.x * blockDim.x + threadIdx.x;
    if (e < EE) {
        int src = ei[e];
        int dst = ei[EE + e];
        int pos = atomicAdd(&cursor[dst], 1);
        col[rowptr[dst] + pos] = src;
    }
}

// ---------------- bf16 split helpers ---------------------------------------
__device__ __forceinline__ void split2_bf16(float a, float b,
                                            uint32_t& hiPair, uint32_t& loPair) {
    __nv_bfloat16 ha = __float2bfloat16_rn(a);
    __nv_bfloat16 hb = __float2bfloat16_rn(b);
    float ra = a - __bfloat162float(ha);
    float rb = b - __bfloat162float(hb);
    __nv_bfloat16 la = __float2bfloat16_rn(ra);
    __nv_bfloat16 lb = __float2bfloat16_rn(rb);
    hiPair = (uint32_t)__bfloat16_as_ushort(ha) |
             ((uint32_t)__bfloat16_as_ushort(hb) << 16);
    loPair = (uint32_t)__bfloat16_as_ushort(la) |
             ((uint32_t)__bfloat16_as_ushort(lb) << 16);
}

__device__ __forceinline__ void mma_bf16(float* c, const uint32_t* a, const uint32_t* b) {
    asm volatile("mma.sync.aligned.m16n8k16.row.col.f32.bf16.bf16.f32 "
        "{%0,%1,%2,%3}, {%4,%5,%6,%7}, {%8,%9}, {%0,%1,%2,%3};"
        : "+f"(c[0]), "+f"(c[1]), "+f"(c[2]), "+f"(c[3])
        : "r"(a[0]), "r"(a[1]), "r"(a[2]), "r"(a[3]), "r"(b[0]), "r"(b[1]));
}

// ---------------- bf16x3 GEMM (split hi/lo in smem, dual-A, rowscale) ------
// C[M,128] = rowscale[r]*(A1[M,K1]@W[0:K1,:] + A2[M,K2]@W[K1:,:]) (+bias)(+relu)
// outHalf: 0 -> fp32 C, 1 -> fp16 C (half2 stores)
#define TM 128
#define TN 128
#define TKK 16
#define RPAD 24
__global__ __launch_bounds__(256)
void bf16_gemm_dual(const float* __restrict__ A1, int K1,
                    const float* __restrict__ A2, int K2,
                    const float* __restrict__ W,
                    const float* __restrict__ bias,
                    const float* __restrict__ rowscale,
                    void* __restrict__ Cout, int M, int relu, int outHalf) {
    __shared__ uint16_t AsH[2][TM][RPAD];
    __shared__ uint16_t AsL[2][TM][RPAD];
    __shared__ uint16_t BsH[2][TN][RPAD];
    __shared__ uint16_t BsL[2][TN][RPAD];
    const int tid  = threadIdx.x;
    const int wid  = tid >> 5;
    const int lane = tid & 31;
    const int g    = lane >> 2;      // 0..7
    const int t    = lane & 3;       // 0..3
    const int wm   = wid & 3;        // M warp coord (0..3)
    const int wn   = wid >> 2;       // N warp coord (0..1)
    const int row0 = blockIdx.x * TM;
    const int nb   = (K1 + K2) / TKK;

    float acc[2][8][4];
#pragma unroll
    for (int mi = 0; mi < 2; mi++)
#pragma unroll
        for (int ni = 0; ni < 8; ni++)
#pragma unroll
            for (int q = 0; q < 4; q++) acc[mi][ni][q] = 0.0f;

    const int aRow = tid >> 1;
    const int aOff = (tid & 1) * 8;
    const int bN  = tid & 127;
    const int bG  = (tid >> 7) * 8;

    auto fetchA = [&](int kb, float4& v0, float4& v1) {
        int kg = kb * TKK + aOff;
        const float* Ap; int kl, Kd;
        if (kg < K1) { Ap = A1; kl = kg; Kd = K1; }
        else         { Ap = A2; kl = kg - K1; Kd = K2; }
        if (row0 + aRow < M) {
            const float* p = Ap + (size_t)(row0 + aRow) * Kd + kl;
            v0 = *(const float4*)p;
            v1 = *(const float4*)(p + 4);
        } else {
            v0 = make_float4(0.f, 0.f, 0.f, 0.f);
            v1 = v0;
        }
    };
    auto fetchB = [&](int kb, float* w) {
        int kbase = kb * TKK + bG;
#pragma unroll
        for (int i = 0; i < 8; i++)
            w[i] = W[(size_t)(kbase + i) * TN + bN];
    };
    auto stA = [&](int buf, float4 v0, float4 v1) {
        uint4 h, l;
        split2_bf16(v0.x, v0.y, h.x, l.x);
        split2_bf16(v0.z, v0.w, h.y, l.y);
        split2_bf16(v1.x, v1.y, h.z, l.z);
        split2_bf16(v1.z, v1.w, h.w, l.w);
        *(uint4*)&AsH[buf][aRow][aOff] = h;
        *(uint4*)&AsL[buf][aRow][aOff] = l;
    };
    auto stB = [&](int buf, const float* w) {
        uint4 h, l;
        split2_bf16(w[0], w[1], h.x, l.x);
        split2_bf16(w[2], w[3], h.y, l.y);
        split2_bf16(w[4], w[5], h.z, l.z);
        split2_bf16(w[6], w[7], h.w, l.w);
        *(uint4*)&BsH[buf][bN][bG] = h;
        *(uint4*)&BsL[buf][bN][bG] = l;
    };

    {
        float4 a0, a1; float w[8];
        fetchA(0, a0, a1); fetchB(0, w);
        stA(0, a0, a1); stB(0, w);
    }
    __syncthreads();

    for (int kb = 0; kb < nb; kb++) {
        const int cur = kb & 1, nxt = cur ^ 1;
        float4 pa0, pa1; float pw[8];
        if (kb + 1 < nb) { fetchA(kb + 1, pa0, pa1); fetchB(kb + 1, pw); }

        uint32_t ahi[2][4], alo[2][4];
#pragma unroll
        for (int mi = 0; mi < 2; mi++) {
            int mb = wm * 32 + mi * 16;
            ahi[mi][0] = *(const uint32_t*)&AsH[cur][mb + g    ][2 * t    ];
            ahi[mi][1] = *(const uint32_t*)&AsH[cur][mb + g + 8][2 * t    ];
            ahi[mi][2] = *(const uint32_t*)&AsH[cur][mb + g    ][2 * t + 8];
            ahi[mi][3] = *(const uint32_t*)&AsH[cur][mb + g + 8][2 * t + 8];
            alo[mi][0] = *(const uint32_t*)&AsL[cur][mb + g    ][2 * t    ];
            alo[mi][1] = *(const uint32_t*)&AsL[cur][mb + g + 8][2 * t    ];
            alo[mi][2] = *(const uint32_t*)&AsL[cur][mb + g    ][2 * t + 8];
            alo[mi][3] = *(const uint32_t*)&AsL[cur][mb + g + 8][2 * t + 8];
        }
        uint32_t bhi[8][2], blo[8][2];
#pragma unroll
        for (int ni = 0; ni < 8; ni++) {
            int nbase = wn * 64 + ni * 8 + g;
            bhi[ni][0] = *(const uint32_t*)&BsH[cur][nbase][2 * t    ];
            bhi[ni][1] = *(const uint32_t*)&BsH[cur][nbase][2 * t + 8];
            blo[ni][0] = *(const uint32_t*)&BsL[cur][nbase][2 * t    ];
            blo[ni][1] = *(const uint32_t*)&BsL[cur][nbase][2 * t + 8];
        }
#pragma unroll
        for (int mi = 0; mi < 2; mi++)
#pragma unroll
            for (int ni = 0; ni < 8; ni++) {
                mma_bf16(acc[mi][ni], ahi[mi], bhi[ni]);
                mma_bf16(acc[mi][ni], ahi[mi], blo[ni]);
                mma_bf16(acc[mi][ni], alo[mi], bhi[ni]);
            }

        if (kb + 1 < nb) { stA(nxt, pa0, pa1); stB(nxt, pw); }
        __syncthreads();
    }

    // Epilogue: c0->(g,2t) c1->(g,2t+1) c2->(g+8,2t) c3->(g+8,2t+1)
    float* Cf = (float*)Cout;
    __half* Ch = (__half*)Cout;
#pragma unroll
    for (int mi = 0; mi < 2; mi++) {
        int rbase = row0 + wm * 32 + mi * 16 + g;
        float rs0 = 1.f, rs1 = 1.f;
        if (rowscale) {
            if (rbase < M)     rs0 = rowscale[rbase];
            if (rbase + 8 < M) rs1 = rowscale[rbase + 8];
        }
#pragma unroll
        for (int ni = 0; ni < 8; ni++) {
            int colb = wn * 64 + ni * 8 + 2 * t;
            float b0 = bias ? bias[colb]     : 0.f;
            float b1 = bias ? bias[colb + 1] : 0.f;
            float v0 = acc[mi][ni][0] * rs0 + b0;
            float v1 = acc[mi][ni][1] * rs0 + b1;
            float v2 = acc[mi][ni][2] * rs1 + b0;
            float v3 = acc[mi][ni][3] * rs1 + b1;
            if (relu) {
                v0 = fmaxf(v0, 0.f); v1 = fmaxf(v1, 0.f);
                v2 = fmaxf(v2, 0.f); v3 = fmaxf(v3, 0.f);
            }
            if (outHalf) {
                if (rbase < M)
                    *(__half2*)(Ch + (size_t)rbase * TN + colb) = __floats2half2_rn(v0, v1);
                if (rbase + 8 < M)
                    *(__half2*)(Ch + (size_t)(rbase + 8) * TN + colb) = __floats2half2_rn(v2, v3);
            } else {
                if (rbase < M)
                    *(float2*)(Cf + (size_t)rbase * TN + colb) = make_float2(v0, v1);
                if (rbase + 8 < M)
                    *(float2*)(Cf + (size_t)(rbase + 8) * TN + colb) = make_float2(v2, v3);
            }
        }
    }
}

// ---------------- GIN agg (fp16 gather): z = relu(y_i + sum y_src + b1) ----
// warp/node; each lane owns 4 features = one uint2 (2x half2) per row.
__global__ __launch_bounds__(256)
void gin_agg_relu_kernel(const __half* __restrict__ y,
                         const int* __restrict__ col,
                         const int* __restrict__ rowptr,
                         const float* __restrict__ b1,
                         float* __restrict__ z) {
    int warp = (blockIdx.x * blockDim.x + threadIdx.x) >> 5;
    if (warp >= NN) return;
    int lane = threadIdx.x & 31;
    const uint2* yv = (const uint2*)y;   // 32 uint2 per 128-feature row
    float ax, ay, az, aw;
    {
        uint2 v = yv[(size_t)warp * 32 + lane];
        float2 p0 = __half22float2(*(const __half2*)&v.x);
        float2 p1 = __half22float2(*(const __half2*)&v.y);
        ax = p0.x; ay = p0.y; az = p1.x; aw = p1.y;
    }
    int b = rowptr[warp], e = rowptr[warp + 1];
    int j = b;
    for (; j + 8 <= e; j += 8) {
        int c0 = col[j],     c1 = col[j + 1], c2 = col[j + 2], c3 = col[j + 3];
        int c4 = col[j + 4], c5 = col[j + 5], c6 = col[j + 6], c7 = col[j + 7];
        uint2 v0 = yv[(size_t)c0 * 32 + lane];
        uint2 v1 = yv[(size_t)c1 * 32 + lane];
        uint2 v2 = yv[(size_t)c2 * 32 + lane];
        uint2 v3 = yv[(size_t)c3 * 32 + lane];
        uint2 v4 = yv[(size_t)c4 * 32 + lane];
        uint2 v5 = yv[(size_t)c5 * 32 + lane];
        uint2 v6 = yv[(size_t)c6 * 32 + lane];
        uint2 v7 = yv[(size_t)c7 * 32 + lane];
#pragma unroll
        for (int q = 0; q < 8; q++) {
            uint2 v = (q==0)?v0:(q==1)?v1:(q==2)?v2:(q==3)?v3:(q==4)?v4:(q==5)?v5:(q==6)?v6:v7;
            float2 p0 = __half22float2(*(const __half2*)&v.x);
            float2 p1 = __half22float2(*(const __half2*)&v.y);
            ax += p0.x; ay += p0.y; az += p1.x; aw += p1.y;
        }
    }
    for (; j < e; j++) {
        uint2 v = yv[(size_t)col[j] * 32 + lane];
        float2 p0 = __half22float2(*(const __half2*)&v.x);
        float2 p1 = __half22float2(*(const __half2*)&v.y);
        ax += p0.x; ay += p0.y; az += p1.x; aw += p1.y;
    }
    float4 bb = ((const float4*)b1)[lane];
    float4 o;
    o.x = fmaxf(ax + bb.x, 0.f);
    o.y = fmaxf(ay + bb.y, 0.f);
    o.z = fmaxf(az + bb.z, 0.f);
    o.w = fmaxf(aw + bb.w, 0.f);
    ((float4*)z)[(size_t)warp * 32 + lane] = o;
}

// ---------------- GCN agg (fp16 gather on prescaled hs' = dinv*hs) ---------
// s = tanh(dinv_i * (sum hs'_src + hs'_i) + b)
__global__ __launch_bounds__(256)
void gcn_agg_kernel(const __half* __restrict__ hsp,
                    const float* __restrict__ dinv,
                    const int* __restrict__ col,
                    const int* __restrict__ rowptr,
                    const float* __restrict__ bias,
                    float* __restrict__ s) {
    int warp = (blockIdx.x * blockDim.x + threadIdx.x) >> 5;
    if (warp >= NN) return;
    int lane = threadIdx.x & 31;
    const uint2* hv = (const uint2*)hsp;
    float ax, ay, az, aw;
    {
        uint2 v = hv[(size_t)warp * 32 + lane];
        float2 p0 = __half22float2(*(const __half2*)&v.x);
        float2 p1 = __half22float2(*(const __half2*)&v.y);
        ax = p0.x; ay = p0.y; az = p1.x; aw = p1.y;
    }
    int b = rowptr[warp], e = rowptr[warp + 1];
    int j = b;
    for (; j + 8 <= e; j += 8) {
        int c0 = col[j],     c1 = col[j + 1], c2 = col[j + 2], c3 = col[j + 3];
        int c4 = col[j + 4], c5 = col[j + 5], c6 = col[j + 6], c7 = col[j + 7];
        uint2 v0 = hv[(size_t)c0 * 32 + lane];
        uint2 v1 = hv[(size_t)c1 * 32 + lane];
        uint2 v2 = hv[(size_t)c2 * 32 + lane];
        uint2 v3 = hv[(size_t)c3 * 32 + lane];
        uint2 v4 = hv[(size_t)c4 * 32 + lane];
        uint2 v5 = hv[(size_t)c5 * 32 + lane];
        uint2 v6 = hv[(size_t)c6 * 32 + lane];
        uint2 v7 = hv[(size_t)c7 * 32 + lane];
#pragma unroll
        for (int q = 0; q < 8; q++) {
            uint2 v = (q==0)?v0:(q==1)?v1:(q==2)?v2:(q==3)?v3:(q==4)?v4:(q==5)?v5:(q==6)?v6:v7;
            float2 p0 = __half22float2(*(const __half2*)&v.x);
            float2 p1 = __half22float2(*(const __half2*)&v.y);
            ax += p0.x; ay += p0.y; az += p1.x; aw += p1.y;
        }
    }
    for (; j < e; j++) {
        uint2 v = hv[(size_t)col[j] * 32 + lane];
        float2 p0 = __half22float2(*(const __half2*)&v.x);
        float2 p1 = __half22float2(*(const __half2*)&v.y);
        ax += p0.x; ay += p0.y; az += p1.x; aw += p1.y;
    }
    float di = dinv[warp];
    float4 bb = ((const float4*)bias)[lane];
    float4 o;
    o.x = tanhf(di * ax + bb.x);
    o.y = tanhf(di * ay + bb.y);
    o.z = tanhf(di * az + bb.z);
    o.w = tanhf(di * aw + bb.w);
    ((float4*)s)[(size_t)warp * 32 + lane] = o;
}

// ---------------- global add pool -----------------------------------------
__global__ void pool_kernel(const float* __restrict__ xf,
                            const int* __restrict__ batch,
                            float* __restrict__ g) {
    int idx = blockIdx.x * blockDim.x + threadIdx.x;
    if (idx < NN * HH) {
        int i = idx >> 7;
        int f = idx & 127;
        atomicAdd(&g[batch[i] * HH + f], xf[idx]);
    }
}

// ---------------- post: relu(g @ post_w + b) ------------------------------
__global__ void post_kernel(const float* __restrict__ g,
                            const float* __restrict__ W,
                            const float* __restrict__ bias,
                            float* __restrict__ gp) {
    int r = blockIdx.x;
    int c = threadIdx.x;
    __shared__ float row[HH];
    row[c] = g[(size_t)r * HH + c];
    __syncthreads();
    float acc = bias[c];
#pragma unroll 8
    for (int k = 0; k < HH; k++) acc = fmaf(row[k], W[(size_t)k * HH + c], acc);
    gp[(size_t)r * HH + c] = fmaxf(acc, 0.0f);
}

// ---------------- readout + log_softmax ----------------------------------
__global__ void readout_kernel(const float* __restrict__ gp,
                               const float* __restrict__ W,
                               const float* __restrict__ bias,
                               float* __restrict__ out) {
    int r = blockIdx.x * blockDim.x + threadIdx.x;
    if (r < GG) {
        float logit[CC];
#pragma unroll
        for (int c = 0; c < CC; c++) logit[c] = bias[c];
        for (int k = 0; k < HH; k++) {
            float gv = gp[(size_t)r * HH + k];
#pragma unroll
            for (int c = 0; c < CC; c++)
                logit[c] = fmaf(gv, W[(size_t)k * CC + c], logit[c]);
        }
        float m = logit[0];
#pragma unroll
        for (int c = 1; c < CC; c++) m = fmaxf(m, logit[c]);
        float sum = 0.0f;
#pragma unroll
        for (int c = 0; c < CC; c++) sum += expf(logit[c] - m);
        float lse = m + logf(sum);
#pragma unroll
        for (int c = 0; c < CC; c++) out[(size_t)r * CC + c] = logit[c] - lse;
    }
}

// ---------------- driver ---------------------------------------------------
extern "C" void kernel_launch(void* const* d_in, const int* in_sizes, int n_in,
                              void* d_out, int out_size) {
    const float* x_in   = (const float*)d_in[0];
    const float* s_in   = (const float*)d_in[1];
    const int*   ei     = (const int*)d_in[2];
    const int*   batch  = (const int*)d_in[3];
    const float* pre_w  = (const float*)d_in[4];
    const float* pre_b  = (const float*)d_in[5];
    const float* emb_w  = (const float*)d_in[6];
    const float* emb_b  = (const float*)d_in[7];
    const float* gin_w1 = (const float*)d_in[8];
    const float* gin_b1 = (const float*)d_in[9];
    const float* gin_w2 = (const float*)d_in[10];
    const float* gin_b2 = (const float*)d_in[11];
    const float* gcn_w  = (const float*)d_in[12];
    const float* gcn_b  = (const float*)d_in[13];
    const float* whp_w  = (const float*)d_in[14];
    const float* whp_b  = (const float*)d_in[15];
    const float* post_w = (const float*)d_in[16];
    const float* post_b = (const float*)d_in[17];
    const float* ro_w   = (const float*)d_in[18];
    const float* ro_b   = (const float*)d_in[19];
    float* out = (float*)d_out;

    float *px, *ps, *py, *pz, *phs, *pg, *pgp, *pdinv;
    int *pdegc, *prow, *pcur, *pcol;
    cudaGetSymbolAddress((void**)&px,    d_x);
    cudaGetSymbolAddress((void**)&ps,    d_s);
    cudaGetSymbolAddress((void**)&py,    d_y);
    cudaGetSymbolAddress((void**)&pz,    d_z);
    cudaGetSymbolAddress((void**)&phs,   d_hs);
    cudaGetSymbolAddress((void**)&pg,    d_g);
    cudaGetSymbolAddress((void**)&pgp,   d_gp);
    cudaGetSymbolAddress((void**)&pdinv, d_dinv);
    cudaGetSymbolAddress((void**)&pdegc, d_degc);
    cudaGetSymbolAddress((void**)&prow,  d_rowptr);
    cudaGetSymbolAddress((void**)&pcur,  d_cursor);
    cudaGetSymbolAddress((void**)&pcol,  d_col);
    __half* pyh  = (__half*)py;
    __half* phsh = (__half*)phs;

    const int TPB = 256;
    const int eBlocks = (EE + TPB - 1) / TPB;
    const int gemmBlocks = (NN + TM - 1) / TM;
    const int aggBlocks = (NN * 32 + TPB - 1) / TPB;

    // CSR build
    cudaMemsetAsync(pdegc, 0, NN * sizeof(int), 0);
    cudaMemsetAsync(pcur,  0, NN * sizeof(int), 0);
    count_deg_kernel<<<eBlocks, TPB>>>(ei, pdegc);
    scan_deg_kernel<<<1, 1024>>>(pdegc, prow, pdinv);
    fill_csr_kernel<<<eBlocks, TPB>>>(ei, prow, pcur, pcol);

    // pre / embedding (fp32 out)
    bf16_gemm_dual<<<gemmBlocks, 256>>>(x_in, FIN, nullptr, 0, pre_w, pre_b,
                                        nullptr, px, NN, 0, 0);
    bf16_gemm_dual<<<gemmBlocks, 256>>>(s_in, NSE, nullptr, 0, emb_w, emb_b,
                                        nullptr, ps, NN, 0, 0);

    for (int i = 0; i < LL; i++) {
        // y = [x|s] @ gin_w1 -> fp16
        bf16_gemm_dual<<<gemmBlocks, 256>>>(px, HH, ps, HH,
                                            gin_w1 + (size_t)i * 2 * HH * HH,
                                            nullptr, nullptr, pyh, NN, 0, 1);
        // hs' = dinv * (s @ gcn_w[i]) -> fp16
        bf16_gemm_dual<<<gemmBlocks, 256>>>(ps, HH, nullptr, 0,
                                            gcn_w + (size_t)i * HH * HH,
                                            nullptr, pdinv, phsh, NN, 0, 1);
        // z = relu(y + A·y + b1)  (fp16 gather, fp32 accumulate/out)
        gin_agg_relu_kernel<<<aggBlocks, TPB>>>(pyh, pcol, prow,
                                                gin_b1 + (size_t)i * HH, pz);
        // s = tanh(dinv_i*(sum hs' + hs'_i) + b)
        gcn_agg_kernel<<<aggBlocks, TPB>>>(phsh, pdinv, pcol, prow,
                                           gcn_b + (size_t)i * HH, ps);
        // x = relu(z @ gin_w2 + b2) (fp32 out)
        bf16_gemm_dual<<<gemmBlocks, 256>>>(pz, HH, nullptr, 0,
                                            gin_w2 + (size_t)i * HH * HH,
                                            gin_b2 + (size_t)i * HH,
                                            nullptr, px, NN, 1, 0);
    }

    // whp on split concat (fp32 out)
    bf16_gemm_dual<<<gemmBlocks, 256>>>(px, HH, ps, HH, whp_w, whp_b,
                                        nullptr, py, NN, 0, 0);

    // pool -> post -> readout
    cudaMemsetAsync(pg, 0, GG * HH * sizeof(float), 0);
    pool_kernel<<<(NN * HH + TPB - 1) / TPB, TPB>>>(py, batch, pg);
    post_kernel<<<GG, HH>>>(pg, post_w, post_b, pgp);
    readout_kernel<<<1, GG>>>(pgp, ro_w, ro_b, out);
}

// round 11
// speedup vs baseline: 1.6171x; 1.1925x over previous
#include <cuda_runtime.h>
#include <cuda_bf16.h>
#include <cuda_fp16.h>
#include <math.h>
#include <stdint.h>

// Problem constants (fixed by the dataset)
#define NN 50000
#define EE 800000
#define HH 128
#define FIN 128
#define NSE 16
#define LL 3
#define CC 10
#define GG 256

// ---------------- scratch (static __device__ — no allocs allowed) ----------
__device__ float d_x [NN * HH];
__device__ float d_s [NN * HH];
__device__ float d_y [NN * HH];     // fp16 y / fp32 whp out (reused)
__device__ float d_z [NN * HH];
__device__ float d_hs[NN * HH];     // fp16 hs'
__device__ float d_g [GG * HH];
__device__ float d_gp[GG * HH];
__device__ float d_dinv[NN];
__device__ int   d_degc[NN];
__device__ int   d_rowptr[NN + 1];
__device__ int   d_cursor[NN];
__device__ int   d_col[EE];

// ---------------- CSR build ------------------------------------------------
__global__ void count_deg_kernel(const int* __restrict__ ei, int* __restrict__ degc) {
    int e = blockIdx.x * blockDim.x + threadIdx.x;
    if (e < EE) atomicAdd(&degc[ei[EE + e]], 1);
}

__global__ void scan_deg_kernel(const int* __restrict__ degc,
                                int* __restrict__ rowptr,
                                float* __restrict__ dinv) {
    __shared__ int ssum[1024];
    int t = threadIdx.x;
    const int chunk = (NN + 1023) / 1024;
    int b0 = t * chunk;
    int b1 = b0 + chunk; if (b1 > NN) b1 = NN;
    int sum = 0;
    for (int i = b0; i < b1; i++) sum += degc[i];
    ssum[t] = sum;
    __syncthreads();
    for (int off = 1; off < 1024; off <<= 1) {
        int v = 0;
        if (t >= off) v = ssum[t - off];
        __syncthreads();
        if (t >= off) ssum[t] += v;
        __syncthreads();
    }
    int prefix = (t == 0) ? 0 : ssum[t - 1];
    for (int i = b0; i < b1; i++) {
        int d = degc[i];
        rowptr[i] = prefix;
        prefix += d;
        dinv[i] = rsqrtf((float)d + 1.0f);
    }
    if (t == 1023) rowptr[NN] = ssum[1023];
}

__global__ void fill_csr_kernel(const int* __restrict__ ei,
                                const int* __restrict__ rowptr,
                                int* __restrict__ cursor,
                                int* __restrict__ col) {
    int e = blockIdx.x * blockDim.x + threadIdx.x;
    if (e < EE) {
        int src = ei[e];
        int dst = ei[EE + e];
        int pos = atomicAdd(&cursor[dst], 1);
        col[rowptr[dst] + pos] = src;
    }
}

// ---------------- fp16 helpers ---------------------------------------------
__device__ __forceinline__ uint32_t pack2_f16(float a, float b) {
    __half2 h = __floats2half2_rn(a, b);
    return *(uint32_t*)&h;
}
__device__ __forceinline__ void mma_f16(float* c, const uint32_t* a, const uint32_t* b) {
    asm volatile("mma.sync.aligned.m16n8k16.row.col.f32.f16.f16.f32 "
        "{%0,%1,%2,%3}, {%4,%5,%6,%7}, {%8,%9}, {%0,%1,%2,%3};"
        : "+f"(c[0]), "+f"(c[1]), "+f"(c[2]), "+f"(c[3])
        : "r"(a[0]), "r"(a[1]), "r"(a[2]), "r"(a[3]), "r"(b[0]), "r"(b[1]));
}

// ---------------- fp16 GEMM (single mma, dual-A, rowscale) -----------------
// C[M,128] = rowscale[r]*(A1[M,K1]@W[0:K1,:] + A2[M,K2]@W[K1:,:]) (+bias)(+relu)
// outHalf: 0 -> fp32 C, 1 -> fp16 C
#define TM 128
#define TN 128
#define TKK 16
#define RPAD 24
__global__ __launch_bounds__(256)
void fp16_gemm_dual(const float* __restrict__ A1, int K1,
                    const float* __restrict__ A2, int K2,
                    const float* __restrict__ W,
                    const float* __restrict__ bias,
                    const float* __restrict__ rowscale,
                    void* __restrict__ Cout, int M, int relu, int outHalf) {
    __shared__ uint16_t As[2][TM][RPAD];
    __shared__ uint16_t Bs[2][TN][RPAD];
    const int tid  = threadIdx.x;
    const int wid  = tid >> 5;
    const int lane = tid & 31;
    const int g    = lane >> 2;      // 0..7
    const int t    = lane & 3;       // 0..3
    const int wm   = wid & 3;        // M warp coord (0..3)
    const int wn   = wid >> 2;       // N warp coord (0..1)
    const int row0 = blockIdx.x * TM;
    const int nb   = (K1 + K2) / TKK;

    float acc[2][8][4];
#pragma unroll
    for (int mi = 0; mi < 2; mi++)
#pragma unroll
        for (int ni = 0; ni < 8; ni++)
#pragma unroll
            for (int q = 0; q < 4; q++) acc[mi][ni][q] = 0.0f;

    const int aRow = tid >> 1;
    const int aOff = (tid & 1) * 8;
    const int bN  = tid & 127;
    const int bG  = (tid >> 7) * 8;

    auto fetchA = [&](int kb, float4& v0, float4& v1) {
        int kg = kb * TKK + aOff;
        const float* Ap; int kl, Kd;
        if (kg < K1) { Ap = A1; kl = kg; Kd = K1; }
        else         { Ap = A2; kl = kg - K1; Kd = K2; }
        if (row0 + aRow < M) {
            const float* p = Ap + (size_t)(row0 + aRow) * Kd + kl;
            v0 = *(const float4*)p;
            v1 = *(const float4*)(p + 4);
        } else {
            v0 = make_float4(0.f, 0.f, 0.f, 0.f);
            v1 = v0;
        }
    };
    auto fetchB = [&](int kb, float* w) {
        int kbase = kb * TKK + bG;
#pragma unroll
        for (int i = 0; i < 8; i++)
            w[i] = W[(size_t)(kbase + i) * TN + bN];
    };
    auto stA = [&](int buf, float4 v0, float4 v1) {
        uint4 h;
        h.x = pack2_f16(v0.x, v0.y);
        h.y = pack2_f16(v0.z, v0.w);
        h.z = pack2_f16(v1.x, v1.y);
        h.w = pack2_f16(v1.z, v1.w);
        *(uint4*)&As[buf][aRow][aOff] = h;
    };
    auto stB = [&](int buf, const float* w) {
        uint4 h;
        h.x = pack2_f16(w[0], w[1]);
        h.y = pack2_f16(w[2], w[3]);
        h.z = pack2_f16(w[4], w[5]);
        h.w = pack2_f16(w[6], w[7]);
        *(uint4*)&Bs[buf][bN][bG] = h;
    };

    {
        float4 a0, a1; float w[8];
        fetchA(0, a0, a1); fetchB(0, w);
        stA(0, a0, a1); stB(0, w);
    }
    __syncthreads();

    for (int kb = 0; kb < nb; kb++) {
        const int cur = kb & 1, nxt = cur ^ 1;
        float4 pa0, pa1; float pw[8];
        if (kb + 1 < nb) { fetchA(kb + 1, pa0, pa1); fetchB(kb + 1, pw); }

        uint32_t af[2][4];
#pragma unroll
        for (int mi = 0; mi < 2; mi++) {
            int mb = wm * 32 + mi * 16;
            af[mi][0] = *(const uint32_t*)&As[cur][mb + g    ][2 * t    ];
            af[mi][1] = *(const uint32_t*)&As[cur][mb + g + 8][2 * t    ];
            af[mi][2] = *(const uint32_t*)&As[cur][mb + g    ][2 * t + 8];
            af[mi][3] = *(const uint32_t*)&As[cur][mb + g + 8][2 * t + 8];
        }
        uint32_t bf[8][2];
#pragma unroll
        for (int ni = 0; ni < 8; ni++) {
            int nbase = wn * 64 + ni * 8 + g;
            bf[ni][0] = *(const uint32_t*)&Bs[cur][nbase][2 * t    ];
            bf[ni][1] = *(const uint32_t*)&Bs[cur][nbase][2 * t + 8];
        }
#pragma unroll
        for (int mi = 0; mi < 2; mi++)
#pragma unroll
            for (int ni = 0; ni < 8; ni++)
                mma_f16(acc[mi][ni], af[mi], bf[ni]);

        if (kb + 1 < nb) { stA(nxt, pa0, pa1); stB(nxt, pw); }
        __syncthreads();
    }

    // Epilogue: c0->(g,2t) c1->(g,2t+1) c2->(g+8,2t) c3->(g+8,2t+1)
    float* Cf = (float*)Cout;
    __half* Ch = (__half*)Cout;
#pragma unroll
    for (int mi = 0; mi < 2; mi++) {
        int rbase = row0 + wm * 32 + mi * 16 + g;
        float rs0 = 1.f, rs1 = 1.f;
        if (rowscale) {
            if (rbase < M)     rs0 = rowscale[rbase];
            if (rbase + 8 < M) rs1 = rowscale[rbase + 8];
        }
#pragma unroll
        for (int ni = 0; ni < 8; ni++) {
            int colb = wn * 64 + ni * 8 + 2 * t;
            float b0 = bias ? bias[colb]     : 0.f;
            float b1 = bias ? bias[colb + 1] : 0.f;
            float v0 = acc[mi][ni][0] * rs0 + b0;
            float v1 = acc[mi][ni][1] * rs0 + b1;
            float v2 = acc[mi][ni][2] * rs1 + b0;
            float v3 = acc[mi][ni][3] * rs1 + b1;
            if (relu) {
                v0 = fmaxf(v0, 0.f); v1 = fmaxf(v1, 0.f);
                v2 = fmaxf(v2, 0.f); v3 = fmaxf(v3, 0.f);
            }
            if (outHalf) {
                if (rbase < M)
                    *(__half2*)(Ch + (size_t)rbase * TN + colb) = __floats2half2_rn(v0, v1);
                if (rbase + 8 < M)
                    *(__half2*)(Ch + (size_t)(rbase + 8) * TN + colb) = __floats2half2_rn(v2, v3);
            } else {
                if (rbase < M)
                    *(float2*)(Cf + (size_t)rbase * TN + colb) = make_float2(v0, v1);
                if (rbase + 8 < M)
                    *(float2*)(Cf + (size_t)(rbase + 8) * TN + colb) = make_float2(v2, v3);
            }
        }
    }
}

// ---------------- GIN agg (fp16 gather): z = relu(y_i + sum y_src + b1) ----
__global__ __launch_bounds__(256)
void gin_agg_relu_kernel(const __half* __restrict__ y,
                         const int* __restrict__ col,
                         const int* __restrict__ rowptr,
                         const float* __restrict__ b1,
                         float* __restrict__ z) {
    int warp = (blockIdx.x * blockDim.x + threadIdx.x) >> 5;
    if (warp >= NN) return;
    int lane = threadIdx.x & 31;
    const uint2* yv = (const uint2*)y;
    float ax, ay, az, aw;
    {
        uint2 v = yv[(size_t)warp * 32 + lane];
        float2 p0 = __half22float2(*(const __half2*)&v.x);
        float2 p1 = __half22float2(*(const __half2*)&v.y);
        ax = p0.x; ay = p0.y; az = p1.x; aw = p1.y;
    }
    int b = rowptr[warp], e = rowptr[warp + 1];
    int j = b;
    for (; j + 8 <= e; j += 8) {
        int c0 = col[j],     c1 = col[j + 1], c2 = col[j + 2], c3 = col[j + 3];
        int c4 = col[j + 4], c5 = col[j + 5], c6 = col[j + 6], c7 = col[j + 7];
        uint2 v0 = yv[(size_t)c0 * 32 + lane];
        uint2 v1 = yv[(size_t)c1 * 32 + lane];
        uint2 v2 = yv[(size_t)c2 * 32 + lane];
        uint2 v3 = yv[(size_t)c3 * 32 + lane];
        uint2 v4 = yv[(size_t)c4 * 32 + lane];
        uint2 v5 = yv[(size_t)c5 * 32 + lane];
        uint2 v6 = yv[(size_t)c6 * 32 + lane];
        uint2 v7 = yv[(size_t)c7 * 32 + lane];
#pragma unroll
        for (int q = 0; q < 8; q++) {
            uint2 v = (q==0)?v0:(q==1)?v1:(q==2)?v2:(q==3)?v3:(q==4)?v4:(q==5)?v5:(q==6)?v6:v7;
            float2 p0 = __half22float2(*(const __half2*)&v.x);
            float2 p1 = __half22float2(*(const __half2*)&v.y);
            ax += p0.x; ay += p0.y; az += p1.x; aw += p1.y;
        }
    }
    for (; j < e; j++) {
        uint2 v = yv[(size_t)col[j] * 32 + lane];
        float2 p0 = __half22float2(*(const __half2*)&v.x);
        float2 p1 = __half22float2(*(const __half2*)&v.y);
        ax += p0.x; ay += p0.y; az += p1.x; aw += p1.y;
    }
    float4 bb = ((const float4*)b1)[lane];
    float4 o;
    o.x = fmaxf(ax + bb.x, 0.f);
    o.y = fmaxf(ay + bb.y, 0.f);
    o.z = fmaxf(az + bb.z, 0.f);
    o.w = fmaxf(aw + bb.w, 0.f);
    ((float4*)z)[(size_t)warp * 32 + lane] = o;
}

// ---------------- GCN agg (fp16 gather on prescaled hs' = dinv*hs) ---------
__global__ __launch_bounds__(256)
void gcn_agg_kernel(const __half* __restrict__ hsp,
                    const float* __restrict__ dinv,
                    const int* __restrict__ col,
                    const int* __restrict__ rowptr,
                    const float* __restrict__ bias,
                    float* __restrict__ s) {
    int warp = (blockIdx.x * blockDim.x + threadIdx.x) >> 5;
    if (warp >= NN) return;
    int lane = threadIdx.x & 31;
    const uint2* hv = (const uint2*)hsp;
    float ax, ay, az, aw;
    {
        uint2 v = hv[(size_t)warp * 32 + lane];
        float2 p0 = __half22float2(*(const __half2*)&v.x);
        float2 p1 = __half22float2(*(const __half2*)&v.y);
        ax = p0.x; ay = p0.y; az = p1.x; aw = p1.y;
    }
    int b = rowptr[warp], e = rowptr[warp + 1];
    int j = b;
    for (; j + 8 <= e; j += 8) {
        int c0 = col[j],     c1 = col[j + 1], c2 = col[j + 2], c3 = col[j + 3];
        int c4 = col[j + 4], c5 = col[j + 5], c6 = col[j + 6], c7 = col[j + 7];
        uint2 v0 = hv[(size_t)c0 * 32 + lane];
        uint2 v1 = hv[(size_t)c1 * 32 + lane];
        uint2 v2 = hv[(size_t)c2 * 32 + lane];
        uint2 v3 = hv[(size_t)c3 * 32 + lane];
        uint2 v4 = hv[(size_t)c4 * 32 + lane];
        uint2 v5 = hv[(size_t)c5 * 32 + lane];
        uint2 v6 = hv[(size_t)c6 * 32 + lane];
        uint2 v7 = hv[(size_t)c7 * 32 + lane];
#pragma unroll
        for (int q = 0; q < 8; q++) {
            uint2 v = (q==0)?v0:(q==1)?v1:(q==2)?v2:(q==3)?v3:(q==4)?v4:(q==5)?v5:(q==6)?v6:v7;
            float2 p0 = __half22float2(*(const __half2*)&v.x);
            float2 p1 = __half22float2(*(const __half2*)&v.y);
            ax += p0.x; ay += p0.y; az += p1.x; aw += p1.y;
        }
    }
    for (; j < e; j++) {
        uint2 v = hv[(size_t)col[j] * 32 + lane];
        float2 p0 = __half22float2(*(const __half2*)&v.x);
        float2 p1 = __half22float2(*(const __half2*)&v.y);
        ax += p0.x; ay += p0.y; az += p1.x; aw += p1.y;
    }
    float di = dinv[warp];
    float4 bb = ((const float4*)bias)[lane];
    float4 o;
    o.x = tanhf(di * ax + bb.x);
    o.y = tanhf(di * ay + bb.y);
    o.z = tanhf(di * az + bb.z);
    o.w = tanhf(di * aw + bb.w);
    ((float4*)s)[(size_t)warp * 32 + lane] = o;
}

// ---------------- global add pool -----------------------------------------
__global__ void pool_kernel(const float* __restrict__ xf,
                            const int* __restrict__ batch,
                            float* __restrict__ g) {
    int idx = blockIdx.x * blockDim.x + threadIdx.x;
    if (idx < NN * HH) {
        int i = idx >> 7;
        int f = idx & 127;
        atomicAdd(&g[batch[i] * HH + f], xf[idx]);
    }
}

// ---------------- post: relu(g @ post_w + b) ------------------------------
__global__ void post_kernel(const float* __restrict__ g,
                            const float* __restrict__ W,
                            const float* __restrict__ bias,
                            float* __restrict__ gp) {
    int r = blockIdx.x;
    int c = threadIdx.x;
    __shared__ float row[HH];
    row[c] = g[(size_t)r * HH + c];
    __syncthreads();
    float acc = bias[c];
#pragma unroll 8
    for (int k = 0; k < HH; k++) acc = fmaf(row[k], W[(size_t)k * HH + c], acc);
    gp[(size_t)r * HH + c] = fmaxf(acc, 0.0f);
}

// ---------------- readout + log_softmax ----------------------------------
__global__ void readout_kernel(const float* __restrict__ gp,
                               const float* __restrict__ W,
                               const float* __restrict__ bias,
                               float* __restrict__ out) {
    int r = blockIdx.x * blockDim.x + threadIdx.x;
    if (r < GG) {
        float logit[CC];
#pragma unroll
        for (int c = 0; c < CC; c++) logit[c] = bias[c];
        for (int k = 0; k < HH; k++) {
            float gv = gp[(size_t)r * HH + k];
#pragma unroll
            for (int c = 0; c < CC; c++)
                logit[c] = fmaf(gv, W[(size_t)k * CC + c], logit[c]);
        }
        float m = logit[0];
#pragma unroll
        for (int c = 1; c < CC; c++) m = fmaxf(m, logit[c]);
        float sum = 0.0f;
#pragma unroll
        for (int c = 0; c < CC; c++) sum += expf(logit[c] - m);
        float lse = m + logf(sum);
#pragma unroll
        for (int c = 0; c < CC; c++) out[(size_t)r * CC + c] = logit[c] - lse;
    }
}

// ---------------- driver ---------------------------------------------------
extern "C" void kernel_launch(void* const* d_in, const int* in_sizes, int n_in,
                              void* d_out, int out_size) {
    const float* x_in   = (const float*)d_in[0];
    const float* s_in   = (const float*)d_in[1];
    const int*   ei     = (const int*)d_in[2];
    const int*   batch  = (const int*)d_in[3];
    const float* pre_w  = (const float*)d_in[4];
    const float* pre_b  = (const float*)d_in[5];
    const float* emb_w  = (const float*)d_in[6];
    const float* emb_b  = (const float*)d_in[7];
    const float* gin_w1 = (const float*)d_in[8];
    const float* gin_b1 = (const float*)d_in[9];
    const float* gin_w2 = (const float*)d_in[10];
    const float* gin_b2 = (const float*)d_in[11];
    const float* gcn_w  = (const float*)d_in[12];
    const float* gcn_b  = (const float*)d_in[13];
    const float* whp_w  = (const float*)d_in[14];
    const float* whp_b  = (const float*)d_in[15];
    const float* post_w = (const float*)d_in[16];
    const float* post_b = (const float*)d_in[17];
    const float* ro_w   = (const float*)d_in[18];
    const float* ro_b   = (const float*)d_in[19];
    float* out = (float*)d_out;

    float *px, *ps, *py, *pz, *phs, *pg, *pgp, *pdinv;
    int *pdegc, *prow, *pcur, *pcol;
    cudaGetSymbolAddress((void**)&px,    d_x);
    cudaGetSymbolAddress((void**)&ps,    d_s);
    cudaGetSymbolAddress((void**)&py,    d_y);
    cudaGetSymbolAddress((void**)&pz,    d_z);
    cudaGetSymbolAddress((void**)&phs,   d_hs);
    cudaGetSymbolAddress((void**)&pg,    d_g);
    cudaGetSymbolAddress((void**)&pgp,   d_gp);
    cudaGetSymbolAddress((void**)&pdinv, d_dinv);
    cudaGetSymbolAddress((void**)&pdegc, d_degc);
    cudaGetSymbolAddress((void**)&prow,  d_rowptr);
    cudaGetSymbolAddress((void**)&pcur,  d_cursor);
    cudaGetSymbolAddress((void**)&pcol,  d_col);
    __half* pyh  = (__half*)py;
    __half* phsh = (__half*)phs;

    const int TPB = 256;
    const int eBlocks = (EE + TPB - 1) / TPB;
    const int gemmBlocks = (NN + TM - 1) / TM;
    const int aggBlocks = (NN * 32 + TPB - 1) / TPB;

    // CSR build
    cudaMemsetAsync(pdegc, 0, NN * sizeof(int), 0);
    cudaMemsetAsync(pcur,  0, NN * sizeof(int), 0);
    count_deg_kernel<<<eBlocks, TPB>>>(ei, pdegc);
    scan_deg_kernel<<<1, 1024>>>(pdegc, prow, pdinv);
    fill_csr_kernel<<<eBlocks, TPB>>>(ei, prow, pcur, pcol);

    // pre / embedding (fp32 out)
    fp16_gemm_dual<<<gemmBlocks, 256>>>(x_in, FIN, nullptr, 0, pre_w, pre_b,
                                        nullptr, px, NN, 0, 0);
    fp16_gemm_dual<<<gemmBlocks, 256>>>(s_in, NSE, nullptr, 0, emb_w, emb_b,
                                        nullptr, ps, NN, 0, 0);

    for (int i = 0; i < LL; i++) {
        // y = [x|s] @ gin_w1 -> fp16
        fp16_gemm_dual<<<gemmBlocks, 256>>>(px, HH, ps, HH,
                                            gin_w1 + (size_t)i * 2 * HH * HH,
                                            nullptr, nullptr, pyh, NN, 0, 1);
        // hs' = dinv * (s @ gcn_w[i]) -> fp16
        fp16_gemm_dual<<<gemmBlocks, 256>>>(ps, HH, nullptr, 0,
                                            gcn_w + (size_t)i * HH * HH,
                                            nullptr, pdinv, phsh, NN, 0, 1);
        // z = relu(y + A·y + b1)
        gin_agg_relu_kernel<<<aggBlocks, TPB>>>(pyh, pcol, prow,
                                                gin_b1 + (size_t)i * HH, pz);
        // s = tanh(dinv_i*(sum hs' + hs'_i) + b)
        gcn_agg_kernel<<<aggBlocks, TPB>>>(phsh, pdinv, pcol, prow,
                                           gcn_b + (size_t)i * HH, ps);
        // x = relu(z @ gin_w2 + b2) (fp32 out)
        fp16_gemm_dual<<<gemmBlocks, 256>>>(pz, HH, nullptr, 0,
                                            gin_w2 + (size_t)i * HH * HH,
                                            gin_b2 + (size_t)i * HH,
                                            nullptr, px, NN, 1, 0);
    }

    // whp on split concat (fp32 out)
    fp16_gemm_dual<<<gemmBlocks, 256>>>(px, HH, ps, HH, whp_w, whp_b,
                                        nullptr, py, NN, 0, 0);

    // pool -> post -> readout
    cudaMemsetAsync(pg, 0, GG * HH * sizeof(float), 0);
    pool_kernel<<<(NN * HH + TPB - 1) / TPB, TPB>>>(py, batch, pg);
    post_kernel<<<GG, HH>>>(pg, post_w, post_b, pgp);
    readout_kernel<<<1, GG>>>(pgp, ro_w, ro_b, out);
}

// round 12
// speedup vs baseline: 1.7707x; 1.0950x over previous
#include <cuda_runtime.h>
#include <cuda_bf16.h>
#include <cuda_fp16.h>
#include <math.h>
#include <stdint.h>

// Problem constants (fixed by the dataset)
#define NN 50000
#define EE 800000
#define HH 128
#define FIN 128
#define NSE 16
#define LL 3
#define CC 10
#define GG 256

// ---------------- scratch (static __device__ — no allocs allowed) ----------
__device__ float d_x [NN * HH];     // fp16 x stream (half the buffer used)
__device__ float d_s [NN * HH];     // fp16 s stream
__device__ float d_y [NN * HH];     // fp16 y / fp32 whp out (reused)
__device__ float d_z [NN * HH];     // fp16 z
__device__ float d_hs[NN * HH];     // fp16 hs'
__device__ float d_g [GG * HH];
__device__ float d_gp[GG * HH];
__device__ float d_dinv[NN];
__device__ int   d_degc[NN];
__device__ int   d_rowptr[NN + 1];
__device__ int   d_cursor[NN];
__device__ int   d_col[EE];
// fp16 converted inputs + weights (transposed [n][k])
__device__ __half d_xh [NN * FIN];
__device__ __half d_shn[NN * NSE];
__device__ __half d_wpre[128 * 128];
__device__ __half d_wemb[128 * 16];
__device__ __half d_wg1 [3 * 128 * 256];
__device__ __half d_wgc [3 * 128 * 128];
__device__ __half d_wg2 [3 * 128 * 128];
__device__ __half d_wwhp[128 * 256];

// ---------------- CSR build ------------------------------------------------
__global__ void count_deg_kernel(const int* __restrict__ ei, int* __restrict__ degc) {
    int e = blockIdx.x * blockDim.x + threadIdx.x;
    if (e < EE) atomicAdd(&degc[ei[EE + e]], 1);
}

__global__ void scan_deg_kernel(const int* __restrict__ degc,
                                int* __restrict__ rowptr,
                                float* __restrict__ dinv) {
    __shared__ int ssum[1024];
    int t = threadIdx.x;
    const int chunk = (NN + 1023) / 1024;
    int b0 = t * chunk;
    int b1 = b0 + chunk; if (b1 > NN) b1 = NN;
    int sum = 0;
    for (int i = b0; i < b1; i++) sum += degc[i];
    ssum[t] = sum;
    __syncthreads();
    for (int off = 1; off < 1024; off <<= 1) {
        int v = 0;
        if (t >= off) v = ssum[t - off];
        __syncthreads();
        if (t >= off) ssum[t] += v;
        __syncthreads();
    }
    int prefix = (t == 0) ? 0 : ssum[t - 1];
    for (int i = b0; i < b1; i++) {
        int d = degc[i];
        rowptr[i] = prefix;
        prefix += d;
        dinv[i] = rsqrtf((float)d + 1.0f);
    }
    if (t == 1023) rowptr[NN] = ssum[1023];
}

__global__ void fill_csr_kernel(const int* __restrict__ ei,
                                const int* __restrict__ rowptr,
                                int* __restrict__ cursor,
                                int* __restrict__ col) {
    int e = blockIdx.x * blockDim.x + threadIdx.x;
    if (e < EE) {
        int src = ei[e];
        int dst = ei[EE + e];
        int pos = atomicAdd(&cursor[dst], 1);
        col[rowptr[dst] + pos] = src;
    }
}

// ---------------- prep: fp32->fp16 + weight transpose ----------------------
__global__ void f2h_kernel(const float* __restrict__ src, __half* __restrict__ dst, int n4) {
    int i = blockIdx.x * blockDim.x + threadIdx.x;
    if (i < n4) {
        float4 v = ((const float4*)src)[i];
        __half2 h0 = __floats2half2_rn(v.x, v.y);
        __half2 h1 = __floats2half2_rn(v.z, v.w);
        uint2 p; p.x = *(uint32_t*)&h0; p.y = *(uint32_t*)&h1;
        ((uint2*)dst)[i] = p;
    }
}
// src: [nmat][K][128] fp32 -> dst: [nmat][128][K] fp16
__global__ void wtrans_kernel(const float* __restrict__ src, __half* __restrict__ dst,
                              int K, int total) {
    int i = blockIdx.x * blockDim.x + threadIdx.x;
    if (i < total) {
        int n = i & 127;
        int k = (i >> 7) % K;
        int m = i / (K * 128);
        dst[(size_t)m * 128 * K + (size_t)n * K + k] = __float2half(src[i]);
    }
}

// ---------------- cp.async helpers ----------------------------------------
__device__ __forceinline__ uint32_t smem_u32(const void* p) {
    uint32_t a;
    asm("{ .reg .u64 t; cvta.to.shared.u64 t, %1; cvt.u32.u64 %0, t; }"
        : "=r"(a) : "l"(p));
    return a;
}
__device__ __forceinline__ void cp16(uint32_t dst, const void* src, int sz) {
    asm volatile("cp.async.cg.shared.global [%0], [%1], 16, %2;"
                 :: "r"(dst), "l"(src), "r"(sz));
}
#define CP_COMMIT() asm volatile("cp.async.commit_group;")
#define CP_WAIT(n)  asm volatile("cp.async.wait_group %0;" :: "n"(n))

__device__ __forceinline__ void mma_f16(float* c, const uint32_t* a, const uint32_t* b) {
    asm volatile("mma.sync.aligned.m16n8k16.row.col.f32.f16.f16.f32 "
        "{%0,%1,%2,%3}, {%4,%5,%6,%7}, {%8,%9}, {%0,%1,%2,%3};"
        : "+f"(c[0]), "+f"(c[1]), "+f"(c[2]), "+f"(c[3])
        : "r"(a[0]), "r"(a[1]), "r"(a[2]), "r"(a[3]), "r"(b[0]), "r"(b[1]));
}

// ---------------- fp16 GEMM (cp.async staged, 3-stage, dual-A) -------------
// C[M,128] = rowscale[r]*(A1[M,K1]@Wt^T + A2[M,K2]@...) (+bias)(+relu)
// A1/A2: fp16 [M][K]; Wt: fp16 [128][Ktot] (n-major, pre-transposed)
#define TM 128
#define TN 128
#define TKK 16
#define RPAD 24
#define NS 3
__global__ __launch_bounds__(256)
void h_gemm_dual(const __half* __restrict__ A1, int K1,
                 const __half* __restrict__ A2, int K2,
                 const __half* __restrict__ Wt,
                 const float* __restrict__ bias,
                 const float* __restrict__ rowscale,
                 void* __restrict__ Cout, int M, int relu, int outHalf) {
    __shared__ __half As[NS][TM][RPAD];
    __shared__ __half Bs[NS][TN][RPAD];
    const int tid  = threadIdx.x;
    const int wid  = tid >> 5;
    const int lane = tid & 31;
    const int g    = lane >> 2;
    const int t    = lane & 3;
    const int wm   = wid & 3;
    const int wn   = wid >> 2;
    const int row0 = blockIdx.x * TM;
    const int Ktot = K1 + K2;
    const int nb   = Ktot / TKK;

    float acc[2][8][4];
#pragma unroll
    for (int mi = 0; mi < 2; mi++)
#pragma unroll
        for (int ni = 0; ni < 8; ni++)
#pragma unroll
            for (int q = 0; q < 4; q++) acc[mi][ni][q] = 0.0f;

    const int r  = tid >> 1;           // staging row (A row / B n-row)
    const int ch = (tid & 1) * 8;      // chunk offset (halves)
    const int grow = row0 + r;

    auto issue = [&](int kb) {
        int st = kb % NS;
        int kg = kb * TKK + ch;
        const __half* sa;
        if (kg < K1) sa = A1 + (size_t)grow * K1 + kg;
        else         sa = A2 + (size_t)grow * K2 + (kg - K1);
        cp16(smem_u32(&As[st][r][ch]), sa, (grow < M) ? 16 : 0);
        cp16(smem_u32(&Bs[st][r][ch]), Wt + (size_t)r * Ktot + kg, 16);
    };

    // prefetch NS-1 groups (empty-commit if nb is small)
#pragma unroll
    for (int s = 0; s < NS - 1; s++) {
        if (s < nb) issue(s);
        CP_COMMIT();
    }

    for (int kb = 0; kb < nb; kb++) {
        CP_WAIT(NS - 2);
        __syncthreads();
        if (kb + NS - 1 < nb) issue(kb + NS - 1);
        CP_COMMIT();

        const int cur = kb % NS;
        uint32_t af[2][4];
#pragma unroll
        for (int mi = 0; mi < 2; mi++) {
            int mb = wm * 32 + mi * 16;
            af[mi][0] = *(const uint32_t*)&As[cur][mb + g    ][2 * t    ];
            af[mi][1] = *(const uint32_t*)&As[cur][mb + g + 8][2 * t    ];
            af[mi][2] = *(const uint32_t*)&As[cur][mb + g    ][2 * t + 8];
            af[mi][3] = *(const uint32_t*)&As[cur][mb + g + 8][2 * t + 8];
        }
        uint32_t bf[8][2];
#pragma unroll
        for (int ni = 0; ni < 8; ni++) {
            int nbase = wn * 64 + ni * 8 + g;
            bf[ni][0] = *(const uint32_t*)&Bs[cur][nbase][2 * t    ];
            bf[ni][1] = *(const uint32_t*)&Bs[cur][nbase][2 * t + 8];
        }
#pragma unroll
        for (int mi = 0; mi < 2; mi++)
#pragma unroll
            for (int ni = 0; ni < 8; ni++)
                mma_f16(acc[mi][ni], af[mi], bf[ni]);
    }

    // Epilogue: c0->(g,2t) c1->(g,2t+1) c2->(g+8,2t) c3->(g+8,2t+1)
    float* Cf = (float*)Cout;
    __half* Ch = (__half*)Cout;
#pragma unroll
    for (int mi = 0; mi < 2; mi++) {
        int rbase = row0 + wm * 32 + mi * 16 + g;
        float rs0 = 1.f, rs1 = 1.f;
        if (rowscale) {
            if (rbase < M)     rs0 = rowscale[rbase];
            if (rbase + 8 < M) rs1 = rowscale[rbase + 8];
        }
#pragma unroll
        for (int ni = 0; ni < 8; ni++) {
            int colb = wn * 64 + ni * 8 + 2 * t;
            float b0 = bias ? bias[colb]     : 0.f;
            float b1 = bias ? bias[colb + 1] : 0.f;
            float v0 = acc[mi][ni][0] * rs0 + b0;
            float v1 = acc[mi][ni][1] * rs0 + b1;
            float v2 = acc[mi][ni][2] * rs1 + b0;
            float v3 = acc[mi][ni][3] * rs1 + b1;
            if (relu) {
                v0 = fmaxf(v0, 0.f); v1 = fmaxf(v1, 0.f);
                v2 = fmaxf(v2, 0.f); v3 = fmaxf(v3, 0.f);
            }
            if (outHalf) {
                if (rbase < M)
                    *(__half2*)(Ch + (size_t)rbase * TN + colb) = __floats2half2_rn(v0, v1);
                if (rbase + 8 < M)
                    *(__half2*)(Ch + (size_t)(rbase + 8) * TN + colb) = __floats2half2_rn(v2, v3);
            } else {
                if (rbase < M)
                    *(float2*)(Cf + (size_t)rbase * TN + colb) = make_float2(v0, v1);
                if (rbase + 8 < M)
                    *(float2*)(Cf + (size_t)(rbase + 8) * TN + colb) = make_float2(v2, v3);
            }
        }
    }
}

// ---------------- GIN agg (fp16 gather/out): z = relu(y_i + sum y + b1) ----
__global__ __launch_bounds__(256)
void gin_agg_relu_kernel(const __half* __restrict__ y,
                         const int* __restrict__ col,
                         const int* __restrict__ rowptr,
                         const float* __restrict__ b1,
                         __half* __restrict__ z) {
    int warp = (blockIdx.x * blockDim.x + threadIdx.x) >> 5;
    if (warp >= NN) return;
    int lane = threadIdx.x & 31;
    const uint2* yv = (const uint2*)y;
    float ax, ay, az, aw;
    {
        uint2 v = yv[(size_t)warp * 32 + lane];
        float2 p0 = __half22float2(*(const __half2*)&v.x);
        float2 p1 = __half22float2(*(const __half2*)&v.y);
        ax = p0.x; ay = p0.y; az = p1.x; aw = p1.y;
    }
    int b = rowptr[warp], e = rowptr[warp + 1];
    int j = b;
    for (; j + 8 <= e; j += 8) {
        int c0 = col[j],     c1 = col[j + 1], c2 = col[j + 2], c3 = col[j + 3];
        int c4 = col[j + 4], c5 = col[j + 5], c6 = col[j + 6], c7 = col[j + 7];
        uint2 v0 = yv[(size_t)c0 * 32 + lane];
        uint2 v1 = yv[(size_t)c1 * 32 + lane];
        uint2 v2 = yv[(size_t)c2 * 32 + lane];
        uint2 v3 = yv[(size_t)c3 * 32 + lane];
        uint2 v4 = yv[(size_t)c4 * 32 + lane];
        uint2 v5 = yv[(size_t)c5 * 32 + lane];
        uint2 v6 = yv[(size_t)c6 * 32 + lane];
        uint2 v7 = yv[(size_t)c7 * 32 + lane];
#pragma unroll
        for (int q = 0; q < 8; q++) {
            uint2 v = (q==0)?v0:(q==1)?v1:(q==2)?v2:(q==3)?v3:(q==4)?v4:(q==5)?v5:(q==6)?v6:v7;
            float2 p0 = __half22float2(*(const __half2*)&v.x);
            float2 p1 = __half22float2(*(const __half2*)&v.y);
            ax += p0.x; ay += p0.y; az += p1.x; aw += p1.y;
        }
    }
    for (; j < e; j++) {
        uint2 v = yv[(size_t)col[j] * 32 + lane];
        float2 p0 = __half22float2(*(const __half2*)&v.x);
        float2 p1 = __half22float2(*(const __half2*)&v.y);
        ax += p0.x; ay += p0.y; az += p1.x; aw += p1.y;
    }
    float4 bb = ((const float4*)b1)[lane];
    __half2 o0 = __floats2half2_rn(fmaxf(ax + bb.x, 0.f), fmaxf(ay + bb.y, 0.f));
    __half2 o1 = __floats2half2_rn(fmaxf(az + bb.z, 0.f), fmaxf(aw + bb.w, 0.f));
    uint2 p; p.x = *(uint32_t*)&o0; p.y = *(uint32_t*)&o1;
    ((uint2*)z)[(size_t)warp * 32 + lane] = p;
}

// ---------------- GCN agg (fp16 gather/out on prescaled hs') ---------------
__global__ __launch_bounds__(256)
void gcn_agg_kernel(const __half* __restrict__ hsp,
                    const float* __restrict__ dinv,
                    const int* __restrict__ col,
                    const int* __restrict__ rowptr,
                    const float* __restrict__ bias,
                    __half* __restrict__ s) {
    int warp = (blockIdx.x * blockDim.x + threadIdx.x) >> 5;
    if (warp >= NN) return;
    int lane = threadIdx.x & 31;
    const uint2* hv = (const uint2*)hsp;
    float ax, ay, az, aw;
    {
        uint2 v = hv[(size_t)warp * 32 + lane];
        float2 p0 = __half22float2(*(const __half2*)&v.x);
        float2 p1 = __half22float2(*(const __half2*)&v.y);
        ax = p0.x; ay = p0.y; az = p1.x; aw = p1.y;
    }
    int b = rowptr[warp], e = rowptr[warp + 1];
    int j = b;
    for (; j + 8 <= e; j += 8) {
        int c0 = col[j],     c1 = col[j + 1], c2 = col[j + 2], c3 = col[j + 3];
        int c4 = col[j + 4], c5 = col[j + 5], c6 = col[j + 6], c7 = col[j + 7];
        uint2 v0 = hv[(size_t)c0 * 32 + lane];
        uint2 v1 = hv[(size_t)c1 * 32 + lane];
        uint2 v2 = hv[(size_t)c2 * 32 + lane];
        uint2 v3 = hv[(size_t)c3 * 32 + lane];
        uint2 v4 = hv[(size_t)c4 * 32 + lane];
        uint2 v5 = hv[(size_t)c5 * 32 + lane];
        uint2 v6 = hv[(size_t)c6 * 32 + lane];
        uint2 v7 = hv[(size_t)c7 * 32 + lane];
#pragma unroll
        for (int q = 0; q < 8; q++) {
            uint2 v = (q==0)?v0:(q==1)?v1:(q==2)?v2:(q==3)?v3:(q==4)?v4:(q==5)?v5:(q==6)?v6:v7;
            float2 p0 = __half22float2(*(const __half2*)&v.x);
            float2 p1 = __half22float2(*(const __half2*)&v.y);
            ax += p0.x; ay += p0.y; az += p1.x; aw += p1.y;
        }
    }
    for (; j < e; j++) {
        uint2 v = hv[(size_t)col[j] * 32 + lane];
        float2 p0 = __half22float2(*(const __half2*)&v.x);
        float2 p1 = __half22float2(*(const __half2*)&v.y);
        ax += p0.x; ay += p0.y; az += p1.x; aw += p1.y;
    }
    float di = dinv[warp];
    float4 bb = ((const float4*)bias)[lane];
    __half2 o0 = __floats2half2_rn(tanhf(di * ax + bb.x), tanhf(di * ay + bb.y));
    __half2 o1 = __floats2half2_rn(tanhf(di * az + bb.z), tanhf(di * aw + bb.w));
    uint2 p; p.x = *(uint32_t*)&o0; p.y = *(uint32_t*)&o1;
    ((uint2*)s)[(size_t)warp * 32 + lane] = p;
}

// ---------------- global add pool -----------------------------------------
__global__ void pool_kernel(const float* __restrict__ xf,
                            const int* __restrict__ batch,
                            float* __restrict__ g) {
    int idx = blockIdx.x * blockDim.x + threadIdx.x;
    if (idx < NN * HH) {
        int i = idx >> 7;
        int f = idx & 127;
        atomicAdd(&g[batch[i] * HH + f], xf[idx]);
    }
}

// ---------------- post: relu(g @ post_w + b) ------------------------------
__global__ void post_kernel(const float* __restrict__ g,
                            const float* __restrict__ W,
                            const float* __restrict__ bias,
                            float* __restrict__ gp) {
    int r = blockIdx.x;
    int c = threadIdx.x;
    __shared__ float row[HH];
    row[c] = g[(size_t)r * HH + c];
    __syncthreads();
    float acc = bias[c];
#pragma unroll 8
    for (int k = 0; k < HH; k++) acc = fmaf(row[k], W[(size_t)k * HH + c], acc);
    gp[(size_t)r * HH + c] = fmaxf(acc, 0.0f);
}

// ---------------- readout + log_softmax ----------------------------------
__global__ void readout_kernel(const float* __restrict__ gp,
                               const float* __restrict__ W,
                               const float* __restrict__ bias,
                               float* __restrict__ out) {
    int r = blockIdx.x * blockDim.x + threadIdx.x;
    if (r < GG) {
        float logit[CC];
#pragma unroll
        for (int c = 0; c < CC; c++) logit[c] = bias[c];
        for (int k = 0; k < HH; k++) {
            float gv = gp[(size_t)r * HH + k];
#pragma unroll
            for (int c = 0; c < CC; c++)
                logit[c] = fmaf(gv, W[(size_t)k * CC + c], logit[c]);
        }
        float m = logit[0];
#pragma unroll
        for (int c = 1; c < CC; c++) m = fmaxf(m, logit[c]);
        float sum = 0.0f;
#pragma unroll
        for (int c = 0; c < CC; c++) sum += expf(logit[c] - m);
        float lse = m + logf(sum);
#pragma unroll
        for (int c = 0; c < CC; c++) out[(size_t)r * CC + c] = logit[c] - lse;
    }
}

// ---------------- driver ---------------------------------------------------
extern "C" void kernel_launch(void* const* d_in, const int* in_sizes, int n_in,
                              void* d_out, int out_size) {
    const float* x_in   = (const float*)d_in[0];
    const float* s_in   = (const float*)d_in[1];
    const int*   ei     = (const int*)d_in[2];
    const int*   batch  = (const int*)d_in[3];
    const float* pre_w  = (const float*)d_in[4];
    const float* pre_b  = (const float*)d_in[5];
    const float* emb_w  = (const float*)d_in[6];
    const float* emb_b  = (const float*)d_in[7];
    const float* gin_w1 = (const float*)d_in[8];
    const float* gin_b1 = (const float*)d_in[9];
    const float* gin_w2 = (const float*)d_in[10];
    const float* gin_b2 = (const float*)d_in[11];
    const float* gcn_w  = (const float*)d_in[12];
    const float* gcn_b  = (const float*)d_in[13];
    const float* whp_w  = (const float*)d_in[14];
    const float* whp_b  = (const float*)d_in[15];
    const float* post_w = (const float*)d_in[16];
    const float* post_b = (const float*)d_in[17];
    const float* ro_w   = (const float*)d_in[18];
    const float* ro_b   = (const float*)d_in[19];
    float* out = (float*)d_out;

    float *px, *ps, *py, *pz, *phs, *pg, *pgp, *pdinv;
    int *pdegc, *prow, *pcur, *pcol;
    __half *pxh, *pshn, *pwpre, *pwemb, *pwg1, *pwgc, *pwg2, *pwwhp;
    cudaGetSymbolAddress((void**)&px,    d_x);
    cudaGetSymbolAddress((void**)&ps,    d_s);
    cudaGetSymbolAddress((void**)&py,    d_y);
    cudaGetSymbolAddress((void**)&pz,    d_z);
    cudaGetSymbolAddress((void**)&phs,   d_hs);
    cudaGetSymbolAddress((void**)&pg,    d_g);
    cudaGetSymbolAddress((void**)&pgp,   d_gp);
    cudaGetSymbolAddress((void**)&pdinv, d_dinv);
    cudaGetSymbolAddress((void**)&pdegc, d_degc);
    cudaGetSymbolAddress((void**)&prow,  d_rowptr);
    cudaGetSymbolAddress((void**)&pcur,  d_cursor);
    cudaGetSymbolAddress((void**)&pcol,  d_col);
    cudaGetSymbolAddress((void**)&pxh,   d_xh);
    cudaGetSymbolAddress((void**)&pshn,  d_shn);
    cudaGetSymbolAddress((void**)&pwpre, d_wpre);
    cudaGetSymbolAddress((void**)&pwemb, d_wemb);
    cudaGetSymbolAddress((void**)&pwg1,  d_wg1);
    cudaGetSymbolAddress((void**)&pwgc,  d_wgc);
    cudaGetSymbolAddress((void**)&pwg2,  d_wg2);
    cudaGetSymbolAddress((void**)&pwwhp, d_wwhp);
    __half* pxH  = (__half*)px;
    __half* psH  = (__half*)ps;
    __half* pyH  = (__half*)py;
    __half* pzH  = (__half*)pz;
    __half* phsH = (__half*)phs;

    const int TPB = 256;
    const int eBlocks = (EE + TPB - 1) / TPB;
    const int gemmBlocks = (NN + TM - 1) / TM;
    const int aggBlocks = (NN * 32 + TPB - 1) / TPB;

    // ---- prep: conversions + weight transposes ----
    f2h_kernel<<<(NN * FIN / 4 + TPB - 1) / TPB, TPB>>>(x_in, pxh, NN * FIN / 4);
    f2h_kernel<<<(NN * NSE / 4 + TPB - 1) / TPB, TPB>>>(s_in, pshn, NN * NSE / 4);
    wtrans_kernel<<<(128 * 128 + TPB - 1) / TPB, TPB>>>(pre_w, pwpre, 128, 128 * 128);
    wtrans_kernel<<<(16 * 128 + TPB - 1) / TPB, TPB>>>(emb_w, pwemb, 16, 16 * 128);
    wtrans_kernel<<<(3 * 256 * 128 + TPB - 1) / TPB, TPB>>>(gin_w1, pwg1, 256, 3 * 256 * 128);
    wtrans_kernel<<<(3 * 128 * 128 + TPB - 1) / TPB, TPB>>>(gcn_w, pwgc, 128, 3 * 128 * 128);
    wtrans_kernel<<<(3 * 128 * 128 + TPB - 1) / TPB, TPB>>>(gin_w2, pwg2, 128, 3 * 128 * 128);
    wtrans_kernel<<<(256 * 128 + TPB - 1) / TPB, TPB>>>(whp_w, pwwhp, 256, 256 * 128);

    // ---- CSR build ----
    cudaMemsetAsync(pdegc, 0, NN * sizeof(int), 0);
    cudaMemsetAsync(pcur,  0, NN * sizeof(int), 0);
    count_deg_kernel<<<eBlocks, TPB>>>(ei, pdegc);
    scan_deg_kernel<<<1, 1024>>>(pdegc, prow, pdinv);
    fill_csr_kernel<<<eBlocks, TPB>>>(ei, prow, pcur, pcol);

    // ---- pre / embedding (fp16 out) ----
    h_gemm_dual<<<gemmBlocks, 256>>>(pxh, FIN, nullptr, 0, pwpre, pre_b,
                                     nullptr, pxH, NN, 0, 1);
    h_gemm_dual<<<gemmBlocks, 256>>>(pshn, NSE, nullptr, 0, pwemb, emb_b,
                                     nullptr, psH, NN, 0, 1);

    for (int i = 0; i < LL; i++) {
        // y = [x|s] @ gin_w1 -> fp16
        h_gemm_dual<<<gemmBlocks, 256>>>(pxH, HH, psH, HH,
                                         pwg1 + (size_t)i * 128 * 256,
                                         nullptr, nullptr, pyH, NN, 0, 1);
        // hs' = dinv * (s @ gcn_w[i]) -> fp16
        h_gemm_dual<<<gemmBlocks, 256>>>(psH, HH, nullptr, 0,
                                         pwgc + (size_t)i * 128 * 128,
                                         nullptr, pdinv, phsH, NN, 0, 1);
        // z = relu(y + A·y + b1) -> fp16
        gin_agg_relu_kernel<<<aggBlocks, TPB>>>(pyH, pcol, prow,
                                                gin_b1 + (size_t)i * HH, pzH);
        // s = tanh(dinv_i*(sum hs' + hs'_i) + b) -> fp16
        gcn_agg_kernel<<<aggBlocks, TPB>>>(phsH, pdinv, pcol, prow,
                                           gcn_b + (size_t)i * HH, psH);
        // x = relu(z @ gin_w2 + b2) -> fp16
        h_gemm_dual<<<gemmBlocks, 256>>>(pzH, HH, nullptr, 0,
                                         pwg2 + (size_t)i * 128 * 128,
                                         gin_b2 + (size_t)i * HH,
                                         nullptr, pxH, NN, 1, 1);
    }

    // whp on split concat (fp32 out for pooling)
    h_gemm_dual<<<gemmBlocks, 256>>>(pxH, HH, psH, HH, pwwhp, whp_b,
                                     nullptr, py, NN, 0, 0);

    // pool -> post -> readout
    cudaMemsetAsync(pg, 0, GG * HH * sizeof(float), 0);
    pool_kernel<<<(NN * HH + TPB - 1) / TPB, TPB>>>(py, batch, pg);
    post_kernel<<<GG, HH>>>(pg, post_w, post_b, pgp);
    readout_kernel<<<1, GG>>>(pgp, ro_w, ro_b, out);
}

// round 13
// speedup vs baseline: 1.8113x; 1.0229x over previous
#include <cuda_runtime.h>
#include <cuda_bf16.h>
#include <cuda_fp16.h>
#include <math.h>
#include <stdint.h>

// Problem constants (fixed by the dataset)
#define NN 50000
#define EE 800000
#define HH 128
#define FIN 128
#define NSE 16
#define LL 3
#define CC 10
#define GG 256

// ---------------- scratch (static __device__ — no allocs allowed) ----------
__device__ float d_x [NN * HH];     // fp16 x stream (half the buffer used)
__device__ float d_s [NN * HH];     // fp16 s stream
__device__ float d_y [NN * HH];     // fp16 y / fp32 whp out (reused)
__device__ float d_z [NN * HH];     // fp16 z
__device__ float d_hs[NN * HH];     // fp16 hs'
__device__ float d_g [GG * HH];
__device__ float d_gp[GG * HH];
__device__ float d_dinv[NN];
__device__ int   d_degc[NN];
__device__ int   d_rowptr[NN + 1];
__device__ int   d_cursor[NN];
__device__ int   d_col[EE];
// fp16 converted inputs + weights (transposed [n][k])
__device__ __half d_xh [NN * FIN];
__device__ __half d_shn[NN * NSE];
__device__ __half d_wpre[128 * 128];
__device__ __half d_wemb[128 * 16];
__device__ __half d_wg1 [3 * 128 * 256];
__device__ __half d_wgc [3 * 128 * 128];
__device__ __half d_wg2 [3 * 128 * 128];
__device__ __half d_wwhp[128 * 256];

// ---------------- CSR build ------------------------------------------------
__global__ void count_deg_kernel(const int* __restrict__ ei, int* __restrict__ degc) {
    int e = blockIdx.x * blockDim.x + threadIdx.x;
    if (e < EE) atomicAdd(&degc[ei[EE + e]], 1);
}

__global__ void scan_deg_kernel(const int* __restrict__ degc,
                                int* __restrict__ rowptr,
                                float* __restrict__ dinv) {
    __shared__ int ssum[1024];
    int t = threadIdx.x;
    const int chunk = (NN + 1023) / 1024;
    int b0 = t * chunk;
    int b1 = b0 + chunk; if (b1 > NN) b1 = NN;
    int sum = 0;
    for (int i = b0; i < b1; i++) sum += degc[i];
    ssum[t] = sum;
    __syncthreads();
    for (int off = 1; off < 1024; off <<= 1) {
        int v = 0;
        if (t >= off) v = ssum[t - off];
        __syncthreads();
        if (t >= off) ssum[t] += v;
        __syncthreads();
    }
    int prefix = (t == 0) ? 0 : ssum[t - 1];
    for (int i = b0; i < b1; i++) {
        int d = degc[i];
        rowptr[i] = prefix;
        prefix += d;
        dinv[i] = rsqrtf((float)d + 1.0f);
    }
    if (t == 1023) rowptr[NN] = ssum[1023];
}

__global__ void fill_csr_kernel(const int* __restrict__ ei,
                                const int* __restrict__ rowptr,
                                int* __restrict__ cursor,
                                int* __restrict__ col) {
    int e = blockIdx.x * blockDim.x + threadIdx.x;
    if (e < EE) {
        int src = ei[e];
        int dst = ei[EE + e];
        int pos = atomicAdd(&cursor[dst], 1);
        col[rowptr[dst] + pos] = src;
    }
}

// ---------------- prep: fp32->fp16 + weight transpose ----------------------
__global__ void f2h_kernel(const float* __restrict__ src, __half* __restrict__ dst, int n4) {
    int i = blockIdx.x * blockDim.x + threadIdx.x;
    if (i < n4) {
        float4 v = ((const float4*)src)[i];
        __half2 h0 = __floats2half2_rn(v.x, v.y);
        __half2 h1 = __floats2half2_rn(v.z, v.w);
        uint2 p; p.x = *(uint32_t*)&h0; p.y = *(uint32_t*)&h1;
        ((uint2*)dst)[i] = p;
    }
}
// src: [nmat][K][128] fp32 -> dst: [nmat][128][K] fp16
__global__ void wtrans_kernel(const float* __restrict__ src, __half* __restrict__ dst,
                              int K, int total) {
    int i = blockIdx.x * blockDim.x + threadIdx.x;
    if (i < total) {
        int n = i & 127;
        int k = (i >> 7) % K;
        int m = i / (K * 128);
        dst[(size_t)m * 128 * K + (size_t)n * K + k] = __float2half(src[i]);
    }
}

// ---------------- cp.async helpers ----------------------------------------
__device__ __forceinline__ uint32_t smem_u32(const void* p) {
    uint32_t a;
    asm("{ .reg .u64 t; cvta.to.shared.u64 t, %1; cvt.u32.u64 %0, t; }"
        : "=r"(a) : "l"(p));
    return a;
}
__device__ __forceinline__ void cp16(uint32_t dst, const void* src, int sz) {
    asm volatile("cp.async.cg.shared.global [%0], [%1], 16, %2;"
                 :: "r"(dst), "l"(src), "r"(sz));
}
#define CP_COMMIT() asm volatile("cp.async.commit_group;")
#define CP_WAIT(n)  asm volatile("cp.async.wait_group %0;" :: "n"(n))

__device__ __forceinline__ void mma_f16(float* c, const uint32_t* a, const uint32_t* b) {
    asm volatile("mma.sync.aligned.m16n8k16.row.col.f32.f16.f16.f32 "
        "{%0,%1,%2,%3}, {%4,%5,%6,%7}, {%8,%9}, {%0,%1,%2,%3};"
        : "+f"(c[0]), "+f"(c[1]), "+f"(c[2]), "+f"(c[3])
        : "r"(a[0]), "r"(a[1]), "r"(a[2]), "r"(a[3]), "r"(b[0]), "r"(b[1]));
}

// ---------------- fp16 GEMM (cp.async staged, 3-stage, dual-A, 2 CTA/SM) ---
#define TM 128
#define TN 128
#define TKK 16
#define RPAD 24
#define NS 3
__global__ __launch_bounds__(256, 2)
void h_gemm_dual(const __half* __restrict__ A1, int K1,
                 const __half* __restrict__ A2, int K2,
                 const __half* __restrict__ Wt,
                 const float* __restrict__ bias,
                 const float* __restrict__ rowscale,
                 void* __restrict__ Cout, int M, int relu, int outHalf) {
    __shared__ __half As[NS][TM][RPAD];
    __shared__ __half Bs[NS][TN][RPAD];
    const int tid  = threadIdx.x;
    const int wid  = tid >> 5;
    const int lane = tid & 31;
    const int g    = lane >> 2;
    const int t    = lane & 3;
    const int wm   = wid & 3;
    const int wn   = wid >> 2;
    const int row0 = blockIdx.x * TM;
    const int Ktot = K1 + K2;
    const int nb   = Ktot / TKK;

    float acc[2][8][4];
#pragma unroll
    for (int mi = 0; mi < 2; mi++)
#pragma unroll
        for (int ni = 0; ni < 8; ni++)
#pragma unroll
            for (int q = 0; q < 4; q++) acc[mi][ni][q] = 0.0f;

    const int r  = tid >> 1;           // staging row (A row / B n-row)
    const int ch = (tid & 1) * 8;      // chunk offset (halves)
    const int grow = row0 + r;

    auto issue = [&](int kb) {
        int st = kb % NS;
        int kg = kb * TKK + ch;
        const __half* sa;
        if (kg < K1) sa = A1 + (size_t)grow * K1 + kg;
        else         sa = A2 + (size_t)grow * K2 + (kg - K1);
        cp16(smem_u32(&As[st][r][ch]), sa, (grow < M) ? 16 : 0);
        cp16(smem_u32(&Bs[st][r][ch]), Wt + (size_t)r * Ktot + kg, 16);
    };

#pragma unroll
    for (int s = 0; s < NS - 1; s++) {
        if (s < nb) issue(s);
        CP_COMMIT();
    }

    for (int kb = 0; kb < nb; kb++) {
        CP_WAIT(NS - 2);
        __syncthreads();
        if (kb + NS - 1 < nb) issue(kb + NS - 1);
        CP_COMMIT();

        const int cur = kb % NS;
        uint32_t af[2][4];
#pragma unroll
        for (int mi = 0; mi < 2; mi++) {
            int mb = wm * 32 + mi * 16;
            af[mi][0] = *(const uint32_t*)&As[cur][mb + g    ][2 * t    ];
            af[mi][1] = *(const uint32_t*)&As[cur][mb + g + 8][2 * t    ];
            af[mi][2] = *(const uint32_t*)&As[cur][mb + g    ][2 * t + 8];
            af[mi][3] = *(const uint32_t*)&As[cur][mb + g + 8][2 * t + 8];
        }
        uint32_t bf[8][2];
#pragma unroll
        for (int ni = 0; ni < 8; ni++) {
            int nbase = wn * 64 + ni * 8 + g;
            bf[ni][0] = *(const uint32_t*)&Bs[cur][nbase][2 * t    ];
            bf[ni][1] = *(const uint32_t*)&Bs[cur][nbase][2 * t + 8];
        }
#pragma unroll
        for (int mi = 0; mi < 2; mi++)
#pragma unroll
            for (int ni = 0; ni < 8; ni++)
                mma_f16(acc[mi][ni], af[mi], bf[ni]);
    }

    // Epilogue: c0->(g,2t) c1->(g,2t+1) c2->(g+8,2t) c3->(g+8,2t+1)
    float* Cf = (float*)Cout;
    __half* Ch = (__half*)Cout;
#pragma unroll
    for (int mi = 0; mi < 2; mi++) {
        int rbase = row0 + wm * 32 + mi * 16 + g;
        float rs0 = 1.f, rs1 = 1.f;
        if (rowscale) {
            if (rbase < M)     rs0 = rowscale[rbase];
            if (rbase + 8 < M) rs1 = rowscale[rbase + 8];
        }
#pragma unroll
        for (int ni = 0; ni < 8; ni++) {
            int colb = wn * 64 + ni * 8 + 2 * t;
            float b0 = bias ? bias[colb]     : 0.f;
            float b1 = bias ? bias[colb + 1] : 0.f;
            float v0 = acc[mi][ni][0] * rs0 + b0;
            float v1 = acc[mi][ni][1] * rs0 + b1;
            float v2 = acc[mi][ni][2] * rs1 + b0;
            float v3 = acc[mi][ni][3] * rs1 + b1;
            if (relu) {
                v0 = fmaxf(v0, 0.f); v1 = fmaxf(v1, 0.f);
                v2 = fmaxf(v2, 0.f); v3 = fmaxf(v3, 0.f);
            }
            if (outHalf) {
                if (rbase < M)
                    *(__half2*)(Ch + (size_t)rbase * TN + colb) = __floats2half2_rn(v0, v1);
                if (rbase + 8 < M)
                    *(__half2*)(Ch + (size_t)(rbase + 8) * TN + colb) = __floats2half2_rn(v2, v3);
            } else {
                if (rbase < M)
                    *(float2*)(Cf + (size_t)rbase * TN + colb) = make_float2(v0, v1);
                if (rbase + 8 < M)
                    *(float2*)(Cf + (size_t)(rbase + 8) * TN + colb) = make_float2(v2, v3);
            }
        }
    }
}

// ---------------- GIN agg: half2 partial sums per unroll-8 block -----------
__global__ __launch_bounds__(256)
void gin_agg_relu_kernel(const __half* __restrict__ y,
                         const int* __restrict__ col,
                         const int* __restrict__ rowptr,
                         const float* __restrict__ b1,
                         __half* __restrict__ z) {
    int warp = (blockIdx.x * blockDim.x + threadIdx.x) >> 5;
    if (warp >= NN) return;
    int lane = threadIdx.x & 31;
    const uint2* yv = (const uint2*)y;
    float ax, ay, az, aw;
    {
        uint2 v = yv[(size_t)warp * 32 + lane];
        float2 p0 = __half22float2(*(const __half2*)&v.x);
        float2 p1 = __half22float2(*(const __half2*)&v.y);
        ax = p0.x; ay = p0.y; az = p1.x; aw = p1.y;
    }
    int b = rowptr[warp], e = rowptr[warp + 1];
    int j = b;
    for (; j + 8 <= e; j += 8) {
        int c0 = col[j],     c1 = col[j + 1], c2 = col[j + 2], c3 = col[j + 3];
        int c4 = col[j + 4], c5 = col[j + 5], c6 = col[j + 6], c7 = col[j + 7];
        uint2 v0 = yv[(size_t)c0 * 32 + lane];
        uint2 v1 = yv[(size_t)c1 * 32 + lane];
        uint2 v2 = yv[(size_t)c2 * 32 + lane];
        uint2 v3 = yv[(size_t)c3 * 32 + lane];
        uint2 v4 = yv[(size_t)c4 * 32 + lane];
        uint2 v5 = yv[(size_t)c5 * 32 + lane];
        uint2 v6 = yv[(size_t)c6 * 32 + lane];
        uint2 v7 = yv[(size_t)c7 * 32 + lane];
        __half2 p0 = __hadd2(__hadd2(*(__half2*)&v0.x, *(__half2*)&v1.x),
                             __hadd2(*(__half2*)&v2.x, *(__half2*)&v3.x));
        __half2 p1 = __hadd2(__hadd2(*(__half2*)&v4.x, *(__half2*)&v5.x),
                             __hadd2(*(__half2*)&v6.x, *(__half2*)&v7.x));
        __half2 q0 = __hadd2(__hadd2(*(__half2*)&v0.y, *(__half2*)&v1.y),
                             __hadd2(*(__half2*)&v2.y, *(__half2*)&v3.y));
        __half2 q1 = __hadd2(__hadd2(*(__half2*)&v4.y, *(__half2*)&v5.y),
                             __hadd2(*(__half2*)&v6.y, *(__half2*)&v7.y));
        float2 f0 = __half22float2(p0);
        float2 f1 = __half22float2(p1);
        float2 g0 = __half22float2(q0);
        float2 g1 = __half22float2(q1);
        ax += f0.x + f1.x; ay += f0.y + f1.y;
        az += g0.x + g1.x; aw += g0.y + g1.y;
    }
    for (; j < e; j++) {
        uint2 v = yv[(size_t)col[j] * 32 + lane];
        float2 p0 = __half22float2(*(const __half2*)&v.x);
        float2 p1 = __half22float2(*(const __half2*)&v.y);
        ax += p0.x; ay += p0.y; az += p1.x; aw += p1.y;
    }
    float4 bb = ((const float4*)b1)[lane];
    __half2 o0 = __floats2half2_rn(fmaxf(ax + bb.x, 0.f), fmaxf(ay + bb.y, 0.f));
    __half2 o1 = __floats2half2_rn(fmaxf(az + bb.z, 0.f), fmaxf(aw + bb.w, 0.f));
    uint2 p; p.x = *(uint32_t*)&o0; p.y = *(uint32_t*)&o1;
    ((uint2*)z)[(size_t)warp * 32 + lane] = p;
}

// ---------------- GCN agg: half2 partials on prescaled hs' -----------------
__global__ __launch_bounds__(256)
void gcn_agg_kernel(const __half* __restrict__ hsp,
                    const float* __restrict__ dinv,
                    const int* __restrict__ col,
                    const int* __restrict__ rowptr,
                    const float* __restrict__ bias,
                    __half* __restrict__ s) {
    int warp = (blockIdx.x * blockDim.x + threadIdx.x) >> 5;
    if (warp >= NN) return;
    int lane = threadIdx.x & 31;
    const uint2* hv = (const uint2*)hsp;
    float ax, ay, az, aw;
    {
        uint2 v = hv[(size_t)warp * 32 + lane];
        float2 p0 = __half22float2(*(const __half2*)&v.x);
        float2 p1 = __half22float2(*(const __half2*)&v.y);
        ax = p0.x; ay = p0.y; az = p1.x; aw = p1.y;
    }
    int b = rowptr[warp], e = rowptr[warp + 1];
    int j = b;
    for (; j + 8 <= e; j += 8) {
        int c0 = col[j],     c1 = col[j + 1], c2 = col[j + 2], c3 = col[j + 3];
        int c4 = col[j + 4], c5 = col[j + 5], c6 = col[j + 6], c7 = col[j + 7];
        uint2 v0 = hv[(size_t)c0 * 32 + lane];
        uint2 v1 = hv[(size_t)c1 * 32 + lane];
        uint2 v2 = hv[(size_t)c2 * 32 + lane];
        uint2 v3 = hv[(size_t)c3 * 32 + lane];
        uint2 v4 = hv[(size_t)c4 * 32 + lane];
        uint2 v5 = hv[(size_t)c5 * 32 + lane];
        uint2 v6 = hv[(size_t)c6 * 32 + lane];
        uint2 v7 = hv[(size_t)c7 * 32 + lane];
        __half2 p0 = __hadd2(__hadd2(*(__half2*)&v0.x, *(__half2*)&v1.x),
                             __hadd2(*(__half2*)&v2.x, *(__half2*)&v3.x));
        __half2 p1 = __hadd2(__hadd2(*(__half2*)&v4.x, *(__half2*)&v5.x),
                             __hadd2(*(__half2*)&v6.x, *(__half2*)&v7.x));
        __half2 q0 = __hadd2(__hadd2(*(__half2*)&v0.y, *(__half2*)&v1.y),
                             __hadd2(*(__half2*)&v2.y, *(__half2*)&v3.y));
        __half2 q1 = __hadd2(__hadd2(*(__half2*)&v4.y, *(__half2*)&v5.y),
                             __hadd2(*(__half2*)&v6.y, *(__half2*)&v7.y));
        float2 f0 = __half22float2(p0);
        float2 f1 = __half22float2(p1);
        float2 g0 = __half22float2(q0);
        float2 g1 = __half22float2(q1);
        ax += f0.x + f1.x; ay += f0.y + f1.y;
        az += g0.x + g1.x; aw += g0.y + g1.y;
    }
    for (; j < e; j++) {
        uint2 v = hv[(size_t)col[j] * 32 + lane];
        float2 p0 = __half22float2(*(const __half2*)&v.x);
        float2 p1 = __half22float2(*(const __half2*)&v.y);
        ax += p0.x; ay += p0.y; az += p1.x; aw += p1.y;
    }
    float di = dinv[warp];
    float4 bb = ((const float4*)bias)[lane];
    __half2 o0 = __floats2half2_rn(tanhf(di * ax + bb.x), tanhf(di * ay + bb.y));
    __half2 o1 = __floats2half2_rn(tanhf(di * az + bb.z), tanhf(di * aw + bb.w));
    uint2 p; p.x = *(uint32_t*)&o0; p.y = *(uint32_t*)&o1;
    ((uint2*)s)[(size_t)warp * 32 + lane] = p;
}

// ---------------- global add pool -----------------------------------------
__global__ void pool_kernel(const float* __restrict__ xf,
                            const int* __restrict__ batch,
                            float* __restrict__ g) {
    int idx = blockIdx.x * blockDim.x + threadIdx.x;
    if (idx < NN * HH) {
        int i = idx >> 7;
        int f = idx & 127;
        atomicAdd(&g[batch[i] * HH + f], xf[idx]);
    }
}

// ---------------- post: relu(g @ post_w + b) ------------------------------
__global__ void post_kernel(const float* __restrict__ g,
                            const float* __restrict__ W,
                            const float* __restrict__ bias,
                            float* __restrict__ gp) {
    int r = blockIdx.x;
    int c = threadIdx.x;
    __shared__ float row[HH];
    row[c] = g[(size_t)r * HH + c];
    __syncthreads();
    float acc = bias[c];
#pragma unroll 8
    for (int k = 0; k < HH; k++) acc = fmaf(row[k], W[(size_t)k * HH + c], acc);
    gp[(size_t)r * HH + c] = fmaxf(acc, 0.0f);
}

// ---------------- readout + log_softmax ----------------------------------
__global__ void readout_kernel(const float* __restrict__ gp,
                               const float* __restrict__ W,
                               const float* __restrict__ bias,
                               float* __restrict__ out) {
    int r = blockIdx.x * blockDim.x + threadIdx.x;
    if (r < GG) {
        float logit[CC];
#pragma unroll
        for (int c = 0; c < CC; c++) logit[c] = bias[c];
        for (int k = 0; k < HH; k++) {
            float gv = gp[(size_t)r * HH + k];
#pragma unroll
            for (int c = 0; c < CC; c++)
                logit[c] = fmaf(gv, W[(size_t)k * CC + c], logit[c]);
        }
        float m = logit[0];
#pragma unroll
        for (int c = 1; c < CC; c++) m = fmaxf(m, logit[c]);
        float sum = 0.0f;
#pragma unroll
        for (int c = 0; c < CC; c++) sum += expf(logit[c] - m);
        float lse = m + logf(sum);
#pragma unroll
        for (int c = 0; c < CC; c++) out[(size_t)r * CC + c] = logit[c] - lse;
    }
}

// ---------------- driver ---------------------------------------------------
extern "C" void kernel_launch(void* const* d_in, const int* in_sizes, int n_in,
                              void* d_out, int out_size) {
    const float* x_in   = (const float*)d_in[0];
    const float* s_in   = (const float*)d_in[1];
    const int*   ei     = (const int*)d_in[2];
    const int*   batch  = (const int*)d_in[3];
    const float* pre_w  = (const float*)d_in[4];
    const float* pre_b  = (const float*)d_in[5];
    const float* emb_w  = (const float*)d_in[6];
    const float* emb_b  = (const float*)d_in[7];
    const float* gin_w1 = (const float*)d_in[8];
    const float* gin_b1 = (const float*)d_in[9];
    const float* gin_w2 = (const float*)d_in[10];
    const float* gin_b2 = (const float*)d_in[11];
    const float* gcn_w  = (const float*)d_in[12];
    const float* gcn_b  = (const float*)d_in[13];
    const float* whp_w  = (const float*)d_in[14];
    const float* whp_b  = (const float*)d_in[15];
    const float* post_w = (const float*)d_in[16];
    const float* post_b = (const float*)d_in[17];
    const float* ro_w   = (const float*)d_in[18];
    const float* ro_b   = (const float*)d_in[19];
    float* out = (float*)d_out;

    float *px, *ps, *py, *pz, *phs, *pg, *pgp, *pdinv;
    int *pdegc, *prow, *pcur, *pcol;
    __half *pxh, *pshn, *pwpre, *pwemb, *pwg1, *pwgc, *pwg2, *pwwhp;
    cudaGetSymbolAddress((void**)&px,    d_x);
    cudaGetSymbolAddress((void**)&ps,    d_s);
    cudaGetSymbolAddress((void**)&py,    d_y);
    cudaGetSymbolAddress((void**)&pz,    d_z);
    cudaGetSymbolAddress((void**)&phs,   d_hs);
    cudaGetSymbolAddress((void**)&pg,    d_g);
    cudaGetSymbolAddress((void**)&pgp,   d_gp);
    cudaGetSymbolAddress((void**)&pdinv, d_dinv);
    cudaGetSymbolAddress((void**)&pdegc, d_degc);
    cudaGetSymbolAddress((void**)&prow,  d_rowptr);
    cudaGetSymbolAddress((void**)&pcur,  d_cursor);
    cudaGetSymbolAddress((void**)&pcol,  d_col);
    cudaGetSymbolAddress((void**)&pxh,   d_xh);
    cudaGetSymbolAddress((void**)&pshn,  d_shn);
    cudaGetSymbolAddress((void**)&pwpre, d_wpre);
    cudaGetSymbolAddress((void**)&pwemb, d_wemb);
    cudaGetSymbolAddress((void**)&pwg1,  d_wg1);
    cudaGetSymbolAddress((void**)&pwgc,  d_wgc);
    cudaGetSymbolAddress((void**)&pwg2,  d_wg2);
    cudaGetSymbolAddress((void**)&pwwhp, d_wwhp);
    __half* pxH  = (__half*)px;
    __half* psH  = (__half*)ps;
    __half* pyH  = (__half*)py;
    __half* pzH  = (__half*)pz;
    __half* phsH = (__half*)phs;

    const int TPB = 256;
    const int eBlocks = (EE + TPB - 1) / TPB;
    const int gemmBlocks = (NN + TM - 1) / TM;
    const int aggBlocks = (NN * 32 + TPB - 1) / TPB;

    // ---- prep: conversions + weight transposes ----
    f2h_kernel<<<(NN * FIN / 4 + TPB - 1) / TPB, TPB>>>(x_in, pxh, NN * FIN / 4);
    f2h_kernel<<<(NN * NSE / 4 + TPB - 1) / TPB, TPB>>>(s_in, pshn, NN * NSE / 4);
    wtrans_kernel<<<(128 * 128 + TPB - 1) / TPB, TPB>>>(pre_w, pwpre, 128, 128 * 128);
    wtrans_kernel<<<(16 * 128 + TPB - 1) / TPB, TPB>>>(emb_w, pwemb, 16, 16 * 128);
    wtrans_kernel<<<(3 * 256 * 128 + TPB - 1) / TPB, TPB>>>(gin_w1, pwg1, 256, 3 * 256 * 128);
    wtrans_kernel<<<(3 * 128 * 128 + TPB - 1) / TPB, TPB>>>(gcn_w, pwgc, 128, 3 * 128 * 128);
    wtrans_kernel<<<(3 * 128 * 128 + TPB - 1) / TPB, TPB>>>(gin_w2, pwg2, 128, 3 * 128 * 128);
    wtrans_kernel<<<(256 * 128 + TPB - 1) / TPB, TPB>>>(whp_w, pwwhp, 256, 256 * 128);

    // ---- CSR build ----
    cudaMemsetAsync(pdegc, 0, NN * sizeof(int), 0);
    cudaMemsetAsync(pcur,  0, NN * sizeof(int), 0);
    count_deg_kernel<<<eBlocks, TPB>>>(ei, pdegc);
    scan_deg_kernel<<<1, 1024>>>(pdegc, prow, pdinv);
    fill_csr_kernel<<<eBlocks, TPB>>>(ei, prow, pcur, pcol);

    // ---- pre / embedding (fp16 out) ----
    h_gemm_dual<<<gemmBlocks, 256>>>(pxh, FIN, nullptr, 0, pwpre, pre_b,
                                     nullptr, pxH, NN, 0, 1);
    h_gemm_dual<<<gemmBlocks, 256>>>(pshn, NSE, nullptr, 0, pwemb, emb_b,
                                     nullptr, psH, NN, 0, 1);

    for (int i = 0; i < LL; i++) {
        // y = [x|s] @ gin_w1 -> fp16
        h_gemm_dual<<<gemmBlocks, 256>>>(pxH, HH, psH, HH,
                                         pwg1 + (size_t)i * 128 * 256,
                                         nullptr, nullptr, pyH, NN, 0, 1);
        // hs' = dinv * (s @ gcn_w[i]) -> fp16
        h_gemm_dual<<<gemmBlocks, 256>>>(psH, HH, nullptr, 0,
                                         pwgc + (size_t)i * 128 * 128,
                                         nullptr, pdinv, phsH, NN, 0, 1);
        // z = relu(y + A·y + b1) -> fp16
        gin_agg_relu_kernel<<<aggBlocks, TPB>>>(pyH, pcol, prow,
                                                gin_b1 + (size_t)i * HH, pzH);
        // s = tanh(dinv_i*(sum hs' + hs'_i) + b) -> fp16
        gcn_agg_kernel<<<aggBlocks, TPB>>>(phsH, pdinv, pcol, prow,
                                           gcn_b + (size_t)i * HH, psH);
        // x = relu(z @ gin_w2 + b2) -> fp16
        h_gemm_dual<<<gemmBlocks, 256>>>(pzH, HH, nullptr, 0,
                                         pwg2 + (size_t)i * 128 * 128,
                                         gin_b2 + (size_t)i * HH,
                                         nullptr, pxH, NN, 1, 1);
    }

    // whp on split concat (fp32 out for pooling)
    h_gemm_dual<<<gemmBlocks, 256>>>(pxH, HH, psH, HH, pwwhp, whp_b,
                                     nullptr, py, NN, 0, 0);

    // pool -> post -> readout
    cudaMemsetAsync(pg, 0, GG * HH * sizeof(float), 0);
    pool_kernel<<<(NN * HH + TPB - 1) / TPB, TPB>>>(py, batch, pg);
    post_kernel<<<GG, HH>>>(pg, post_w, post_b, pgp);
    readout_kernel<<<1, GG>>>(pgp, ro_w, ro_b, out);
}

// round 14
// speedup vs baseline: 1.9313x; 1.0663x over previous
#include <cuda_runtime.h>
#include <cuda_bf16.h>
#include <cuda_fp16.h>
#include <math.h>
#include <stdint.h>

// Problem constants (fixed by the dataset)
#define NN 50000
#define EE 800000
#define HH 128
#define FIN 128
#define NSE 16
#define LL 3
#define CC 10
#define GG 256

// ---------------- scratch (static __device__ — no allocs allowed) ----------
__device__ float d_x [NN * HH];
__device__ float d_s [NN * HH];
__device__ float d_y [NN * HH];     // fp16 y / fp32 whp out (reused)
__device__ float d_z [NN * HH];
__device__ float d_hs[NN * HH];
__device__ float d_g [GG * HH];
__device__ float d_gp[GG * HH];
__device__ float d_dinv[NN];
__device__ int   d_degc[NN];
__device__ int   d_rowptr[NN + 1];
__device__ int   d_cursor[NN];
__device__ int   d_col[EE];
// fp16 converted inputs + weights (transposed [n][k])
__device__ __half d_xh [NN * FIN];
__device__ __half d_shn[NN * NSE];
__device__ __half d_wpre[128 * 128];
__device__ __half d_wemb[128 * 16];
__device__ __half d_wg1 [3 * 128 * 256];
__device__ __half d_wgc [3 * 128 * 128];
__device__ __half d_wg2 [3 * 128 * 128];
__device__ __half d_wwhp[128 * 256];

// ---------------- CSR build ------------------------------------------------
__global__ void count_deg_kernel(const int* __restrict__ ei, int* __restrict__ degc) {
    int e = blockIdx.x * blockDim.x + threadIdx.x;
    if (e < EE) atomicAdd(&degc[ei[EE + e]], 1);
}

__global__ void scan_deg_kernel(const int* __restrict__ degc,
                                int* __restrict__ rowptr,
                                float* __restrict__ dinv) {
    __shared__ int ssum[1024];
    int t = threadIdx.x;
    const int chunk = (NN + 1023) / 1024;
    int b0 = t * chunk;
    int b1 = b0 + chunk; if (b1 > NN) b1 = NN;
    int sum = 0;
    for (int i = b0; i < b1; i++) sum += degc[i];
    ssum[t] = sum;
    __syncthreads();
    for (int off = 1; off < 1024; off <<= 1) {
        int v = 0;
        if (t >= off) v = ssum[t - off];
        __syncthreads();
        if (t >= off) ssum[t] += v;
        __syncthreads();
    }
    int prefix = (t == 0) ? 0 : ssum[t - 1];
    for (int i = b0; i < b1; i++) {
        int d = degc[i];
        rowptr[i] = prefix;
        prefix += d;
        dinv[i] = rsqrtf((float)d + 1.0f);
    }
    if (t == 1023) rowptr[NN] = ssum[1023];
}

__global__ void fill_csr_kernel(const int* __restrict__ ei,
                                const int* __restrict__ rowptr,
                                int* __restrict__ cursor,
                                int* __restrict__ col) {
    int e = blockIdx.x * blockDim.x + threadIdx.x;
    if (e < EE) {
        int src = ei[e];
        int dst = ei[EE + e];
        int pos = atomicAdd(&cursor[dst], 1);
        col[rowptr[dst] + pos] = src;
    }
}

// ---------------- prep: fp32->fp16 + weight transpose ----------------------
__global__ void f2h_kernel(const float* __restrict__ src, __half* __restrict__ dst, int n4) {
    int i = blockIdx.x * blockDim.x + threadIdx.x;
    if (i < n4) {
        float4 v = ((const float4*)src)[i];
        __half2 h0 = __floats2half2_rn(v.x, v.y);
        __half2 h1 = __floats2half2_rn(v.z, v.w);
        uint2 p; p.x = *(uint32_t*)&h0; p.y = *(uint32_t*)&h1;
        ((uint2*)dst)[i] = p;
    }
}
// src: [nmat][K][128] fp32 -> dst: [nmat][128][K] fp16
__global__ void wtrans_kernel(const float* __restrict__ src, __half* __restrict__ dst,
                              int K, int total) {
    int i = blockIdx.x * blockDim.x + threadIdx.x;
    if (i < total) {
        int n = i & 127;
        int k = (i >> 7) % K;
        int m = i / (K * 128);
        dst[(size_t)m * 128 * K + (size_t)n * K + k] = __float2half(src[i]);
    }
}

// ---------------- cp.async helpers ----------------------------------------
__device__ __forceinline__ uint32_t smem_u32(const void* p) {
    uint32_t a;
    asm("{ .reg .u64 t; cvta.to.shared.u64 t, %1; cvt.u32.u64 %0, t; }"
        : "=r"(a) : "l"(p));
    return a;
}
__device__ __forceinline__ void cp16(uint32_t dst, const void* src, int sz) {
    asm volatile("cp.async.cg.shared.global [%0], [%1], 16, %2;"
                 :: "r"(dst), "l"(src), "r"(sz));
}
#define CP_COMMIT() asm volatile("cp.async.commit_group;")
#define CP_WAIT(n)  asm volatile("cp.async.wait_group %0;" :: "n"(n))

__device__ __forceinline__ void mma_f16(float* c, const uint32_t* a, const uint32_t* b) {
    asm volatile("mma.sync.aligned.m16n8k16.row.col.f32.f16.f16.f32 "
        "{%0,%1,%2,%3}, {%4,%5,%6,%7}, {%8,%9}, {%0,%1,%2,%3};"
        : "+f"(c[0]), "+f"(c[1]), "+f"(c[2]), "+f"(c[3])
        : "r"(a[0]), "r"(a[1]), "r"(a[2]), "r"(a[3]), "r"(b[0]), "r"(b[1]));
}

// ---------------- GEMM params + core ---------------------------------------
#define TM 128
#define TN 128
#define TKK 16
#define RPAD 24
#define NS 3

struct GemmP {
    const __half* A1; int K1;
    const __half* A2; int K2;
    const __half* Wt;
    const float* bias;
    const float* rowscale;
    void* C; int M; int relu; int outHalf;
};

__device__ __forceinline__ void gemm_core(
    const GemmP& P, int blk,
    __half (*As)[TM][RPAD], __half (*Bs)[TN][RPAD]) {
    const int tid  = threadIdx.x;
    const int wid  = tid >> 5;
    const int lane = tid & 31;
    const int g    = lane >> 2;
    const int t    = lane & 3;
    const int wm   = wid & 3;
    const int wn   = wid >> 2;
    const int row0 = blk * TM;
    const int Ktot = P.K1 + P.K2;
    const int nb   = Ktot / TKK;

    float acc[2][8][4];
#pragma unroll
    for (int mi = 0; mi < 2; mi++)
#pragma unroll
        for (int ni = 0; ni < 8; ni++)
#pragma unroll
            for (int q = 0; q < 4; q++) acc[mi][ni][q] = 0.0f;

    const int r  = tid >> 1;
    const int ch = (tid & 1) * 8;
    const int grow = row0 + r;

    auto issue = [&](int kb) {
        int st = kb % NS;
        int kg = kb * TKK + ch;
        const __half* sa;
        if (kg < P.K1) sa = P.A1 + (size_t)grow * P.K1 + kg;
        else           sa = P.A2 + (size_t)grow * P.K2 + (kg - P.K1);
        cp16(smem_u32(&As[st][r][ch]), sa, (grow < P.M) ? 16 : 0);
        cp16(smem_u32(&Bs[st][r][ch]), P.Wt + (size_t)r * Ktot + kg, 16);
    };

#pragma unroll
    for (int s = 0; s < NS - 1; s++) {
        if (s < nb) issue(s);
        CP_COMMIT();
    }

    for (int kb = 0; kb < nb; kb++) {
        CP_WAIT(NS - 2);
        __syncthreads();
        if (kb + NS - 1 < nb) issue(kb + NS - 1);
        CP_COMMIT();

        const int cur = kb % NS;
        uint32_t af[2][4];
#pragma unroll
        for (int mi = 0; mi < 2; mi++) {
            int mb = wm * 32 + mi * 16;
            af[mi][0] = *(const uint32_t*)&As[cur][mb + g    ][2 * t    ];
            af[mi][1] = *(const uint32_t*)&As[cur][mb + g + 8][2 * t    ];
            af[mi][2] = *(const uint32_t*)&As[cur][mb + g    ][2 * t + 8];
            af[mi][3] = *(const uint32_t*)&As[cur][mb + g + 8][2 * t + 8];
        }
        uint32_t bf[8][2];
#pragma unroll
        for (int ni = 0; ni < 8; ni++) {
            int nbase = wn * 64 + ni * 8 + g;
            bf[ni][0] = *(const uint32_t*)&Bs[cur][nbase][2 * t    ];
            bf[ni][1] = *(const uint32_t*)&Bs[cur][nbase][2 * t + 8];
        }
#pragma unroll
        for (int mi = 0; mi < 2; mi++)
#pragma unroll
            for (int ni = 0; ni < 8; ni++)
                mma_f16(acc[mi][ni], af[mi], bf[ni]);
    }

    float* Cf = (float*)P.C;
    __half* Chh = (__half*)P.C;
#pragma unroll
    for (int mi = 0; mi < 2; mi++) {
        int rbase = row0 + wm * 32 + mi * 16 + g;
        float rs0 = 1.f, rs1 = 1.f;
        if (P.rowscale) {
            if (rbase < P.M)     rs0 = P.rowscale[rbase];
            if (rbase + 8 < P.M) rs1 = P.rowscale[rbase + 8];
        }
#pragma unroll
        for (int ni = 0; ni < 8; ni++) {
            int colb = wn * 64 + ni * 8 + 2 * t;
            float b0 = P.bias ? P.bias[colb]     : 0.f;
            float b1 = P.bias ? P.bias[colb + 1] : 0.f;
            float v0 = acc[mi][ni][0] * rs0 + b0;
            float v1 = acc[mi][ni][1] * rs0 + b1;
            float v2 = acc[mi][ni][2] * rs1 + b0;
            float v3 = acc[mi][ni][3] * rs1 + b1;
            if (P.relu) {
                v0 = fmaxf(v0, 0.f); v1 = fmaxf(v1, 0.f);
                v2 = fmaxf(v2, 0.f); v3 = fmaxf(v3, 0.f);
            }
            if (P.outHalf) {
                if (rbase < P.M)
                    *(__half2*)(Chh + (size_t)rbase * TN + colb) = __floats2half2_rn(v0, v1);
                if (rbase + 8 < P.M)
                    *(__half2*)(Chh + (size_t)(rbase + 8) * TN + colb) = __floats2half2_rn(v2, v3);
            } else {
                if (rbase < P.M)
                    *(float2*)(Cf + (size_t)rbase * TN + colb) = make_float2(v0, v1);
                if (rbase + 8 < P.M)
                    *(float2*)(Cf + (size_t)(rbase + 8) * TN + colb) = make_float2(v2, v3);
            }
        }
    }
}

// single GEMM
__global__ __launch_bounds__(256, 2)
void h_gemm1(GemmP P0) {
    __shared__ __half As[NS][TM][RPAD];
    __shared__ __half Bs[NS][TN][RPAD];
    gemm_core(P0, blockIdx.x, As, Bs);
}
// two independent GEMMs fused at block level
__global__ __launch_bounds__(256, 2)
void h_gemm2(GemmP P0, GemmP P1, int nb0) {
    __shared__ __half As[NS][TM][RPAD];
    __shared__ __half Bs[NS][TN][RPAD];
    if ((int)blockIdx.x < nb0) gemm_core(P0, blockIdx.x, As, Bs);
    else                       gemm_core(P1, blockIdx.x - nb0, As, Bs);
}

// ---------------- aggregation cores ----------------------------------------
__device__ __forceinline__ void gin_core(const __half* __restrict__ y,
                                         const int* __restrict__ col,
                                         const int* __restrict__ rowptr,
                                         const float* __restrict__ b1,
                                         __half* __restrict__ z,
                                         int node, int lane) {
    const uint2* yv = (const uint2*)y;
    float ax, ay, az, aw;
    {
        uint2 v = yv[(size_t)node * 32 + lane];
        float2 p0 = __half22float2(*(const __half2*)&v.x);
        float2 p1 = __half22float2(*(const __half2*)&v.y);
        ax = p0.x; ay = p0.y; az = p1.x; aw = p1.y;
    }
    int b = rowptr[node], e = rowptr[node + 1];
    int j = b;
    for (; j + 8 <= e; j += 8) {
        int c0 = col[j],     c1 = col[j + 1], c2 = col[j + 2], c3 = col[j + 3];
        int c4 = col[j + 4], c5 = col[j + 5], c6 = col[j + 6], c7 = col[j + 7];
        uint2 v0 = yv[(size_t)c0 * 32 + lane];
        uint2 v1 = yv[(size_t)c1 * 32 + lane];
        uint2 v2 = yv[(size_t)c2 * 32 + lane];
        uint2 v3 = yv[(size_t)c3 * 32 + lane];
        uint2 v4 = yv[(size_t)c4 * 32 + lane];
        uint2 v5 = yv[(size_t)c5 * 32 + lane];
        uint2 v6 = yv[(size_t)c6 * 32 + lane];
        uint2 v7 = yv[(size_t)c7 * 32 + lane];
        __half2 p0 = __hadd2(__hadd2(*(__half2*)&v0.x, *(__half2*)&v1.x),
                             __hadd2(*(__half2*)&v2.x, *(__half2*)&v3.x));
        __half2 p1 = __hadd2(__hadd2(*(__half2*)&v4.x, *(__half2*)&v5.x),
                             __hadd2(*(__half2*)&v6.x, *(__half2*)&v7.x));
        __half2 q0 = __hadd2(__hadd2(*(__half2*)&v0.y, *(__half2*)&v1.y),
                             __hadd2(*(__half2*)&v2.y, *(__half2*)&v3.y));
        __half2 q1 = __hadd2(__hadd2(*(__half2*)&v4.y, *(__half2*)&v5.y),
                             __hadd2(*(__half2*)&v6.y, *(__half2*)&v7.y));
        float2 f0 = __half22float2(p0);
        float2 f1 = __half22float2(p1);
        float2 g0 = __half22float2(q0);
        float2 g1 = __half22float2(q1);
        ax += f0.x + f1.x; ay += f0.y + f1.y;
        az += g0.x + g1.x; aw += g0.y + g1.y;
    }
    for (; j < e; j++) {
        uint2 v = yv[(size_t)col[j] * 32 + lane];
        float2 p0 = __half22float2(*(const __half2*)&v.x);
        float2 p1 = __half22float2(*(const __half2*)&v.y);
        ax += p0.x; ay += p0.y; az += p1.x; aw += p1.y;
    }
    float4 bb = ((const float4*)b1)[lane];
    __half2 o0 = __floats2half2_rn(fmaxf(ax + bb.x, 0.f), fmaxf(ay + bb.y, 0.f));
    __half2 o1 = __floats2half2_rn(fmaxf(az + bb.z, 0.f), fmaxf(aw + bb.w, 0.f));
    uint2 p; p.x = *(uint32_t*)&o0; p.y = *(uint32_t*)&o1;
    ((uint2*)z)[(size_t)node * 32 + lane] = p;
}

__device__ __forceinline__ void gcn_core(const __half* __restrict__ hsp,
                                         const float* __restrict__ dinv,
                                         const int* __restrict__ col,
                                         const int* __restrict__ rowptr,
                                         const float* __restrict__ bias,
                                         __half* __restrict__ s,
                                         int node, int lane) {
    const uint2* hv = (const uint2*)hsp;
    float ax, ay, az, aw;
    {
        uint2 v = hv[(size_t)node * 32 + lane];
        float2 p0 = __half22float2(*(const __half2*)&v.x);
        float2 p1 = __half22float2(*(const __half2*)&v.y);
        ax = p0.x; ay = p0.y; az = p1.x; aw = p1.y;
    }
    int b = rowptr[node], e = rowptr[node + 1];
    int j = b;
    for (; j + 8 <= e; j += 8) {
        int c0 = col[j],     c1 = col[j + 1], c2 = col[j + 2], c3 = col[j + 3];
        int c4 = col[j + 4], c5 = col[j + 5], c6 = col[j + 6], c7 = col[j + 7];
        uint2 v0 = hv[(size_t)c0 * 32 + lane];
        uint2 v1 = hv[(size_t)c1 * 32 + lane];
        uint2 v2 = hv[(size_t)c2 * 32 + lane];
        uint2 v3 = hv[(size_t)c3 * 32 + lane];
        uint2 v4 = hv[(size_t)c4 * 32 + lane];
        uint2 v5 = hv[(size_t)c5 * 32 + lane];
        uint2 v6 = hv[(size_t)c6 * 32 + lane];
        uint2 v7 = hv[(size_t)c7 * 32 + lane];
        __half2 p0 = __hadd2(__hadd2(*(__half2*)&v0.x, *(__half2*)&v1.x),
                             __hadd2(*(__half2*)&v2.x, *(__half2*)&v3.x));
        __half2 p1 = __hadd2(__hadd2(*(__half2*)&v4.x, *(__half2*)&v5.x),
                             __hadd2(*(__half2*)&v6.x, *(__half2*)&v7.x));
        __half2 q0 = __hadd2(__hadd2(*(__half2*)&v0.y, *(__half2*)&v1.y),
                             __hadd2(*(__half2*)&v2.y, *(__half2*)&v3.y));
        __half2 q1 = __hadd2(__hadd2(*(__half2*)&v4.y, *(__half2*)&v5.y),
                             __hadd2(*(__half2*)&v6.y, *(__half2*)&v7.y));
        float2 f0 = __half22float2(p0);
        float2 f1 = __half22float2(p1);
        float2 g0 = __half22float2(q0);
        float2 g1 = __half22float2(q1);
        ax += f0.x + f1.x; ay += f0.y + f1.y;
        az += g0.x + g1.x; aw += g0.y + g1.y;
    }
    for (; j < e; j++) {
        uint2 v = hv[(size_t)col[j] * 32 + lane];
        float2 p0 = __half22float2(*(const __half2*)&v.x);
        float2 p1 = __half22float2(*(const __half2*)&v.y);
        ax += p0.x; ay += p0.y; az += p1.x; aw += p1.y;
    }
    float di = dinv[node];
    float4 bb = ((const float4*)bias)[lane];
    __half2 o0 = __floats2half2_rn(tanhf(di * ax + bb.x), tanhf(di * ay + bb.y));
    __half2 o1 = __floats2half2_rn(tanhf(di * az + bb.z), tanhf(di * aw + bb.w));
    uint2 p; p.x = *(uint32_t*)&o0; p.y = *(uint32_t*)&o1;
    ((uint2*)s)[(size_t)node * 32 + lane] = p;
}

// combined agg launch: blocks [0, nb0) -> GIN, [nb0, 2*nb0) -> GCN
__global__ __launch_bounds__(256)
void agg_both_kernel(const __half* __restrict__ y,
                     const __half* __restrict__ hsp,
                     const float* __restrict__ dinv,
                     const int* __restrict__ col,
                     const int* __restrict__ rowptr,
                     const float* __restrict__ b1,
                     const float* __restrict__ gcn_b,
                     __half* __restrict__ z,
                     __half* __restrict__ s,
                     int nb0) {
    int lane = threadIdx.x & 31;
    if ((int)blockIdx.x < nb0) {
        int node = (blockIdx.x * blockDim.x + threadIdx.x) >> 5;
        if (node < NN) gin_core(y, col, rowptr, b1, z, node, lane);
    } else {
        int node = ((blockIdx.x - nb0) * blockDim.x + threadIdx.x) >> 5;
        if (node < NN) gcn_core(hsp, dinv, col, rowptr, gcn_b, s, node, lane);
    }
}

// ---------------- global add pool -----------------------------------------
__global__ void pool_kernel(const float* __restrict__ xf,
                            const int* __restrict__ batch,
                            float* __restrict__ g) {
    int idx = blockIdx.x * blockDim.x + threadIdx.x;
    if (idx < NN * HH) {
        int i = idx >> 7;
        int f = idx & 127;
        atomicAdd(&g[batch[i] * HH + f], xf[idx]);
    }
}

// ---------------- post: relu(g @ post_w + b) ------------------------------
__global__ void post_kernel(const float* __restrict__ g,
                            const float* __restrict__ W,
                            const float* __restrict__ bias,
                            float* __restrict__ gp) {
    int r = blockIdx.x;
    int c = threadIdx.x;
    __shared__ float row[HH];
    row[c] = g[(size_t)r * HH + c];
    __syncthreads();
    float acc = bias[c];
#pragma unroll 8
    for (int k = 0; k < HH; k++) acc = fmaf(row[k], W[(size_t)k * HH + c], acc);
    gp[(size_t)r * HH + c] = fmaxf(acc, 0.0f);
}

// ---------------- readout + log_softmax ----------------------------------
__global__ void readout_kernel(const float* __restrict__ gp,
                               const float* __restrict__ W,
                               const float* __restrict__ bias,
                               float* __restrict__ out) {
    int r = blockIdx.x * blockDim.x + threadIdx.x;
    if (r < GG) {
        float logit[CC];
#pragma unroll
        for (int c = 0; c < CC; c++) logit[c] = bias[c];
        for (int k = 0; k < HH; k++) {
            float gv = gp[(size_t)r * HH + k];
#pragma unroll
            for (int c = 0; c < CC; c++)
                logit[c] = fmaf(gv, W[(size_t)k * CC + c], logit[c]);
        }
        float m = logit[0];
#pragma unroll
        for (int c = 1; c < CC; c++) m = fmaxf(m, logit[c]);
        float sum = 0.0f;
#pragma unroll
        for (int c = 0; c < CC; c++) sum += expf(logit[c] - m);
        float lse = m + logf(sum);
#pragma unroll
        for (int c = 0; c < CC; c++) out[(size_t)r * CC + c] = logit[c] - lse;
    }
}

// ---------------- driver ---------------------------------------------------
extern "C" void kernel_launch(void* const* d_in, const int* in_sizes, int n_in,
                              void* d_out, int out_size) {
    const float* x_in   = (const float*)d_in[0];
    const float* s_in   = (const float*)d_in[1];
    const int*   ei     = (const int*)d_in[2];
    const int*   batch  = (const int*)d_in[3];
    const float* pre_w  = (const float*)d_in[4];
    const float* pre_b  = (const float*)d_in[5];
    const float* emb_w  = (const float*)d_in[6];
    const float* emb_b  = (const float*)d_in[7];
    const float* gin_w1 = (const float*)d_in[8];
    const float* gin_b1 = (const float*)d_in[9];
    const float* gin_w2 = (const float*)d_in[10];
    const float* gin_b2 = (const float*)d_in[11];
    const float* gcn_w  = (const float*)d_in[12];
    const float* gcn_b  = (const float*)d_in[13];
    const float* whp_w  = (const float*)d_in[14];
    const float* whp_b  = (const float*)d_in[15];
    const float* post_w = (const float*)d_in[16];
    const float* post_b = (const float*)d_in[17];
    const float* ro_w   = (const float*)d_in[18];
    const float* ro_b   = (const float*)d_in[19];
    float* out = (float*)d_out;

    float *px, *ps, *py, *pz, *phs, *pg, *pgp, *pdinv;
    int *pdegc, *prow, *pcur, *pcol;
    __half *pxh, *pshn, *pwpre, *pwemb, *pwg1, *pwgc, *pwg2, *pwwhp;
    cudaGetSymbolAddress((void**)&px,    d_x);
    cudaGetSymbolAddress((void**)&ps,    d_s);
    cudaGetSymbolAddress((void**)&py,    d_y);
    cudaGetSymbolAddress((void**)&pz,    d_z);
    cudaGetSymbolAddress((void**)&phs,   d_hs);
    cudaGetSymbolAddress((void**)&pg,    d_g);
    cudaGetSymbolAddress((void**)&pgp,   d_gp);
    cudaGetSymbolAddress((void**)&pdinv, d_dinv);
    cudaGetSymbolAddress((void**)&pdegc, d_degc);
    cudaGetSymbolAddress((void**)&prow,  d_rowptr);
    cudaGetSymbolAddress((void**)&pcur,  d_cursor);
    cudaGetSymbolAddress((void**)&pcol,  d_col);
    cudaGetSymbolAddress((void**)&pxh,   d_xh);
    cudaGetSymbolAddress((void**)&pshn,  d_shn);
    cudaGetSymbolAddress((void**)&pwpre, d_wpre);
    cudaGetSymbolAddress((void**)&pwemb, d_wemb);
    cudaGetSymbolAddress((void**)&pwg1,  d_wg1);
    cudaGetSymbolAddress((void**)&pwgc,  d_wgc);
    cudaGetSymbolAddress((void**)&pwg2,  d_wg2);
    cudaGetSymbolAddress((void**)&pwwhp, d_wwhp);
    __half* pxH  = (__half*)px;
    __half* psH  = (__half*)ps;
    __half* pyH  = (__half*)py;
    __half* pzH  = (__half*)pz;
    __half* phsH = (__half*)phs;

    const int TPB = 256;
    const int eBlocks = (EE + TPB - 1) / TPB;
    const int gB = (NN + TM - 1) / TM;       // 391
    const int aggB = (NN * 32 + TPB - 1) / TPB;

    // ---- prep ----
    f2h_kernel<<<(NN * FIN / 4 + TPB - 1) / TPB, TPB>>>(x_in, pxh, NN * FIN / 4);
    f2h_kernel<<<(NN * NSE / 4 + TPB - 1) / TPB, TPB>>>(s_in, pshn, NN * NSE / 4);
    wtrans_kernel<<<(128 * 128 + TPB - 1) / TPB, TPB>>>(pre_w, pwpre, 128, 128 * 128);
    wtrans_kernel<<<(16 * 128 + TPB - 1) / TPB, TPB>>>(emb_w, pwemb, 16, 16 * 128);
    wtrans_kernel<<<(3 * 256 * 128 + TPB - 1) / TPB, TPB>>>(gin_w1, pwg1, 256, 3 * 256 * 128);
    wtrans_kernel<<<(3 * 128 * 128 + TPB - 1) / TPB, TPB>>>(gcn_w, pwgc, 128, 3 * 128 * 128);
    wtrans_kernel<<<(3 * 128 * 128 + TPB - 1) / TPB, TPB>>>(gin_w2, pwg2, 128, 3 * 128 * 128);
    wtrans_kernel<<<(256 * 128 + TPB - 1) / TPB, TPB>>>(whp_w, pwwhp, 256, 256 * 128);

    // ---- CSR build ----
    cudaMemsetAsync(pdegc, 0, NN * sizeof(int), 0);
    cudaMemsetAsync(pcur,  0, NN * sizeof(int), 0);
    count_deg_kernel<<<eBlocks, TPB>>>(ei, pdegc);
    scan_deg_kernel<<<1, 1024>>>(pdegc, prow, pdinv);
    fill_csr_kernel<<<eBlocks, TPB>>>(ei, prow, pcur, pcol);

    // ---- pre + emb fused ----
    GemmP Ppre = { pxh, FIN, nullptr, 0, pwpre, pre_b, nullptr, pxH, NN, 0, 1 };
    GemmP Pemb = { pshn, NSE, nullptr, 0, pwemb, emb_b, nullptr, psH, NN, 0, 1 };
    h_gemm2<<<2 * gB, 256>>>(Ppre, Pemb, gB);

    for (int i = 0; i < LL; i++) {
        GemmP Py  = { pxH, HH, psH, HH, pwg1 + (size_t)i * 128 * 256,
                      nullptr, nullptr, pyH, NN, 0, 1 };
        GemmP Phs = { psH, HH, nullptr, 0, pwgc + (size_t)i * 128 * 128,
                      nullptr, pdinv, phsH, NN, 0, 1 };
        h_gemm2<<<2 * gB, 256>>>(Py, Phs, gB);

        agg_both_kernel<<<2 * aggB, TPB>>>(pyH, phsH, pdinv, pcol, prow,
                                           gin_b1 + (size_t)i * HH,
                                           gcn_b + (size_t)i * HH,
                                           pzH, psH, aggB);

        GemmP Pw2 = { pzH, HH, nullptr, 0, pwg2 + (size_t)i * 128 * 128,
                      gin_b2 + (size_t)i * HH, nullptr, pxH, NN, 1, 1 };
        h_gemm1<<<gB, 256>>>(Pw2);
    }

    // whp on split concat (fp32 out for pooling)
    GemmP Pwhp = { pxH, HH, psH, HH, pwwhp, whp_b, nullptr, py, NN, 0, 0 };
    h_gemm1<<<gB, 256>>>(Pwhp);

    // pool -> post -> readout
    cudaMemsetAsync(pg, 0, GG * HH * sizeof(float), 0);
    pool_kernel<<<(NN * HH + TPB - 1) / TPB, TPB>>>(py, batch, pg);
    post_kernel<<<GG, HH>>>(pg, post_w, post_b, pgp);
    readout_kernel<<<1, GG>>>(pgp, ro_w, ro_b, out);
}

// round 15
// speedup vs baseline: 2.1678x; 1.1224x over previous
#include <cuda_runtime.h>
#include <cuda_bf16.h>
#include <cuda_fp16.h>
#include <math.h>
#include <stdint.h>

// Problem constants (fixed by the dataset)
#define NN 50000
#define EE 800000
#define HH 128
#define FIN 128
#define NSE 16
#define LL 3
#define CC 10
#define GG 256

// ---------------- scratch (static __device__ — no allocs allowed) ----------
__device__ float d_x [NN * HH];
__device__ float d_s [NN * HH];
__device__ float d_y [NN * HH];
__device__ float d_z [NN * HH];
__device__ float d_hs[NN * HH];
__device__ float d_g [GG * HH];
__device__ float d_dinv[NN];
__device__ int   d_degc[NN];
__device__ int   d_rowptr[NN + 1];
__device__ int   d_cursor[NN];
__device__ int   d_col[EE];
// fp16 converted inputs + weights (transposed [n][k])
__device__ __half d_xh [NN * FIN];
__device__ __half d_shn[NN * NSE];
__device__ __half d_wpre[128 * 128];
__device__ __half d_wemb[128 * 16];
__device__ __half d_wg1 [3 * 128 * 256];
__device__ __half d_wgc [3 * 128 * 128];
__device__ __half d_wg2 [3 * 128 * 128];
__device__ __half d_wwhp[128 * 256];

// ---------------- fused prep kernel ----------------------------------------
// Block-range-partitioned elementwise jobs:
//   f2h(x), f2h(s), 6 weight transposes, zero degc/cursor/g
#define PB_F2HX 6250   // 1,600,000 float4
#define PB_F2HS 782    // 200,000 float4
#define PB_WPRE 64     // 16384
#define PB_WEMB 8      // 2048
#define PB_WG1  384    // 98304
#define PB_WGC  192    // 49152
#define PB_WG2  192    // 49152
#define PB_WWHP 128    // 32768
#define PB_ZDEG 196    // 50000 ints
#define PB_ZCUR 196
#define PB_ZPG  128    // 32768 floats
#define PB_TOTAL (PB_F2HX+PB_F2HS+PB_WPRE+PB_WEMB+PB_WG1+PB_WGC+PB_WG2+PB_WWHP+PB_ZDEG+PB_ZCUR+PB_ZPG)

__device__ __forceinline__ void f2h_job(const float* src, __half* dst, int n4,
                                        int blk, int tid) {
    int i = blk * 256 + tid;
    if (i < n4) {
        float4 v = ((const float4*)src)[i];
        __half2 h0 = __floats2half2_rn(v.x, v.y);
        __half2 h1 = __floats2half2_rn(v.z, v.w);
        uint2 p; p.x = *(uint32_t*)&h0; p.y = *(uint32_t*)&h1;
        ((uint2*)dst)[i] = p;
    }
}
__device__ __forceinline__ void wt_job(const float* src, __half* dst, int K, int total,
                                       int blk, int tid) {
    int i = blk * 256 + tid;
    if (i < total) {
        int n = i & 127;
        int k = (i >> 7) % K;
        int m = i / (K * 128);
        dst[(size_t)m * 128 * K + (size_t)n * K + k] = __float2half(src[i]);
    }
}

__global__ __launch_bounds__(256)
void prep_all_kernel(const float* x_in, const float* s_in,
                     const float* pre_w, const float* emb_w,
                     const float* gin_w1, const float* gcn_w,
                     const float* gin_w2, const float* whp_w,
                     __half* xh, __half* shn,
                     __half* wpre, __half* wemb, __half* wg1,
                     __half* wgc, __half* wg2, __half* wwhp,
                     int* degc, int* cursor, float* g) {
    int b = blockIdx.x;
    int tid = threadIdx.x;
    if (b < PB_F2HX) { f2h_job(x_in, xh, NN * FIN / 4, b, tid); return; }
    b -= PB_F2HX;
    if (b < PB_F2HS) { f2h_job(s_in, shn, NN * NSE / 4, b, tid); return; }
    b -= PB_F2HS;
    if (b < PB_WPRE) { wt_job(pre_w, wpre, 128, 128 * 128, b, tid); return; }
    b -= PB_WPRE;
    if (b < PB_WEMB) { wt_job(emb_w, wemb, 16, 16 * 128, b, tid); return; }
    b -= PB_WEMB;
    if (b < PB_WG1)  { wt_job(gin_w1, wg1, 256, 3 * 256 * 128, b, tid); return; }
    b -= PB_WG1;
    if (b < PB_WGC)  { wt_job(gcn_w, wgc, 128, 3 * 128 * 128, b, tid); return; }
    b -= PB_WGC;
    if (b < PB_WG2)  { wt_job(gin_w2, wg2, 128, 3 * 128 * 128, b, tid); return; }
    b -= PB_WG2;
    if (b < PB_WWHP) { wt_job(whp_w, wwhp, 256, 256 * 128, b, tid); return; }
    b -= PB_WWHP;
    if (b < PB_ZDEG) { int i = b * 256 + tid; if (i < NN) degc[i] = 0; return; }
    b -= PB_ZDEG;
    if (b < PB_ZCUR) { int i = b * 256 + tid; if (i < NN) cursor[i] = 0; return; }
    b -= PB_ZCUR;
    { int i = b * 256 + tid; if (i < GG * HH) g[i] = 0.0f; }
}

// ---------------- CSR build ------------------------------------------------
__global__ void count_deg_kernel(const int* __restrict__ ei, int* __restrict__ degc) {
    int e = blockIdx.x * blockDim.x + threadIdx.x;
    if (e < EE) atomicAdd(&degc[ei[EE + e]], 1);
}

__global__ void scan_deg_kernel(const int* __restrict__ degc,
                                int* __restrict__ rowptr,
                                float* __restrict__ dinv) {
    __shared__ int ssum[1024];
    int t = threadIdx.x;
    const int chunk = (NN + 1023) / 1024;
    int b0 = t * chunk;
    int b1 = b0 + chunk; if (b1 > NN) b1 = NN;
    int sum = 0;
    for (int i = b0; i < b1; i++) sum += degc[i];
    ssum[t] = sum;
    __syncthreads();
    for (int off = 1; off < 1024; off <<= 1) {
        int v = 0;
        if (t >= off) v = ssum[t - off];
        __syncthreads();
        if (t >= off) ssum[t] += v;
        __syncthreads();
    }
    int prefix = (t == 0) ? 0 : ssum[t - 1];
    for (int i = b0; i < b1; i++) {
        int d = degc[i];
        rowptr[i] = prefix;
        prefix += d;
        dinv[i] = rsqrtf((float)d + 1.0f);
    }
    if (t == 1023) rowptr[NN] = ssum[1023];
}

__global__ void fill_csr_kernel(const int* __restrict__ ei,
                                const int* __restrict__ rowptr,
                                int* __restrict__ cursor,
                                int* __restrict__ col) {
    int e = blockIdx.x * blockDim.x + threadIdx.x;
    if (e < EE) {
        int src = ei[e];
        int dst = ei[EE + e];
        int pos = atomicAdd(&cursor[dst], 1);
        col[rowptr[dst] + pos] = src;
    }
}

// ---------------- cp.async helpers ----------------------------------------
__device__ __forceinline__ uint32_t smem_u32(const void* p) {
    uint32_t a;
    asm("{ .reg .u64 t; cvta.to.shared.u64 t, %1; cvt.u32.u64 %0, t; }"
        : "=r"(a) : "l"(p));
    return a;
}
__device__ __forceinline__ void cp16(uint32_t dst, const void* src, int sz) {
    asm volatile("cp.async.cg.shared.global [%0], [%1], 16, %2;"
                 :: "r"(dst), "l"(src), "r"(sz));
}
#define CP_COMMIT() asm volatile("cp.async.commit_group;")
#define CP_WAIT(n)  asm volatile("cp.async.wait_group %0;" :: "n"(n))

__device__ __forceinline__ void mma_f16(float* c, const uint32_t* a, const uint32_t* b) {
    asm volatile("mma.sync.aligned.m16n8k16.row.col.f32.f16.f16.f32 "
        "{%0,%1,%2,%3}, {%4,%5,%6,%7}, {%8,%9}, {%0,%1,%2,%3};"
        : "+f"(c[0]), "+f"(c[1]), "+f"(c[2]), "+f"(c[3])
        : "r"(a[0]), "r"(a[1]), "r"(a[2]), "r"(a[3]), "r"(b[0]), "r"(b[1]));
}

// ---------------- GEMM params + core ---------------------------------------
#define TM 128
#define TN 128
#define TKK 16
#define RPAD 24
#define NS 3

struct GemmP {
    const __half* A1; int K1;
    const __half* A2; int K2;
    const __half* Wt;
    const float* bias;
    const float* rowscale;
    const int* batchp;       // if non-null: pool mode, atomicAdd into C[batch[r]*128+col]
    void* C; int M; int relu; int outHalf;
};

__device__ __forceinline__ void gemm_core(
    const GemmP& P, int blk,
    __half (*As)[TM][RPAD], __half (*Bs)[TN][RPAD]) {
    const int tid  = threadIdx.x;
    const int wid  = tid >> 5;
    const int lane = tid & 31;
    const int g    = lane >> 2;
    const int t    = lane & 3;
    const int wm   = wid & 3;
    const int wn   = wid >> 2;
    const int row0 = blk * TM;
    const int Ktot = P.K1 + P.K2;
    const int nb   = Ktot / TKK;

    float acc[2][8][4];
#pragma unroll
    for (int mi = 0; mi < 2; mi++)
#pragma unroll
        for (int ni = 0; ni < 8; ni++)
#pragma unroll
            for (int q = 0; q < 4; q++) acc[mi][ni][q] = 0.0f;

    const int r  = tid >> 1;
    const int ch = (tid & 1) * 8;
    const int grow = row0 + r;

    auto issue = [&](int kb) {
        int st = kb % NS;
        int kg = kb * TKK + ch;
        const __half* sa;
        if (kg < P.K1) sa = P.A1 + (size_t)grow * P.K1 + kg;
        else           sa = P.A2 + (size_t)grow * P.K2 + (kg - P.K1);
        cp16(smem_u32(&As[st][r][ch]), sa, (grow < P.M) ? 16 : 0);
        cp16(smem_u32(&Bs[st][r][ch]), P.Wt + (size_t)r * Ktot + kg, 16);
    };

#pragma unroll
    for (int s = 0; s < NS - 1; s++) {
        if (s < nb) issue(s);
        CP_COMMIT();
    }

    for (int kb = 0; kb < nb; kb++) {
        CP_WAIT(NS - 2);
        __syncthreads();
        if (kb + NS - 1 < nb) issue(kb + NS - 1);
        CP_COMMIT();

        const int cur = kb % NS;
        uint32_t af[2][4];
#pragma unroll
        for (int mi = 0; mi < 2; mi++) {
            int mb = wm * 32 + mi * 16;
            af[mi][0] = *(const uint32_t*)&As[cur][mb + g    ][2 * t    ];
            af[mi][1] = *(const uint32_t*)&As[cur][mb + g + 8][2 * t    ];
            af[mi][2] = *(const uint32_t*)&As[cur][mb + g    ][2 * t + 8];
            af[mi][3] = *(const uint32_t*)&As[cur][mb + g + 8][2 * t + 8];
        }
        uint32_t bf[8][2];
#pragma unroll
        for (int ni = 0; ni < 8; ni++) {
            int nbase = wn * 64 + ni * 8 + g;
            bf[ni][0] = *(const uint32_t*)&Bs[cur][nbase][2 * t    ];
            bf[ni][1] = *(const uint32_t*)&Bs[cur][nbase][2 * t + 8];
        }
#pragma unroll
        for (int mi = 0; mi < 2; mi++)
#pragma unroll
            for (int ni = 0; ni < 8; ni++)
                mma_f16(acc[mi][ni], af[mi], bf[ni]);
    }

    float* Cf = (float*)P.C;
    __half* Chh = (__half*)P.C;
#pragma unroll
    for (int mi = 0; mi < 2; mi++) {
        int rbase = row0 + wm * 32 + mi * 16 + g;
        float rs0 = 1.f, rs1 = 1.f;
        if (P.rowscale) {
            if (rbase < P.M)     rs0 = P.rowscale[rbase];
            if (rbase + 8 < P.M) rs1 = P.rowscale[rbase + 8];
        }
#pragma unroll
        for (int ni = 0; ni < 8; ni++) {
            int colb = wn * 64 + ni * 8 + 2 * t;
            float b0 = P.bias ? P.bias[colb]     : 0.f;
            float b1 = P.bias ? P.bias[colb + 1] : 0.f;
            float v0 = acc[mi][ni][0] * rs0 + b0;
            float v1 = acc[mi][ni][1] * rs0 + b1;
            float v2 = acc[mi][ni][2] * rs1 + b0;
            float v3 = acc[mi][ni][3] * rs1 + b1;
            if (P.relu) {
                v0 = fmaxf(v0, 0.f); v1 = fmaxf(v1, 0.f);
                v2 = fmaxf(v2, 0.f); v3 = fmaxf(v3, 0.f);
            }
            if (P.batchp) {
                // pool mode: accumulate per-graph sums directly
                if (rbase < P.M) {
                    int gi = P.batchp[rbase];
                    atomicAdd(&Cf[gi * 128 + colb],     v0);
                    atomicAdd(&Cf[gi * 128 + colb + 1], v1);
                }
                if (rbase + 8 < P.M) {
                    int gi = P.batchp[rbase + 8];
                    atomicAdd(&Cf[gi * 128 + colb],     v2);
                    atomicAdd(&Cf[gi * 128 + colb + 1], v3);
                }
            } else if (P.outHalf) {
                if (rbase < P.M)
                    *(__half2*)(Chh + (size_t)rbase * TN + colb) = __floats2half2_rn(v0, v1);
                if (rbase + 8 < P.M)
                    *(__half2*)(Chh + (size_t)(rbase + 8) * TN + colb) = __floats2half2_rn(v2, v3);
            } else {
                if (rbase < P.M)
                    *(float2*)(Cf + (size_t)rbase * TN + colb) = make_float2(v0, v1);
                if (rbase + 8 < P.M)
                    *(float2*)(Cf + (size_t)(rbase + 8) * TN + colb) = make_float2(v2, v3);
            }
        }
    }
}

__global__ __launch_bounds__(256, 2)
void h_gemm1(GemmP P0) {
    __shared__ __half As[NS][TM][RPAD];
    __shared__ __half Bs[NS][TN][RPAD];
    gemm_core(P0, blockIdx.x, As, Bs);
}
__global__ __launch_bounds__(256, 2)
void h_gemm2(GemmP P0, GemmP P1, int nb0) {
    __shared__ __half As[NS][TM][RPAD];
    __shared__ __half Bs[NS][TN][RPAD];
    if ((int)blockIdx.x < nb0) gemm_core(P0, blockIdx.x, As, Bs);
    else                       gemm_core(P1, blockIdx.x - nb0, As, Bs);
}

// ---------------- aggregation cores ----------------------------------------
__device__ __forceinline__ void gin_core(const __half* __restrict__ y,
                                         const int* __restrict__ col,
                                         const int* __restrict__ rowptr,
                                         const float* __restrict__ b1,
                                         __half* __restrict__ z,
                                         int node, int lane) {
    const uint2* yv = (const uint2*)y;
    float ax, ay, az, aw;
    {
        uint2 v = yv[(size_t)node * 32 + lane];
        float2 p0 = __half22float2(*(const __half2*)&v.x);
        float2 p1 = __half22float2(*(const __half2*)&v.y);
        ax = p0.x; ay = p0.y; az = p1.x; aw = p1.y;
    }
    int b = rowptr[node], e = rowptr[node + 1];
    int j = b;
    for (; j + 8 <= e; j += 8) {
        int c0 = col[j],     c1 = col[j + 1], c2 = col[j + 2], c3 = col[j + 3];
        int c4 = col[j + 4], c5 = col[j + 5], c6 = col[j + 6], c7 = col[j + 7];
        uint2 v0 = yv[(size_t)c0 * 32 + lane];
        uint2 v1 = yv[(size_t)c1 * 32 + lane];
        uint2 v2 = yv[(size_t)c2 * 32 + lane];
        uint2 v3 = yv[(size_t)c3 * 32 + lane];
        uint2 v4 = yv[(size_t)c4 * 32 + lane];
        uint2 v5 = yv[(size_t)c5 * 32 + lane];
        uint2 v6 = yv[(size_t)c6 * 32 + lane];
        uint2 v7 = yv[(size_t)c7 * 32 + lane];
        __half2 p0 = __hadd2(__hadd2(*(__half2*)&v0.x, *(__half2*)&v1.x),
                             __hadd2(*(__half2*)&v2.x, *(__half2*)&v3.x));
        __half2 p1 = __hadd2(__hadd2(*(__half2*)&v4.x, *(__half2*)&v5.x),
                             __hadd2(*(__half2*)&v6.x, *(__half2*)&v7.x));
        __half2 q0 = __hadd2(__hadd2(*(__half2*)&v0.y, *(__half2*)&v1.y),
                             __hadd2(*(__half2*)&v2.y, *(__half2*)&v3.y));
        __half2 q1 = __hadd2(__hadd2(*(__half2*)&v4.y, *(__half2*)&v5.y),
                             __hadd2(*(__half2*)&v6.y, *(__half2*)&v7.y));
        float2 f0 = __half22float2(p0);
        float2 f1 = __half22float2(p1);
        float2 g0 = __half22float2(q0);
        float2 g1 = __half22float2(q1);
        ax += f0.x + f1.x; ay += f0.y + f1.y;
        az += g0.x + g1.x; aw += g0.y + g1.y;
    }
    for (; j < e; j++) {
        uint2 v = yv[(size_t)col[j] * 32 + lane];
        float2 p0 = __half22float2(*(const __half2*)&v.x);
        float2 p1 = __half22float2(*(const __half2*)&v.y);
        ax += p0.x; ay += p0.y; az += p1.x; aw += p1.y;
    }
    float4 bb = ((const float4*)b1)[lane];
    __half2 o0 = __floats2half2_rn(fmaxf(ax + bb.x, 0.f), fmaxf(ay + bb.y, 0.f));
    __half2 o1 = __floats2half2_rn(fmaxf(az + bb.z, 0.f), fmaxf(aw + bb.w, 0.f));
    uint2 p; p.x = *(uint32_t*)&o0; p.y = *(uint32_t*)&o1;
    ((uint2*)z)[(size_t)node * 32 + lane] = p;
}

__device__ __forceinline__ void gcn_core(const __half* __restrict__ hsp,
                                         const float* __restrict__ dinv,
                                         const int* __restrict__ col,
                                         const int* __restrict__ rowptr,
                                         const float* __restrict__ bias,
                                         __half* __restrict__ s,
                                         int node, int lane) {
    const uint2* hv = (const uint2*)hsp;
    float ax, ay, az, aw;
    {
        uint2 v = hv[(size_t)node * 32 + lane];
        float2 p0 = __half22float2(*(const __half2*)&v.x);
        float2 p1 = __half22float2(*(const __half2*)&v.y);
        ax = p0.x; ay = p0.y; az = p1.x; aw = p1.y;
    }
    int b = rowptr[node], e = rowptr[node + 1];
    int j = b;
    for (; j + 8 <= e; j += 8) {
        int c0 = col[j],     c1 = col[j + 1], c2 = col[j + 2], c3 = col[j + 3];
        int c4 = col[j + 4], c5 = col[j + 5], c6 = col[j + 6], c7 = col[j + 7];
        uint2 v0 = hv[(size_t)c0 * 32 + lane];
        uint2 v1 = hv[(size_t)c1 * 32 + lane];
        uint2 v2 = hv[(size_t)c2 * 32 + lane];
        uint2 v3 = hv[(size_t)c3 * 32 + lane];
        uint2 v4 = hv[(size_t)c4 * 32 + lane];
        uint2 v5 = hv[(size_t)c5 * 32 + lane];
        uint2 v6 = hv[(size_t)c6 * 32 + lane];
        uint2 v7 = hv[(size_t)c7 * 32 + lane];
        __half2 p0 = __hadd2(__hadd2(*(__half2*)&v0.x, *(__half2*)&v1.x),
                             __hadd2(*(__half2*)&v2.x, *(__half2*)&v3.x));
        __half2 p1 = __hadd2(__hadd2(*(__half2*)&v4.x, *(__half2*)&v5.x),
                             __hadd2(*(__half2*)&v6.x, *(__half2*)&v7.x));
        __half2 q0 = __hadd2(__hadd2(*(__half2*)&v0.y, *(__half2*)&v1.y),
                             __hadd2(*(__half2*)&v2.y, *(__half2*)&v3.y));
        __half2 q1 = __hadd2(__hadd2(*(__half2*)&v4.y, *(__half2*)&v5.y),
                             __hadd2(*(__half2*)&v6.y, *(__half2*)&v7.y));
        float2 f0 = __half22float2(p0);
        float2 f1 = __half22float2(p1);
        float2 g0 = __half22float2(q0);
        float2 g1 = __half22float2(q1);
        ax += f0.x + f1.x; ay += f0.y + f1.y;
        az += g0.x + g1.x; aw += g0.y + g1.y;
    }
    for (; j < e; j++) {
        uint2 v = hv[(size_t)col[j] * 32 + lane];
        float2 p0 = __half22float2(*(const __half2*)&v.x);
        float2 p1 = __half22float2(*(const __half2*)&v.y);
        ax += p0.x; ay += p0.y; az += p1.x; aw += p1.y;
    }
    float di = dinv[node];
    float4 bb = ((const float4*)bias)[lane];
    __half2 o0 = __floats2half2_rn(tanhf(di * ax + bb.x), tanhf(di * ay + bb.y));
    __half2 o1 = __floats2half2_rn(tanhf(di * az + bb.z), tanhf(di * aw + bb.w));
    uint2 p; p.x = *(uint32_t*)&o0; p.y = *(uint32_t*)&o1;
    ((uint2*)s)[(size_t)node * 32 + lane] = p;
}

__global__ __launch_bounds__(256)
void agg_both_kernel(const __half* __restrict__ y,
                     const __half* __restrict__ hsp,
                     const float* __restrict__ dinv,
                     const int* __restrict__ col,
                     const int* __restrict__ rowptr,
                     const float* __restrict__ b1,
                     const float* __restrict__ gcn_b,
                     __half* __restrict__ z,
                     __half* __restrict__ s,
                     int nb0) {
    int lane = threadIdx.x & 31;
    if ((int)blockIdx.x < nb0) {
        int node = (blockIdx.x * blockDim.x + threadIdx.x) >> 5;
        if (node < NN) gin_core(y, col, rowptr, b1, z, node, lane);
    } else {
        int node = ((blockIdx.x - nb0) * blockDim.x + threadIdx.x) >> 5;
        if (node < NN) gcn_core(hsp, dinv, col, rowptr, gcn_b, s, node, lane);
    }
}

// ---------------- fused post + readout -------------------------------------
// Block r: gp_row = relu(g[r]@post_w + post_b); out[r] = log_softmax(gp_row@ro_w + ro_b)
__global__ __launch_bounds__(128)
void post_readout_kernel(const float* __restrict__ g,
                         const float* __restrict__ post_w,
                         const float* __restrict__ post_b,
                         const float* __restrict__ ro_w,
                         const float* __restrict__ ro_b,
                         float* __restrict__ out) {
    int r = blockIdx.x;
    int c = threadIdx.x;
    __shared__ float row[HH];
    __shared__ float gp[HH];
    __shared__ float logit[CC];
    row[c] = g[(size_t)r * HH + c];
    __syncthreads();
    float acc = post_b[c];
#pragma unroll 8
    for (int k = 0; k < HH; k++) acc = fmaf(row[k], post_w[(size_t)k * HH + c], acc);
    gp[c] = fmaxf(acc, 0.0f);
    __syncthreads();
    if (c < CC) {
        float l = ro_b[c];
        for (int k = 0; k < HH; k++) l = fmaf(gp[k], ro_w[(size_t)k * CC + c], l);
        logit[c] = l;
    }
    __syncthreads();
    if (c < CC) {
        float m = logit[0];
#pragma unroll
        for (int q = 1; q < CC; q++) m = fmaxf(m, logit[q]);
        float sum = 0.0f;
#pragma unroll
        for (int q = 0; q < CC; q++) sum += expf(logit[q] - m);
        float lse = m + logf(sum);
        out[(size_t)r * CC + c] = logit[c] - lse;
    }
}

// ---------------- driver ---------------------------------------------------
extern "C" void kernel_launch(void* const* d_in, const int* in_sizes, int n_in,
                              void* d_out, int out_size) {
    const float* x_in   = (const float*)d_in[0];
    const float* s_in   = (const float*)d_in[1];
    const int*   ei     = (const int*)d_in[2];
    const int*   batch  = (const int*)d_in[3];
    const float* pre_w  = (const float*)d_in[4];
    const float* pre_b  = (const float*)d_in[5];
    const float* emb_w  = (const float*)d_in[6];
    const float* emb_b  = (const float*)d_in[7];
    const float* gin_w1 = (const float*)d_in[8];
    const float* gin_b1 = (const float*)d_in[9];
    const float* gin_w2 = (const float*)d_in[10];
    const float* gin_b2 = (const float*)d_in[11];
    const float* gcn_w  = (const float*)d_in[12];
    const float* gcn_b  = (const float*)d_in[13];
    const float* whp_w  = (const float*)d_in[14];
    const float* whp_b  = (const float*)d_in[15];
    const float* post_w = (const float*)d_in[16];
    const float* post_b = (const float*)d_in[17];
    const float* ro_w   = (const float*)d_in[18];
    const float* ro_b   = (const float*)d_in[19];
    float* out = (float*)d_out;

    float *px, *ps, *py, *pz, *phs, *pg, *pdinv;
    int *pdegc, *prow, *pcur, *pcol;
    __half *pxh, *pshn, *pwpre, *pwemb, *pwg1, *pwgc, *pwg2, *pwwhp;
    cudaGetSymbolAddress((void**)&px,    d_x);
    cudaGetSymbolAddress((void**)&ps,    d_s);
    cudaGetSymbolAddress((void**)&py,    d_y);
    cudaGetSymbolAddress((void**)&pz,    d_z);
    cudaGetSymbolAddress((void**)&phs,   d_hs);
    cudaGetSymbolAddress((void**)&pg,    d_g);
    cudaGetSymbolAddress((void**)&pdinv, d_dinv);
    cudaGetSymbolAddress((void**)&pdegc, d_degc);
    cudaGetSymbolAddress((void**)&prow,  d_rowptr);
    cudaGetSymbolAddress((void**)&pcur,  d_cursor);
    cudaGetSymbolAddress((void**)&pcol,  d_col);
    cudaGetSymbolAddress((void**)&pxh,   d_xh);
    cudaGetSymbolAddress((void**)&pshn,  d_shn);
    cudaGetSymbolAddress((void**)&pwpre, d_wpre);
    cudaGetSymbolAddress((void**)&pwemb, d_wemb);
    cudaGetSymbolAddress((void**)&pwg1,  d_wg1);
    cudaGetSymbolAddress((void**)&pwgc,  d_wgc);
    cudaGetSymbolAddress((void**)&pwg2,  d_wg2);
    cudaGetSymbolAddress((void**)&pwwhp, d_wwhp);
    __half* pxH  = (__half*)px;
    __half* psH  = (__half*)ps;
    __half* pyH  = (__half*)py;
    __half* pzH  = (__half*)pz;
    __half* phsH = (__half*)phs;

    const int TPB = 256;
    const int eBlocks = (EE + TPB - 1) / TPB;
    const int gB = (NN + TM - 1) / TM;       // 391
    const int aggB = (NN * 32 + TPB - 1) / TPB;

    // ---- fused prep (conversions, transposes, zeroing) ----
    prep_all_kernel<<<PB_TOTAL, TPB>>>(x_in, s_in, pre_w, emb_w, gin_w1, gcn_w,
                                       gin_w2, whp_w, pxh, pshn, pwpre, pwemb,
                                       pwg1, pwgc, pwg2, pwwhp, pdegc, pcur, pg);

    // ---- CSR build ----
    count_deg_kernel<<<eBlocks, TPB>>>(ei, pdegc);
    scan_deg_kernel<<<1, 1024>>>(pdegc, prow, pdinv);
    fill_csr_kernel<<<eBlocks, TPB>>>(ei, prow, pcur, pcol);

    // ---- pre + emb fused ----
    GemmP Ppre = { pxh, FIN, nullptr, 0, pwpre, pre_b, nullptr, nullptr, pxH, NN, 0, 1 };
    GemmP Pemb = { pshn, NSE, nullptr, 0, pwemb, emb_b, nullptr, nullptr, psH, NN, 0, 1 };
    h_gemm2<<<2 * gB, 256>>>(Ppre, Pemb, gB);

    for (int i = 0; i < LL; i++) {
        GemmP Py  = { pxH, HH, psH, HH, pwg1 + (size_t)i * 128 * 256,
                      nullptr, nullptr, nullptr, pyH, NN, 0, 1 };
        GemmP Phs = { psH, HH, nullptr, 0, pwgc + (size_t)i * 128 * 128,
                      nullptr, pdinv, nullptr, phsH, NN, 0, 1 };
        h_gemm2<<<2 * gB, 256>>>(Py, Phs, gB);

        agg_both_kernel<<<2 * aggB, TPB>>>(pyH, phsH, pdinv, pcol, prow,
                                           gin_b1 + (size_t)i * HH,
                                           gcn_b + (size_t)i * HH,
                                           pzH, psH, aggB);

        GemmP Pw2 = { pzH, HH, nullptr, 0, pwg2 + (size_t)i * 128 * 128,
                      gin_b2 + (size_t)i * HH, nullptr, nullptr, pxH, NN, 1, 1 };
        h_gemm1<<<gB, 256>>>(Pw2);
    }

    // whp GEMM with fused global-add-pool (atomicAdd into pg; pg zeroed in prep)
    GemmP Pwhp = { pxH, HH, psH, HH, pwwhp, whp_b, nullptr, batch, pg, NN, 0, 0 };
    h_gemm1<<<gB, 256>>>(Pwhp);

    // fused post + readout
    post_readout_kernel<<<GG, HH>>>(pg, post_w, post_b, ro_w, ro_b, out);
}

// round 16
// speedup vs baseline: 2.1738x; 1.0028x over previous
#include <cuda_runtime.h>
#include <cuda_bf16.h>
#include <cuda_fp16.h>
#include <math.h>
#include <stdint.h>

// Problem constants (fixed by the dataset)
#define NN 50000
#define EE 800000
#define HH 128
#define FIN 128
#define NSE 16
#define LL 3
#define CC 10
#define GG 256

// ---------------- scratch (static __device__ — no allocs allowed) ----------
__device__ float d_x [NN * HH];
__device__ float d_s [NN * HH];
__device__ float d_y [NN * HH];
__device__ float d_z [NN * HH];
__device__ float d_hs[NN * HH];
__device__ float d_g [GG * HH];
__device__ float d_dinv[NN];
__device__ int   d_degc[NN];
__device__ int   d_rowptr[NN + 1];
__device__ int   d_cursor[NN];
__device__ int   d_col[EE];
// fp16 converted inputs + weights (transposed [n][k])
__device__ __half d_xh [NN * FIN];
__device__ __half d_shn[NN * NSE];
__device__ __half d_wpre[128 * 128];
__device__ __half d_wemb[128 * 16];
__device__ __half d_wg1 [3 * 128 * 256];
__device__ __half d_wgc [3 * 128 * 128];
__device__ __half d_wg2 [3 * 128 * 128];
__device__ __half d_wwhp[128 * 256];

#define EBLK ((EE + 255) / 256)   // 3125

// ---------------- fused prep kernel (+ degree count) ------------------------
// degc/cursor are zeroed by cudaMemsetAsync BEFORE this launch.
#define PB_F2HX 6250   // 1,600,000 float4
#define PB_F2HS 782
#define PB_WPRE 64
#define PB_WEMB 8
#define PB_WG1  384
#define PB_WGC  192
#define PB_WG2  192
#define PB_WWHP 128
#define PB_ZPG  128
#define PB_CNT  EBLK
#define PB_TOTAL (PB_F2HX+PB_F2HS+PB_WPRE+PB_WEMB+PB_WG1+PB_WGC+PB_WG2+PB_WWHP+PB_ZPG+PB_CNT)

__device__ __forceinline__ void f2h_job(const float* src, __half* dst, int n4,
                                        int blk, int tid) {
    int i = blk * 256 + tid;
    if (i < n4) {
        float4 v = ((const float4*)src)[i];
        __half2 h0 = __floats2half2_rn(v.x, v.y);
        __half2 h1 = __floats2half2_rn(v.z, v.w);
        uint2 p; p.x = *(uint32_t*)&h0; p.y = *(uint32_t*)&h1;
        ((uint2*)dst)[i] = p;
    }
}
__device__ __forceinline__ void wt_job(const float* src, __half* dst, int K, int total,
                                       int blk, int tid) {
    int i = blk * 256 + tid;
    if (i < total) {
        int n = i & 127;
        int k = (i >> 7) % K;
        int m = i / (K * 128);
        dst[(size_t)m * 128 * K + (size_t)n * K + k] = __float2half(src[i]);
    }
}

__global__ __launch_bounds__(256)
void prep_all_kernel(const float* x_in, const float* s_in,
                     const float* pre_w, const float* emb_w,
                     const float* gin_w1, const float* gcn_w,
                     const float* gin_w2, const float* whp_w,
                     __half* xh, __half* shn,
                     __half* wpre, __half* wemb, __half* wg1,
                     __half* wgc, __half* wg2, __half* wwhp,
                     float* g, const int* ei, int* degc) {
    int b = blockIdx.x;
    int tid = threadIdx.x;
    if (b < PB_F2HX) { f2h_job(x_in, xh, NN * FIN / 4, b, tid); return; }
    b -= PB_F2HX;
    if (b < PB_F2HS) { f2h_job(s_in, shn, NN * NSE / 4, b, tid); return; }
    b -= PB_F2HS;
    if (b < PB_WPRE) { wt_job(pre_w, wpre, 128, 128 * 128, b, tid); return; }
    b -= PB_WPRE;
    if (b < PB_WEMB) { wt_job(emb_w, wemb, 16, 16 * 128, b, tid); return; }
    b -= PB_WEMB;
    if (b < PB_WG1)  { wt_job(gin_w1, wg1, 256, 3 * 256 * 128, b, tid); return; }
    b -= PB_WG1;
    if (b < PB_WGC)  { wt_job(gcn_w, wgc, 128, 3 * 128 * 128, b, tid); return; }
    b -= PB_WGC;
    if (b < PB_WG2)  { wt_job(gin_w2, wg2, 128, 3 * 128 * 128, b, tid); return; }
    b -= PB_WG2;
    if (b < PB_WWHP) { wt_job(whp_w, wwhp, 256, 256 * 128, b, tid); return; }
    b -= PB_WWHP;
    if (b < PB_ZPG)  { int i = b * 256 + tid; if (i < GG * HH) g[i] = 0.0f; return; }
    b -= PB_ZPG;
    { int e = b * 256 + tid; if (e < EE) atomicAdd(&degc[ei[EE + e]], 1); }
}

// ---------------- CSR scan ---------------------------------------------------
__global__ void scan_deg_kernel(const int* __restrict__ degc,
                                int* __restrict__ rowptr,
                                float* __restrict__ dinv) {
    __shared__ int ssum[1024];
    int t = threadIdx.x;
    const int chunk = (NN + 1023) / 1024;
    int b0 = t * chunk;
    int b1 = b0 + chunk; if (b1 > NN) b1 = NN;
    int sum = 0;
    for (int i = b0; i < b1; i++) sum += degc[i];
    ssum[t] = sum;
    __syncthreads();
    for (int off = 1; off < 1024; off <<= 1) {
        int v = 0;
        if (t >= off) v = ssum[t - off];
        __syncthreads();
        if (t >= off) ssum[t] += v;
        __syncthreads();
    }
    int prefix = (t == 0) ? 0 : ssum[t - 1];
    for (int i = b0; i < b1; i++) {
        int d = degc[i];
        rowptr[i] = prefix;
        prefix += d;
        dinv[i] = rsqrtf((float)d + 1.0f);
    }
    if (t == 1023) rowptr[NN] = ssum[1023];
}

__device__ __forceinline__ void fill_job(const int* __restrict__ ei,
                                         const int* __restrict__ rowptr,
                                         int* __restrict__ cursor,
                                         int* __restrict__ col,
                                         int blk, int tid) {
    int e = blk * 256 + tid;
    if (e < EE) {
        int src = ei[e];
        int dst = ei[EE + e];
        int pos = atomicAdd(&cursor[dst], 1);
        col[rowptr[dst] + pos] = src;
    }
}

// ---------------- cp.async helpers ----------------------------------------
__device__ __forceinline__ uint32_t smem_u32(const void* p) {
    uint32_t a;
    asm("{ .reg .u64 t; cvta.to.shared.u64 t, %1; cvt.u32.u64 %0, t; }"
        : "=r"(a) : "l"(p));
    return a;
}
__device__ __forceinline__ void cp16(uint32_t dst, const void* src, int sz) {
    asm volatile("cp.async.cg.shared.global [%0], [%1], 16, %2;"
                 :: "r"(dst), "l"(src), "r"(sz));
}
#define CP_COMMIT() asm volatile("cp.async.commit_group;")
#define CP_WAIT(n)  asm volatile("cp.async.wait_group %0;" :: "n"(n))

__device__ __forceinline__ void mma_f16(float* c, const uint32_t* a, const uint32_t* b) {
    asm volatile("mma.sync.aligned.m16n8k16.row.col.f32.f16.f16.f32 "
        "{%0,%1,%2,%3}, {%4,%5,%6,%7}, {%8,%9}, {%0,%1,%2,%3};"
        : "+f"(c[0]), "+f"(c[1]), "+f"(c[2]), "+f"(c[3])
        : "r"(a[0]), "r"(a[1]), "r"(a[2]), "r"(a[3]), "r"(b[0]), "r"(b[1]));
}

// ---------------- GEMM params + core ---------------------------------------
#define TM 128
#define TN 128
#define TKK 16
#define RPAD 24
#define NS 3

struct GemmP {
    const __half* A1; int K1;
    const __half* A2; int K2;
    const __half* Wt;
    const float* bias;
    const float* rowscale;
    const int* batchp;       // if non-null: pool mode, atomicAdd into C[batch[r]*128+col]
    void* C; int M; int relu; int outHalf;
};

__device__ __forceinline__ void gemm_core(
    const GemmP& P, int blk,
    __half (*As)[TM][RPAD], __half (*Bs)[TN][RPAD]) {
    const int tid  = threadIdx.x;
    const int wid  = tid >> 5;
    const int lane = tid & 31;
    const int g    = lane >> 2;
    const int t    = lane & 3;
    const int wm   = wid & 3;
    const int wn   = wid >> 2;
    const int row0 = blk * TM;
    const int Ktot = P.K1 + P.K2;
    const int nb   = Ktot / TKK;

    float acc[2][8][4];
#pragma unroll
    for (int mi = 0; mi < 2; mi++)
#pragma unroll
        for (int ni = 0; ni < 8; ni++)
#pragma unroll
            for (int q = 0; q < 4; q++) acc[mi][ni][q] = 0.0f;

    const int r  = tid >> 1;
    const int ch = (tid & 1) * 8;
    const int grow = row0 + r;

    auto issue = [&](int kb) {
        int st = kb % NS;
        int kg = kb * TKK + ch;
        const __half* sa;
        if (kg < P.K1) sa = P.A1 + (size_t)grow * P.K1 + kg;
        else           sa = P.A2 + (size_t)grow * P.K2 + (kg - P.K1);
        cp16(smem_u32(&As[st][r][ch]), sa, (grow < P.M) ? 16 : 0);
        cp16(smem_u32(&Bs[st][r][ch]), P.Wt + (size_t)r * Ktot + kg, 16);
    };

#pragma unroll
    for (int s = 0; s < NS - 1; s++) {
        if (s < nb) issue(s);
        CP_COMMIT();
    }

    for (int kb = 0; kb < nb; kb++) {
        CP_WAIT(NS - 2);
        __syncthreads();
        if (kb + NS - 1 < nb) issue(kb + NS - 1);
        CP_COMMIT();

        const int cur = kb % NS;
        uint32_t af[2][4];
#pragma unroll
        for (int mi = 0; mi < 2; mi++) {
            int mb = wm * 32 + mi * 16;
            af[mi][0] = *(const uint32_t*)&As[cur][mb + g    ][2 * t    ];
            af[mi][1] = *(const uint32_t*)&As[cur][mb + g + 8][2 * t    ];
            af[mi][2] = *(const uint32_t*)&As[cur][mb + g    ][2 * t + 8];
            af[mi][3] = *(const uint32_t*)&As[cur][mb + g + 8][2 * t + 8];
        }
        uint32_t bf[8][2];
#pragma unroll
        for (int ni = 0; ni < 8; ni++) {
            int nbase = wn * 64 + ni * 8 + g;
            bf[ni][0] = *(const uint32_t*)&Bs[cur][nbase][2 * t    ];
            bf[ni][1] = *(const uint32_t*)&Bs[cur][nbase][2 * t + 8];
        }
#pragma unroll
        for (int mi = 0; mi < 2; mi++)
#pragma unroll
            for (int ni = 0; ni < 8; ni++)
                mma_f16(acc[mi][ni], af[mi], bf[ni]);
    }

    float* Cf = (float*)P.C;
    __half* Chh = (__half*)P.C;
#pragma unroll
    for (int mi = 0; mi < 2; mi++) {
        int rbase = row0 + wm * 32 + mi * 16 + g;
        float rs0 = 1.f, rs1 = 1.f;
        if (P.rowscale) {
            if (rbase < P.M)     rs0 = P.rowscale[rbase];
            if (rbase + 8 < P.M) rs1 = P.rowscale[rbase + 8];
        }
#pragma unroll
        for (int ni = 0; ni < 8; ni++) {
            int colb = wn * 64 + ni * 8 + 2 * t;
            float b0 = P.bias ? P.bias[colb]     : 0.f;
            float b1 = P.bias ? P.bias[colb + 1] : 0.f;
            float v0 = acc[mi][ni][0] * rs0 + b0;
            float v1 = acc[mi][ni][1] * rs0 + b1;
            float v2 = acc[mi][ni][2] * rs1 + b0;
            float v3 = acc[mi][ni][3] * rs1 + b1;
            if (P.relu) {
                v0 = fmaxf(v0, 0.f); v1 = fmaxf(v1, 0.f);
                v2 = fmaxf(v2, 0.f); v3 = fmaxf(v3, 0.f);
            }
            if (P.batchp) {
                if (rbase < P.M) {
                    int gi = P.batchp[rbase];
                    atomicAdd(&Cf[gi * 128 + colb],     v0);
                    atomicAdd(&Cf[gi * 128 + colb + 1], v1);
                }
                if (rbase + 8 < P.M) {
                    int gi = P.batchp[rbase + 8];
                    atomicAdd(&Cf[gi * 128 + colb],     v2);
                    atomicAdd(&Cf[gi * 128 + colb + 1], v3);
                }
            } else if (P.outHalf) {
                if (rbase < P.M)
                    *(__half2*)(Chh + (size_t)rbase * TN + colb) = __floats2half2_rn(v0, v1);
                if (rbase + 8 < P.M)
                    *(__half2*)(Chh + (size_t)(rbase + 8) * TN + colb) = __floats2half2_rn(v2, v3);
            } else {
                if (rbase < P.M)
                    *(float2*)(Cf + (size_t)rbase * TN + colb) = make_float2(v0, v1);
                if (rbase + 8 < P.M)
                    *(float2*)(Cf + (size_t)(rbase + 8) * TN + colb) = make_float2(v2, v3);
            }
        }
    }
}

__global__ __launch_bounds__(256, 2)
void h_gemm1(GemmP P0) {
    __shared__ __half As[NS][TM][RPAD];
    __shared__ __half Bs[NS][TN][RPAD];
    gemm_core(P0, blockIdx.x, As, Bs);
}
__global__ __launch_bounds__(256, 2)
void h_gemm2(GemmP P0, GemmP P1, int nb0) {
    __shared__ __half As[NS][TM][RPAD];
    __shared__ __half Bs[NS][TN][RPAD];
    if ((int)blockIdx.x < nb0) gemm_core(P0, blockIdx.x, As, Bs);
    else                       gemm_core(P1, blockIdx.x - nb0, As, Bs);
}
// two GEMMs + CSR fill fused: [0,nb0) P0, [nb0,2nb0) P1, rest fill
__global__ __launch_bounds__(256, 2)
void h_gemm2_fill(GemmP P0, GemmP P1, int nb0,
                  const int* ei, const int* rowptr, int* cursor, int* col) {
    __shared__ __half As[NS][TM][RPAD];
    __shared__ __half Bs[NS][TN][RPAD];
    int b = blockIdx.x;
    if (b < nb0)          gemm_core(P0, b, As, Bs);
    else if (b < 2 * nb0) gemm_core(P1, b - nb0, As, Bs);
    else                  fill_job(ei, rowptr, cursor, col, b - 2 * nb0, threadIdx.x);
}

// ---------------- aggregation cores ----------------------------------------
__device__ __forceinline__ void gin_core(const __half* __restrict__ y,
                                         const int* __restrict__ col,
                                         const int* __restrict__ rowptr,
                                         const float* __restrict__ b1,
                                         __half* __restrict__ z,
                                         int node, int lane) {
    const uint2* yv = (const uint2*)y;
    float ax, ay, az, aw;
    {
        uint2 v = yv[(size_t)node * 32 + lane];
        float2 p0 = __half22float2(*(const __half2*)&v.x);
        float2 p1 = __half22float2(*(const __half2*)&v.y);
        ax = p0.x; ay = p0.y; az = p1.x; aw = p1.y;
    }
    int b = rowptr[node], e = rowptr[node + 1];
    int j = b;
    for (; j + 8 <= e; j += 8) {
        int c0 = col[j],     c1 = col[j + 1], c2 = col[j + 2], c3 = col[j + 3];
        int c4 = col[j + 4], c5 = col[j + 5], c6 = col[j + 6], c7 = col[j + 7];
        uint2 v0 = yv[(size_t)c0 * 32 + lane];
        uint2 v1 = yv[(size_t)c1 * 32 + lane];
        uint2 v2 = yv[(size_t)c2 * 32 + lane];
        uint2 v3 = yv[(size_t)c3 * 32 + lane];
        uint2 v4 = yv[(size_t)c4 * 32 + lane];
        uint2 v5 = yv[(size_t)c5 * 32 + lane];
        uint2 v6 = yv[(size_t)c6 * 32 + lane];
        uint2 v7 = yv[(size_t)c7 * 32 + lane];
        __half2 p0 = __hadd2(__hadd2(*(__half2*)&v0.x, *(__half2*)&v1.x),
                             __hadd2(*(__half2*)&v2.x, *(__half2*)&v3.x));
        __half2 p1 = __hadd2(__hadd2(*(__half2*)&v4.x, *(__half2*)&v5.x),
                             __hadd2(*(__half2*)&v6.x, *(__half2*)&v7.x));
        __half2 q0 = __hadd2(__hadd2(*(__half2*)&v0.y, *(__half2*)&v1.y),
                             __hadd2(*(__half2*)&v2.y, *(__half2*)&v3.y));
        __half2 q1 = __hadd2(__hadd2(*(__half2*)&v4.y, *(__half2*)&v5.y),
                             __hadd2(*(__half2*)&v6.y, *(__half2*)&v7.y));
        float2 f0 = __half22float2(p0);
        float2 f1 = __half22float2(p1);
        float2 g0 = __half22float2(q0);
        float2 g1 = __half22float2(q1);
        ax += f0.x + f1.x; ay += f0.y + f1.y;
        az += g0.x + g1.x; aw += g0.y + g1.y;
    }
    for (; j < e; j++) {
        uint2 v = yv[(size_t)col[j] * 32 + lane];
        float2 p0 = __half22float2(*(const __half2*)&v.x);
        float2 p1 = __half22float2(*(const __half2*)&v.y);
        ax += p0.x; ay += p0.y; az += p1.x; aw += p1.y;
    }
    float4 bb = ((const float4*)b1)[lane];
    __half2 o0 = __floats2half2_rn(fmaxf(ax + bb.x, 0.f), fmaxf(ay + bb.y, 0.f));
    __half2 o1 = __floats2half2_rn(fmaxf(az + bb.z, 0.f), fmaxf(aw + bb.w, 0.f));
    uint2 p; p.x = *(uint32_t*)&o0; p.y = *(uint32_t*)&o1;
    ((uint2*)z)[(size_t)node * 32 + lane] = p;
}

__device__ __forceinline__ void gcn_core(const __half* __restrict__ hsp,
                                         const float* __restrict__ dinv,
                                         const int* __restrict__ col,
                                         const int* __restrict__ rowptr,
                                         const float* __restrict__ bias,
                                         __half* __restrict__ s,
                                         int node, int lane) {
    const uint2* hv = (const uint2*)hsp;
    float ax, ay, az, aw;
    {
        uint2 v = hv[(size_t)node * 32 + lane];
        float2 p0 = __half22float2(*(const __half2*)&v.x);
        float2 p1 = __half22float2(*(const __half2*)&v.y);
        ax = p0.x; ay = p0.y; az = p1.x; aw = p1.y;
    }
    int b = rowptr[node], e = rowptr[node + 1];
    int j = b;
    for (; j + 8 <= e; j += 8) {
        int c0 = col[j],     c1 = col[j + 1], c2 = col[j + 2], c3 = col[j + 3];
        int c4 = col[j + 4], c5 = col[j + 5], c6 = col[j + 6], c7 = col[j + 7];
        uint2 v0 = hv[(size_t)c0 * 32 + lane];
        uint2 v1 = hv[(size_t)c1 * 32 + lane];
        uint2 v2 = hv[(size_t)c2 * 32 + lane];
        uint2 v3 = hv[(size_t)c3 * 32 + lane];
        uint2 v4 = hv[(size_t)c4 * 32 + lane];
        uint2 v5 = hv[(size_t)c5 * 32 + lane];
        uint2 v6 = hv[(size_t)c6 * 32 + lane];
        uint2 v7 = hv[(size_t)c7 * 32 + lane];
        __half2 p0 = __hadd2(__hadd2(*(__half2*)&v0.x, *(__half2*)&v1.x),
                             __hadd2(*(__half2*)&v2.x, *(__half2*)&v3.x));
        __half2 p1 = __hadd2(__hadd2(*(__half2*)&v4.x, *(__half2*)&v5.x),
                             __hadd2(*(__half2*)&v6.x, *(__half2*)&v7.x));
        __half2 q0 = __hadd2(__hadd2(*(__half2*)&v0.y, *(__half2*)&v1.y),
                             __hadd2(*(__half2*)&v2.y, *(__half2*)&v3.y));
        __half2 q1 = __hadd2(__hadd2(*(__half2*)&v4.y, *(__half2*)&v5.y),
                             __hadd2(*(__half2*)&v6.y, *(__half2*)&v7.y));
        float2 f0 = __half22float2(p0);
        float2 f1 = __half22float2(p1);
        float2 g0 = __half22float2(q0);
        float2 g1 = __half22float2(q1);
        ax += f0.x + f1.x; ay += f0.y + f1.y;
        az += g0.x + g1.x; aw += g0.y + g1.y;
    }
    for (; j < e; j++) {
        uint2 v = hv[(size_t)col[j] * 32 + lane];
        float2 p0 = __half22float2(*(const __half2*)&v.x);
        float2 p1 = __half22float2(*(const __half2*)&v.y);
        ax += p0.x; ay += p0.y; az += p1.x; aw += p1.y;
    }
    float di = dinv[node];
    float4 bb = ((const float4*)bias)[lane];
    __half2 o0 = __floats2half2_rn(tanhf(di * ax + bb.x), tanhf(di * ay + bb.y));
    __half2 o1 = __floats2half2_rn(tanhf(di * az + bb.z), tanhf(di * aw + bb.w));
    uint2 p; p.x = *(uint32_t*)&o0; p.y = *(uint32_t*)&o1;
    ((uint2*)s)[(size_t)node * 32 + lane] = p;
}

__global__ __launch_bounds__(256)
void agg_both_kernel(const __half* __restrict__ y,
                     const __half* __restrict__ hsp,
                     const float* __restrict__ dinv,
                     const int* __restrict__ col,
                     const int* __restrict__ rowptr,
                     const float* __restrict__ b1,
                     const float* __restrict__ gcn_b,
                     __half* __restrict__ z,
                     __half* __restrict__ s,
                     int nb0) {
    int lane = threadIdx.x & 31;
    if ((int)blockIdx.x < nb0) {
        int node = (blockIdx.x * blockDim.x + threadIdx.x) >> 5;
        if (node < NN) gin_core(y, col, rowptr, b1, z, node, lane);
    } else {
        int node = ((blockIdx.x - nb0) * blockDim.x + threadIdx.x) >> 5;
        if (node < NN) gcn_core(hsp, dinv, col, rowptr, gcn_b, s, node, lane);
    }
}

// ---------------- fused post + readout -------------------------------------
__global__ __launch_bounds__(128)
void post_readout_kernel(const float* __restrict__ g,
                         const float* __restrict__ post_w,
                         const float* __restrict__ post_b,
                         const float* __restrict__ ro_w,
                         const float* __restrict__ ro_b,
                         float* __restrict__ out) {
    int r = blockIdx.x;
    int c = threadIdx.x;
    __shared__ float row[HH];
    __shared__ float gp[HH];
    __shared__ float logit[CC];
    row[c] = g[(size_t)r * HH + c];
    __syncthreads();
    float acc = post_b[c];
#pragma unroll 8
    for (int k = 0; k < HH; k++) acc = fmaf(row[k], post_w[(size_t)k * HH + c], acc);
    gp[c] = fmaxf(acc, 0.0f);
    __syncthreads();
    if (c < CC) {
        float l = ro_b[c];
        for (int k = 0; k < HH; k++) l = fmaf(gp[k], ro_w[(size_t)k * CC + c], l);
        logit[c] = l;
    }
    __syncthreads();
    if (c < CC) {
        float m = logit[0];
#pragma unroll
        for (int q = 1; q < CC; q++) m = fmaxf(m, logit[q]);
        float sum = 0.0f;
#pragma unroll
        for (int q = 0; q < CC; q++) sum += expf(logit[q] - m);
        float lse = m + logf(sum);
        out[(size_t)r * CC + c] = logit[c] - lse;
    }
}

// ---------------- driver ---------------------------------------------------
extern "C" void kernel_launch(void* const* d_in, const int* in_sizes, int n_in,
                              void* d_out, int out_size) {
    const float* x_in   = (const float*)d_in[0];
    const float* s_in   = (const float*)d_in[1];
    const int*   ei     = (const int*)d_in[2];
    const int*   batch  = (const int*)d_in[3];
    const float* pre_w  = (const float*)d_in[4];
    const float* pre_b  = (const float*)d_in[5];
    const float* emb_w  = (const float*)d_in[6];
    const float* emb_b  = (const float*)d_in[7];
    const float* gin_w1 = (const float*)d_in[8];
    const float* gin_b1 = (const float*)d_in[9];
    const float* gin_w2 = (const float*)d_in[10];
    const float* gin_b2 = (const float*)d_in[11];
    const float* gcn_w  = (const float*)d_in[12];
    const float* gcn_b  = (const float*)d_in[13];
    const float* whp_w  = (const float*)d_in[14];
    const float* whp_b  = (const float*)d_in[15];
    const float* post_w = (const float*)d_in[16];
    const float* post_b = (const float*)d_in[17];
    const float* ro_w   = (const float*)d_in[18];
    const float* ro_b   = (const float*)d_in[19];
    float* out = (float*)d_out;

    float *px, *ps, *py, *pz, *phs, *pg, *pdinv;
    int *pdegc, *prow, *pcur, *pcol;
    __half *pxh, *pshn, *pwpre, *pwemb, *pwg1, *pwgc, *pwg2, *pwwhp;
    cudaGetSymbolAddress((void**)&px,    d_x);
    cudaGetSymbolAddress((void**)&ps,    d_s);
    cudaGetSymbolAddress((void**)&py,    d_y);
    cudaGetSymbolAddress((void**)&pz,    d_z);
    cudaGetSymbolAddress((void**)&phs,   d_hs);
    cudaGetSymbolAddress((void**)&pg,    d_g);
    cudaGetSymbolAddress((void**)&pdinv, d_dinv);
    cudaGetSymbolAddress((void**)&pdegc, d_degc);
    cudaGetSymbolAddress((void**)&prow,  d_rowptr);
    cudaGetSymbolAddress((void**)&pcur,  d_cursor);
    cudaGetSymbolAddress((void**)&pcol,  d_col);
    cudaGetSymbolAddress((void**)&pxh,   d_xh);
    cudaGetSymbolAddress((void**)&pshn,  d_shn);
    cudaGetSymbolAddress((void**)&pwpre, d_wpre);
    cudaGetSymbolAddress((void**)&pwemb, d_wemb);
    cudaGetSymbolAddress((void**)&pwg1,  d_wg1);
    cudaGetSymbolAddress((void**)&pwgc,  d_wgc);
    cudaGetSymbolAddress((void**)&pwg2,  d_wg2);
    cudaGetSymbolAddress((void**)&pwwhp, d_wwhp);
    __half* pxH  = (__half*)px;
    __half* psH  = (__half*)ps;
    __half* pyH  = (__half*)py;
    __half* pzH  = (__half*)pz;
    __half* phsH = (__half*)phs;

    const int TPB = 256;
    const int gB = (NN + TM - 1) / TM;       // 391
    const int aggB = (NN * 32 + TPB - 1) / TPB;

    // zero degc/cursor (needed before fused count / fill)
    cudaMemsetAsync(pdegc, 0, NN * sizeof(int), 0);
    cudaMemsetAsync(pcur,  0, NN * sizeof(int), 0);

    // fused prep: conversions, transposes, zero g, degree count
    prep_all_kernel<<<PB_TOTAL, TPB>>>(x_in, s_in, pre_w, emb_w, gin_w1, gcn_w,
                                       gin_w2, whp_w, pxh, pshn, pwpre, pwemb,
                                       pwg1, pwgc, pwg2, pwwhp, pg, ei, pdegc);

    // scan (rowptr + dinv)
    scan_deg_kernel<<<1, 1024>>>(pdegc, prow, pdinv);

    // pre + emb GEMMs fused with CSR fill
    GemmP Ppre = { pxh, FIN, nullptr, 0, pwpre, pre_b, nullptr, nullptr, pxH, NN, 0, 1 };
    GemmP Pemb = { pshn, NSE, nullptr, 0, pwemb, emb_b, nullptr, nullptr, psH, NN, 0, 1 };
    h_gemm2_fill<<<2 * gB + EBLK, 256>>>(Ppre, Pemb, gB, ei, prow, pcur, pcol);

    for (int i = 0; i < LL; i++) {
        GemmP Py  = { pxH, HH, psH, HH, pwg1 + (size_t)i * 128 * 256,
                      nullptr, nullptr, nullptr, pyH, NN, 0, 1 };
        GemmP Phs = { psH, HH, nullptr, 0, pwgc + (size_t)i * 128 * 128,
                      nullptr, pdinv, nullptr, phsH, NN, 0, 1 };
        h_gemm2<<<2 * gB, 256>>>(Py, Phs, gB);

        agg_both_kernel<<<2 * aggB, TPB>>>(pyH, phsH, pdinv, pcol, prow,
                                           gin_b1 + (size_t)i * HH,
                                           gcn_b + (size_t)i * HH,
                                           pzH, psH, aggB);

        GemmP Pw2 = { pzH, HH, nullptr, 0, pwg2 + (size_t)i * 128 * 128,
                      gin_b2 + (size_t)i * HH, nullptr, nullptr, pxH, NN, 1, 1 };
        h_gemm1<<<gB, 256>>>(Pw2);
    }

    // whp GEMM with fused global-add-pool
    GemmP Pwhp = { pxH, HH, psH, HH, pwwhp, whp_b, nullptr, batch, pg, NN, 0, 0 };
    h_gemm1<<<gB, 256>>>(Pwhp);

    // fused post + readout
    post_readout_kernel<<<GG, HH>>>(pg, post_w, post_b, ro_w, ro_b, out);
}

// round 17
// speedup vs baseline: 2.2528x; 1.0363x over previous
#include <cuda_runtime.h>
#include <cuda_bf16.h>
#include <cuda_fp16.h>
#include <math.h>
#include <stdint.h>

// Problem constants (fixed by the dataset)
#define NN 50000
#define EE 800000
#define HH 128
#define FIN 128
#define NSE 16
#define LL 3
#define CC 10
#define GG 256

// ---------------- scratch (static __device__ — no allocs allowed) ----------
__device__ float d_x [NN * HH];
__device__ float d_s [NN * HH];
__device__ float d_y [NN * HH];
__device__ float d_z [NN * HH];
__device__ float d_hs[NN * HH];
__device__ float d_g [GG * HH];
__device__ float d_dinv[NN];
__device__ int   d_degc[NN];
__device__ int   d_rowptr[NN + 1];
__device__ int   d_cursor[NN];
__device__ int   d_col[EE];
// fp16 converted inputs + weights (transposed [n][k])
__device__ __half d_xh [NN * FIN];
__device__ __half d_shn[NN * NSE];
__device__ __half d_wpre[128 * 128];
__device__ __half d_wemb[128 * 16];
__device__ __half d_wg1 [3 * 128 * 256];
__device__ __half d_wgc [3 * 128 * 128];
__device__ __half d_wg2 [3 * 128 * 128];
__device__ __half d_wwhp[128 * 256];

#define EBLK ((EE + 255) / 256)   // 3125

// ---------------- fused prep kernel (+ degree count) ------------------------
#define PB_F2HX 6250
#define PB_F2HS 782
#define PB_WPRE 64
#define PB_WEMB 8
#define PB_WG1  384
#define PB_WGC  192
#define PB_WG2  192
#define PB_WWHP 128
#define PB_ZPG  128
#define PB_CNT  EBLK
#define PB_TOTAL (PB_F2HX+PB_F2HS+PB_WPRE+PB_WEMB+PB_WG1+PB_WGC+PB_WG2+PB_WWHP+PB_ZPG+PB_CNT)

__device__ __forceinline__ void f2h_job(const float* src, __half* dst, int n4,
                                        int blk, int tid) {
    int i = blk * 256 + tid;
    if (i < n4) {
        float4 v = ((const float4*)src)[i];
        __half2 h0 = __floats2half2_rn(v.x, v.y);
        __half2 h1 = __floats2half2_rn(v.z, v.w);
        uint2 p; p.x = *(uint32_t*)&h0; p.y = *(uint32_t*)&h1;
        ((uint2*)dst)[i] = p;
    }
}
__device__ __forceinline__ void wt_job(const float* src, __half* dst, int K, int total,
                                       int blk, int tid) {
    int i = blk * 256 + tid;
    if (i < total) {
        int n = i & 127;
        int k = (i >> 7) % K;
        int m = i / (K * 128);
        dst[(size_t)m * 128 * K + (size_t)n * K + k] = __float2half(src[i]);
    }
}

__global__ __launch_bounds__(256)
void prep_all_kernel(const float* x_in, const float* s_in,
                     const float* pre_w, const float* emb_w,
                     const float* gin_w1, const float* gcn_w,
                     const float* gin_w2, const float* whp_w,
                     __half* xh, __half* shn,
                     __half* wpre, __half* wemb, __half* wg1,
                     __half* wgc, __half* wg2, __half* wwhp,
                     float* g, const int* ei, int* degc) {
    int b = blockIdx.x;
    int tid = threadIdx.x;
    if (b < PB_F2HX) { f2h_job(x_in, xh, NN * FIN / 4, b, tid); return; }
    b -= PB_F2HX;
    if (b < PB_F2HS) { f2h_job(s_in, shn, NN * NSE / 4, b, tid); return; }
    b -= PB_F2HS;
    if (b < PB_WPRE) { wt_job(pre_w, wpre, 128, 128 * 128, b, tid); return; }
    b -= PB_WPRE;
    if (b < PB_WEMB) { wt_job(emb_w, wemb, 16, 16 * 128, b, tid); return; }
    b -= PB_WEMB;
    if (b < PB_WG1)  { wt_job(gin_w1, wg1, 256, 3 * 256 * 128, b, tid); return; }
    b -= PB_WG1;
    if (b < PB_WGC)  { wt_job(gcn_w, wgc, 128, 3 * 128 * 128, b, tid); return; }
    b -= PB_WGC;
    if (b < PB_WG2)  { wt_job(gin_w2, wg2, 128, 3 * 128 * 128, b, tid); return; }
    b -= PB_WG2;
    if (b < PB_WWHP) { wt_job(whp_w, wwhp, 256, 256 * 128, b, tid); return; }
    b -= PB_WWHP;
    if (b < PB_ZPG)  { int i = b * 256 + tid; if (i < GG * HH) g[i] = 0.0f; return; }
    b -= PB_ZPG;
    { int e = b * 256 + tid; if (e < EE) atomicAdd(&degc[ei[EE + e]], 1); }
}

// ---------------- CSR scan ---------------------------------------------------
__global__ void scan_deg_kernel(const int* __restrict__ degc,
                                int* __restrict__ rowptr,
                                float* __restrict__ dinv) {
    __shared__ int ssum[1024];
    int t = threadIdx.x;
    const int chunk = (NN + 1023) / 1024;
    int b0 = t * chunk;
    int b1 = b0 + chunk; if (b1 > NN) b1 = NN;
    int sum = 0;
    for (int i = b0; i < b1; i++) sum += degc[i];
    ssum[t] = sum;
    __syncthreads();
    for (int off = 1; off < 1024; off <<= 1) {
        int v = 0;
        if (t >= off) v = ssum[t - off];
        __syncthreads();
        if (t >= off) ssum[t] += v;
        __syncthreads();
    }
    int prefix = (t == 0) ? 0 : ssum[t - 1];
    for (int i = b0; i < b1; i++) {
        int d = degc[i];
        rowptr[i] = prefix;
        prefix += d;
        dinv[i] = rsqrtf((float)d + 1.0f);
    }
    if (t == 1023) rowptr[NN] = ssum[1023];
}

__device__ __forceinline__ void fill_job(const int* __restrict__ ei,
                                         const int* __restrict__ rowptr,
                                         int* __restrict__ cursor,
                                         int* __restrict__ col,
                                         int blk, int tid) {
    int e = blk * 256 + tid;
    if (e < EE) {
        int src = ei[e];
        int dst = ei[EE + e];
        int pos = atomicAdd(&cursor[dst], 1);
        col[rowptr[dst] + pos] = src;
    }
}

// ---------------- cp.async / ldmatrix helpers ------------------------------
__device__ __forceinline__ uint32_t smem_u32(const void* p) {
    uint32_t a;
    asm("{ .reg .u64 t; cvta.to.shared.u64 t, %1; cvt.u32.u64 %0, t; }"
        : "=r"(a) : "l"(p));
    return a;
}
__device__ __forceinline__ void cp16(uint32_t dst, const void* src, int sz) {
    asm volatile("cp.async.cg.shared.global [%0], [%1], 16, %2;"
                 :: "r"(dst), "l"(src), "r"(sz));
}
#define CP_COMMIT() asm volatile("cp.async.commit_group;")
#define CP_WAIT(n)  asm volatile("cp.async.wait_group %0;" :: "n"(n))

__device__ __forceinline__ void mma_f16(float* c, const uint32_t* a, const uint32_t* b) {
    asm volatile("mma.sync.aligned.m16n8k16.row.col.f32.f16.f16.f32 "
        "{%0,%1,%2,%3}, {%4,%5,%6,%7}, {%8,%9}, {%0,%1,%2,%3};"
        : "+f"(c[0]), "+f"(c[1]), "+f"(c[2]), "+f"(c[3])
        : "r"(a[0]), "r"(a[1]), "r"(a[2]), "r"(a[3]), "r"(b[0]), "r"(b[1]));
}
__device__ __forceinline__ void ldm_x4(uint32_t& r0, uint32_t& r1,
                                       uint32_t& r2, uint32_t& r3, uint32_t addr) {
    asm volatile("ldmatrix.sync.aligned.m8n8.x4.shared.b16 {%0,%1,%2,%3}, [%4];"
                 : "=r"(r0), "=r"(r1), "=r"(r2), "=r"(r3) : "r"(addr));
}

// ---------------- GEMM params + core ---------------------------------------
#define TM 128
#define TN 128
#define TKK 16
#define RPAD 24
#define NS 3

struct GemmP {
    const __half* A1; int K1;
    const __half* A2; int K2;
    const __half* Wt;
    const float* bias;
    const float* rowscale;
    const int* batchp;       // pool mode
    void* C; int M; int relu; int outHalf;
};

__device__ __forceinline__ void gemm_core(
    const GemmP& P, int blk,
    __half (*As)[TM][RPAD], __half (*Bs)[TN][RPAD]) {
    const int tid  = threadIdx.x;
    const int wid  = tid >> 5;
    const int lane = tid & 31;
    const int g    = lane >> 2;
    const int t    = lane & 3;
    const int wm   = wid & 3;
    const int wn   = wid >> 2;
    const int row0 = blk * TM;
    const int Ktot = P.K1 + P.K2;
    const int nb   = Ktot / TKK;

    float acc[2][8][4];
#pragma unroll
    for (int mi = 0; mi < 2; mi++)
#pragma unroll
        for (int ni = 0; ni < 8; ni++)
#pragma unroll
            for (int q = 0; q < 4; q++) acc[mi][ni][q] = 0.0f;

    const int r  = tid >> 1;
    const int ch = (tid & 1) * 8;
    const int grow = row0 + r;

    // ldmatrix addressing: sub-group (0..3), row-in-group (0..7)
    const int sub = lane >> 3;
    const int rin = lane & 7;
    const int aRowOff = (sub & 1) * 8 + rin;  // + mb
    const int aColOff = (sub >> 1) * 8;
    const int bRowOff = (sub >> 1) * 8 + rin; // + nbase (pair)
    const int bColOff = (sub & 1) * 8;

    auto issue = [&](int kb) {
        int st = kb % NS;
        int kg = kb * TKK + ch;
        const __half* sa;
        if (kg < P.K1) sa = P.A1 + (size_t)grow * P.K1 + kg;
        else           sa = P.A2 + (size_t)grow * P.K2 + (kg - P.K1);
        cp16(smem_u32(&As[st][r][ch]), sa, (grow < P.M) ? 16 : 0);
        cp16(smem_u32(&Bs[st][r][ch]), P.Wt + (size_t)r * Ktot + kg, 16);
    };

#pragma unroll
    for (int s = 0; s < NS - 1; s++) {
        if (s < nb) issue(s);
        CP_COMMIT();
    }

    for (int kb = 0; kb < nb; kb++) {
        CP_WAIT(NS - 2);
        __syncthreads();
        if (kb + NS - 1 < nb) issue(kb + NS - 1);
        CP_COMMIT();

        const int cur = kb % NS;
        uint32_t af[2][4];
#pragma unroll
        for (int mi = 0; mi < 2; mi++) {
            int arow = wm * 32 + mi * 16 + aRowOff;
            ldm_x4(af[mi][0], af[mi][1], af[mi][2], af[mi][3],
                   smem_u32(&As[cur][arow][aColOff]));
        }
        uint32_t bf[8][2];
#pragma unroll
        for (int p = 0; p < 4; p++) {
            int nrow = wn * 64 + p * 16 + bRowOff;
            ldm_x4(bf[2 * p][0], bf[2 * p][1], bf[2 * p + 1][0], bf[2 * p + 1][1],
                   smem_u32(&Bs[cur][nrow][bColOff]));
        }
#pragma unroll
        for (int mi = 0; mi < 2; mi++)
#pragma unroll
            for (int ni = 0; ni < 8; ni++)
                mma_f16(acc[mi][ni], af[mi], bf[ni]);
    }

    float* Cf = (float*)P.C;
    __half* Chh = (__half*)P.C;
#pragma unroll
    for (int mi = 0; mi < 2; mi++) {
        int rbase = row0 + wm * 32 + mi * 16 + g;
        float rs0 = 1.f, rs1 = 1.f;
        if (P.rowscale) {
            if (rbase < P.M)     rs0 = P.rowscale[rbase];
            if (rbase + 8 < P.M) rs1 = P.rowscale[rbase + 8];
        }
#pragma unroll
        for (int ni = 0; ni < 8; ni++) {
            int colb = wn * 64 + ni * 8 + 2 * t;
            float b0 = P.bias ? P.bias[colb]     : 0.f;
            float b1 = P.bias ? P.bias[colb + 1] : 0.f;
            float v0 = acc[mi][ni][0] * rs0 + b0;
            float v1 = acc[mi][ni][1] * rs0 + b1;
            float v2 = acc[mi][ni][2] * rs1 + b0;
            float v3 = acc[mi][ni][3] * rs1 + b1;
            if (P.relu) {
                v0 = fmaxf(v0, 0.f); v1 = fmaxf(v1, 0.f);
                v2 = fmaxf(v2, 0.f); v3 = fmaxf(v3, 0.f);
            }
            if (P.batchp) {
                if (rbase < P.M) {
                    int gi = P.batchp[rbase];
                    atomicAdd(&Cf[gi * 128 + colb],     v0);
                    atomicAdd(&Cf[gi * 128 + colb + 1], v1);
                }
                if (rbase + 8 < P.M) {
                    int gi = P.batchp[rbase + 8];
                    atomicAdd(&Cf[gi * 128 + colb],     v2);
                    atomicAdd(&Cf[gi * 128 + colb + 1], v3);
                }
            } else if (P.outHalf) {
                if (rbase < P.M)
                    *(__half2*)(Chh + (size_t)rbase * TN + colb) = __floats2half2_rn(v0, v1);
                if (rbase + 8 < P.M)
                    *(__half2*)(Chh + (size_t)(rbase + 8) * TN + colb) = __floats2half2_rn(v2, v3);
            } else {
                if (rbase < P.M)
                    *(float2*)(Cf + (size_t)rbase * TN + colb) = make_float2(v0, v1);
                if (rbase + 8 < P.M)
                    *(float2*)(Cf + (size_t)(rbase + 8) * TN + colb) = make_float2(v2, v3);
            }
        }
    }
}

__global__ __launch_bounds__(256, 2)
void h_gemm1(GemmP P0) {
    __shared__ __half As[NS][TM][RPAD];
    __shared__ __half Bs[NS][TN][RPAD];
    gemm_core(P0, blockIdx.x, As, Bs);
}
__global__ __launch_bounds__(256, 2)
void h_gemm2(GemmP P0, GemmP P1, int nb0) {
    __shared__ __half As[NS][TM][RPAD];
    __shared__ __half Bs[NS][TN][RPAD];
    if ((int)blockIdx.x < nb0) gemm_core(P0, blockIdx.x, As, Bs);
    else                       gemm_core(P1, blockIdx.x - nb0, As, Bs);
}
__global__ __launch_bounds__(256, 2)
void h_gemm2_fill(GemmP P0, GemmP P1, int nb0,
                  const int* ei, const int* rowptr, int* cursor, int* col) {
    __shared__ __half As[NS][TM][RPAD];
    __shared__ __half Bs[NS][TN][RPAD];
    int b = blockIdx.x;
    if (b < nb0)          gemm_core(P0, b, As, Bs);
    else if (b < 2 * nb0) gemm_core(P1, b - nb0, As, Bs);
    else                  fill_job(ei, rowptr, cursor, col, b - 2 * nb0, threadIdx.x);
}

// ---------------- aggregation cores ----------------------------------------
__device__ __forceinline__ void gin_core(const __half* __restrict__ y,
                                         const int* __restrict__ col,
                                         const int* __restrict__ rowptr,
                                         const float* __restrict__ b1,
                                         __half* __restrict__ z,
                                         int node, int lane) {
    const uint2* yv = (const uint2*)y;
    float ax, ay, az, aw;
    {
        uint2 v = yv[(size_t)node * 32 + lane];
        float2 p0 = __half22float2(*(const __half2*)&v.x);
        float2 p1 = __half22float2(*(const __half2*)&v.y);
        ax = p0.x; ay = p0.y; az = p1.x; aw = p1.y;
    }
    int b = rowptr[node], e = rowptr[node + 1];
    int j = b;
    for (; j + 8 <= e; j += 8) {
        int c0 = col[j],     c1 = col[j + 1], c2 = col[j + 2], c3 = col[j + 3];
        int c4 = col[j + 4], c5 = col[j + 5], c6 = col[j + 6], c7 = col[j + 7];
        uint2 v0 = yv[(size_t)c0 * 32 + lane];
        uint2 v1 = yv[(size_t)c1 * 32 + lane];
        uint2 v2 = yv[(size_t)c2 * 32 + lane];
        uint2 v3 = yv[(size_t)c3 * 32 + lane];
        uint2 v4 = yv[(size_t)c4 * 32 + lane];
        uint2 v5 = yv[(size_t)c5 * 32 + lane];
        uint2 v6 = yv[(size_t)c6 * 32 + lane];
        uint2 v7 = yv[(size_t)c7 * 32 + lane];
        __half2 p0 = __hadd2(__hadd2(*(__half2*)&v0.x, *(__half2*)&v1.x),
                             __hadd2(*(__half2*)&v2.x, *(__half2*)&v3.x));
        __half2 p1 = __hadd2(__hadd2(*(__half2*)&v4.x, *(__half2*)&v5.x),
                             __hadd2(*(__half2*)&v6.x, *(__half2*)&v7.x));
        __half2 q0 = __hadd2(__hadd2(*(__half2*)&v0.y, *(__half2*)&v1.y),
                             __hadd2(*(__half2*)&v2.y, *(__half2*)&v3.y));
        __half2 q1 = __hadd2(__hadd2(*(__half2*)&v4.y, *(__half2*)&v5.y),
                             __hadd2(*(__half2*)&v6.y, *(__half2*)&v7.y));
        float2 f0 = __half22float2(p0);
        float2 f1 = __half22float2(p1);
        float2 g0 = __half22float2(q0);
        float2 g1 = __half22float2(q1);
        ax += f0.x + f1.x; ay += f0.y + f1.y;
        az += g0.x + g1.x; aw += g0.y + g1.y;
    }
    for (; j < e; j++) {
        uint2 v = yv[(size_t)col[j] * 32 + lane];
        float2 p0 = __half22float2(*(const __half2*)&v.x);
        float2 p1 = __half22float2(*(const __half2*)&v.y);
        ax += p0.x; ay += p0.y; az += p1.x; aw += p1.y;
    }
    float4 bb = ((const float4*)b1)[lane];
    __half2 o0 = __floats2half2_rn(fmaxf(ax + bb.x, 0.f), fmaxf(ay + bb.y, 0.f));
    __half2 o1 = __floats2half2_rn(fmaxf(az + bb.z, 0.f), fmaxf(aw + bb.w, 0.f));
    uint2 p; p.x = *(uint32_t*)&o0; p.y = *(uint32_t*)&o1;
    ((uint2*)z)[(size_t)node * 32 + lane] = p;
}

__device__ __forceinline__ void gcn_core(const __half* __restrict__ hsp,
                                         const float* __restrict__ dinv,
                                         const int* __restrict__ col,
                                         const int* __restrict__ rowptr,
                                         const float* __restrict__ bias,
                                         __half* __restrict__ s,
                                         int node, int lane) {
    const uint2* hv = (const uint2*)hsp;
    float ax, ay, az, aw;
    {
        uint2 v = hv[(size_t)node * 32 + lane];
        float2 p0 = __half22float2(*(const __half2*)&v.x);
        float2 p1 = __half22float2(*(const __half2*)&v.y);
        ax = p0.x; ay = p0.y; az = p1.x; aw = p1.y;
    }
    int b = rowptr[node], e = rowptr[node + 1];
    int j = b;
    for (; j + 8 <= e; j += 8) {
        int c0 = col[j],     c1 = col[j + 1], c2 = col[j + 2], c3 = col[j + 3];
        int c4 = col[j + 4], c5 = col[j + 5], c6 = col[j + 6], c7 = col[j + 7];
        uint2 v0 = hv[(size_t)c0 * 32 + lane];
        uint2 v1 = hv[(size_t)c1 * 32 + lane];
        uint2 v2 = hv[(size_t)c2 * 32 + lane];
        uint2 v3 = hv[(size_t)c3 * 32 + lane];
        uint2 v4 = hv[(size_t)c4 * 32 + lane];
        uint2 v5 = hv[(size_t)c5 * 32 + lane];
        uint2 v6 = hv[(size_t)c6 * 32 + lane];
        uint2 v7 = hv[(size_t)c7 * 32 + lane];
        __half2 p0 = __hadd2(__hadd2(*(__half2*)&v0.x, *(__half2*)&v1.x),
                             __hadd2(*(__half2*)&v2.x, *(__half2*)&v3.x));
        __half2 p1 = __hadd2(__hadd2(*(__half2*)&v4.x, *(__half2*)&v5.x),
                             __hadd2(*(__half2*)&v6.x, *(__half2*)&v7.x));
        __half2 q0 = __hadd2(__hadd2(*(__half2*)&v0.y, *(__half2*)&v1.y),
                             __hadd2(*(__half2*)&v2.y, *(__half2*)&v3.y));
        __half2 q1 = __hadd2(__hadd2(*(__half2*)&v4.y, *(__half2*)&v5.y),
                             __hadd2(*(__half2*)&v6.y, *(__half2*)&v7.y));
        float2 f0 = __half22float2(p0);
        float2 f1 = __half22float2(p1);
        float2 g0 = __half22float2(q0);
        float2 g1 = __half22float2(q1);
        ax += f0.x + f1.x; ay += f0.y + f1.y;
        az += g0.x + g1.x; aw += g0.y + g1.y;
    }
    for (; j < e; j++) {
        uint2 v = hv[(size_t)col[j] * 32 + lane];
        float2 p0 = __half22float2(*(const __half2*)&v.x);
        float2 p1 = __half22float2(*(const __half2*)&v.y);
        ax += p0.x; ay += p0.y; az += p1.x; aw += p1.y;
    }
    float di = dinv[node];
    float4 bb = ((const float4*)bias)[lane];
    __half2 o0 = __floats2half2_rn(tanhf(di * ax + bb.x), tanhf(di * ay + bb.y));
    __half2 o1 = __floats2half2_rn(tanhf(di * az + bb.z), tanhf(di * aw + bb.w));
    uint2 p; p.x = *(uint32_t*)&o0; p.y = *(uint32_t*)&o1;
    ((uint2*)s)[(size_t)node * 32 + lane] = p;
}

__global__ __launch_bounds__(256)
void agg_both_kernel(const __half* __restrict__ y,
                     const __half* __restrict__ hsp,
                     const float* __restrict__ dinv,
                     const int* __restrict__ col,
                     const int* __restrict__ rowptr,
                     const float* __restrict__ b1,
                     const float* __restrict__ gcn_b,
                     __half* __restrict__ z,
                     __half* __restrict__ s,
                     int nb0) {
    int lane = threadIdx.x & 31;
    if ((int)blockIdx.x < nb0) {
        int node = (blockIdx.x * blockDim.x + threadIdx.x) >> 5;
        if (node < NN) gin_core(y, col, rowptr, b1, z, node, lane);
    } else {
        int node = ((blockIdx.x - nb0) * blockDim.x + threadIdx.x) >> 5;
        if (node < NN) gcn_core(hsp, dinv, col, rowptr, gcn_b, s, node, lane);
    }
}

// ---------------- fused post + readout -------------------------------------
__global__ __launch_bounds__(128)
void post_readout_kernel(const float* __restrict__ g,
                         const float* __restrict__ post_w,
                         const float* __restrict__ post_b,
                         const float* __restrict__ ro_w,
                         const float* __restrict__ ro_b,
                         float* __restrict__ out) {
    int r = blockIdx.x;
    int c = threadIdx.x;
    __shared__ float row[HH];
    __shared__ float gp[HH];
    __shared__ float logit[CC];
    row[c] = g[(size_t)r * HH + c];
    __syncthreads();
    float acc = post_b[c];
#pragma unroll 8
    for (int k = 0; k < HH; k++) acc = fmaf(row[k], post_w[(size_t)k * HH + c], acc);
    gp[c] = fmaxf(acc, 0.0f);
    __syncthreads();
    if (c < CC) {
        float l = ro_b[c];
        for (int k = 0; k < HH; k++) l = fmaf(gp[k], ro_w[(size_t)k * CC + c], l);
        logit[c] = l;
    }
    __syncthreads();
    if (c < CC) {
        float m = logit[0];
#pragma unroll
        for (int q = 1; q < CC; q++) m = fmaxf(m, logit[q]);
        float sum = 0.0f;
#pragma unroll
        for (int q = 0; q < CC; q++) sum += expf(logit[q] - m);
        float lse = m + logf(sum);
        out[(size_t)r * CC + c] = logit[c] - lse;
    }
}

// ---------------- driver ---------------------------------------------------
extern "C" void kernel_launch(void* const* d_in, const int* in_sizes, int n_in,
                              void* d_out, int out_size) {
    const float* x_in   = (const float*)d_in[0];
    const float* s_in   = (const float*)d_in[1];
    const int*   ei     = (const int*)d_in[2];
    const int*   batch  = (const int*)d_in[3];
    const float* pre_w  = (const float*)d_in[4];
    const float* pre_b  = (const float*)d_in[5];
    const float* emb_w  = (const float*)d_in[6];
    const float* emb_b  = (const float*)d_in[7];
    const float* gin_w1 = (const float*)d_in[8];
    const float* gin_b1 = (const float*)d_in[9];
    const float* gin_w2 = (const float*)d_in[10];
    const float* gin_b2 = (const float*)d_in[11];
    const float* gcn_w  = (const float*)d_in[12];
    const float* gcn_b  = (const float*)d_in[13];
    const float* whp_w  = (const float*)d_in[14];
    const float* whp_b  = (const float*)d_in[15];
    const float* post_w = (const float*)d_in[16];
    const float* post_b = (const float*)d_in[17];
    const float* ro_w   = (const float*)d_in[18];
    const float* ro_b   = (const float*)d_in[19];
    float* out = (float*)d_out;

    float *px, *ps, *py, *pz, *phs, *pg, *pdinv;
    int *pdegc, *prow, *pcur, *pcol;
    __half *pxh, *pshn, *pwpre, *pwemb, *pwg1, *pwgc, *pwg2, *pwwhp;
    cudaGetSymbolAddress((void**)&px,    d_x);
    cudaGetSymbolAddress((void**)&ps,    d_s);
    cudaGetSymbolAddress((void**)&py,    d_y);
    cudaGetSymbolAddress((void**)&pz,    d_z);
    cudaGetSymbolAddress((void**)&phs,   d_hs);
    cudaGetSymbolAddress((void**)&pg,    d_g);
    cudaGetSymbolAddress((void**)&pdinv, d_dinv);
    cudaGetSymbolAddress((void**)&pdegc, d_degc);
    cudaGetSymbolAddress((void**)&prow,  d_rowptr);
    cudaGetSymbolAddress((void**)&pcur,  d_cursor);
    cudaGetSymbolAddress((void**)&pcol,  d_col);
    cudaGetSymbolAddress((void**)&pxh,   d_xh);
    cudaGetSymbolAddress((void**)&pshn,  d_shn);
    cudaGetSymbolAddress((void**)&pwpre, d_wpre);
    cudaGetSymbolAddress((void**)&pwemb, d_wemb);
    cudaGetSymbolAddress((void**)&pwg1,  d_wg1);
    cudaGetSymbolAddress((void**)&pwgc,  d_wgc);
    cudaGetSymbolAddress((void**)&pwg2,  d_wg2);
    cudaGetSymbolAddress((void**)&pwwhp, d_wwhp);
    __half* pxH  = (__half*)px;
    __half* psH  = (__half*)ps;
    __half* pyH  = (__half*)py;
    __half* pzH  = (__half*)pz;
    __half* phsH = (__half*)phs;

    const int TPB = 256;
    const int gB = (NN + TM - 1) / TM;       // 391
    const int aggB = (NN * 32 + TPB - 1) / TPB;

    cudaMemsetAsync(pdegc, 0, NN * sizeof(int), 0);
    cudaMemsetAsync(pcur,  0, NN * sizeof(int), 0);

    prep_all_kernel<<<PB_TOTAL, TPB>>>(x_in, s_in, pre_w, emb_w, gin_w1, gcn_w,
                                       gin_w2, whp_w, pxh, pshn, pwpre, pwemb,
                                       pwg1, pwgc, pwg2, pwwhp, pg, ei, pdegc);

    scan_deg_kernel<<<1, 1024>>>(pdegc, prow, pdinv);

    GemmP Ppre = { pxh, FIN, nullptr, 0, pwpre, pre_b, nullptr, nullptr, pxH, NN, 0, 1 };
    GemmP Pemb = { pshn, NSE, nullptr, 0, pwemb, emb_b, nullptr, nullptr, psH, NN, 0, 1 };
    h_gemm2_fill<<<2 * gB + EBLK, 256>>>(Ppre, Pemb, gB, ei, prow, pcur, pcol);

    for (int i = 0; i < LL; i++) {
        GemmP Py  = { pxH, HH, psH, HH, pwg1 + (size_t)i * 128 * 256,
                      nullptr, nullptr, nullptr, pyH, NN, 0, 1 };
        GemmP Phs = { psH, HH, nullptr, 0, pwgc + (size_t)i * 128 * 128,
                      nullptr, pdinv, nullptr, phsH, NN, 0, 1 };
        h_gemm2<<<2 * gB, 256>>>(Py, Phs, gB);

        agg_both_kernel<<<2 * aggB, TPB>>>(pyH, phsH, pdinv, pcol, prow,
                                           gin_b1 + (size_t)i * HH,
                                           gcn_b + (size_t)i * HH,
                                           pzH, psH, aggB);

        GemmP Pw2 = { pzH, HH, nullptr, 0, pwg2 + (size_t)i * 128 * 128,
                      gin_b2 + (size_t)i * HH, nullptr, nullptr, pxH, NN, 1, 1 };
        h_gemm1<<<gB, 256>>>(Pw2);
    }

    GemmP Pwhp = { pxH, HH, psH, HH, pwwhp, whp_b, nullptr, batch, pg, NN, 0, 0 };
    h_gemm1<<<gB, 256>>>(Pwhp);

    post_readout_kernel<<<GG, HH>>>(pg, post_w, post_b, ro_w, ro_b, out);
}